// round 8
// baseline (speedup 1.0000x reference)
#include <cuda_runtime.h>
#include <cuda_bf16.h>
#include <cstdint>
#include <math.h>

#define NB    32
#define C_ST  2048
#define C_LT  2048
#define LAT   512
#define SS    512
#define LL    2048
#define LN_EPS 1e-5f

typedef long long ll;
typedef __nv_bfloat16 bf16;

// ---------------------------------------------------------------------------
// Scratch pool
// ---------------------------------------------------------------------------
static constexpr ll B_STT  = (ll)NB * SS * C_ST * 2;   // bf16 hi OR fp8 [hi|lo] pair
static constexpr ll B_LTT  = (ll)NB * LL * C_LT * 2;
static constexpr ll B_TH   = (ll)NB * SS * LAT * 2;
static constexpr ll B_PH   = (ll)NB * LL * LAT * 2;
static constexpr ll B_G    = (ll)NB * LAT * LL * 2;
static constexpr ll B_SC   = (ll)NB * SS * LL * 4;
static constexpr ll B_P    = (ll)NB * SS * LL * 2;
static constexpr ll B_ATT  = (ll)NB * SS * LAT * 4;
static constexpr ll B_Y    = (ll)NB * SS * LAT * 2;
static constexpr ll B_W    = (ll)LAT * C_ST * 2;
static constexpr ll B_LN   = (ll)LAT * SS * 4;

static constexpr ll O_STT_HI = 0;
static constexpr ll O_STT_8  = O_STT_HI + B_STT;
static constexpr ll O_LTT_HI = O_STT_8  + B_STT;
static constexpr ll O_LTT_8  = O_LTT_HI + B_LTT;
static constexpr ll O_TH_HI  = O_LTT_8  + B_LTT;
static constexpr ll O_TH_8   = O_TH_HI  + B_TH;
static constexpr ll O_PH_HI  = O_TH_8   + B_TH;
static constexpr ll O_PH_8   = O_PH_HI  + B_PH;
static constexpr ll O_G_HI   = O_PH_8   + B_PH;
static constexpr ll O_G_LO   = O_G_HI   + B_G;
static constexpr ll O_SCORE  = O_G_LO   + B_G;
static constexpr ll O_P_HI   = O_SCORE  + B_SC;
static constexpr ll O_P_LO   = O_P_HI   + B_P;
static constexpr ll O_ATT    = O_P_LO   + B_P;
static constexpr ll O_Y_HI   = O_ATT    + B_ATT;
static constexpr ll O_Y_8    = O_Y_HI   + B_Y;
static constexpr ll O_WST_HI = O_Y_8    + B_Y;
static constexpr ll O_WST_8  = O_WST_HI + B_W;
static constexpr ll O_WLT_HI = O_WST_8  + B_W;
static constexpr ll O_WLT_8  = O_WLT_HI + B_W;
static constexpr ll O_WG_HI  = O_WLT_8  + B_W;
static constexpr ll O_WG_8   = O_WG_HI  + B_W;
static constexpr ll O_WO_HI  = O_WG_8   + B_W;
static constexpr ll O_WO_8   = O_WO_HI  + B_W;
static constexpr ll O_LNW_T  = O_WO_8   + B_W;
static constexpr ll O_LNB_T  = O_LNW_T  + B_LN;
static constexpr ll O_STATS  = O_LNB_T  + B_LN;
static constexpr ll POOL_BYTES = O_STATS + 256;

__device__ __align__(256) unsigned char g_pool[POOL_BYTES];

// ---------------------------------------------------------------------------
// PTX helpers
// ---------------------------------------------------------------------------
__device__ __forceinline__ uint32_t smem_u32(const void* p) {
    uint32_t a;
    asm("{ .reg .u64 t; cvta.to.shared.u64 t, %1; cvt.u32.u64 %0, t; }" : "=r"(a) : "l"(p));
    return a;
}
__device__ __forceinline__ void cpa16(uint32_t s, const void* g) {
    asm volatile("cp.async.cg.shared.global [%0], [%1], 16;" :: "r"(s), "l"(g) : "memory");
}
#define CP_COMMIT asm volatile("cp.async.commit_group;" ::: "memory")
#define CP_WAIT1  asm volatile("cp.async.wait_group 1;" ::: "memory")
#define CP_WAIT0  asm volatile("cp.async.wait_group 0;" ::: "memory")

#define LDSM4(r, addr) \
    asm volatile("ldmatrix.sync.aligned.m8n8.x4.shared.b16 {%0,%1,%2,%3}, [%4];" \
        : "=r"((r)[0]), "=r"((r)[1]), "=r"((r)[2]), "=r"((r)[3]) : "r"(addr))

#define MMA16816(d, a, b0, b1) \
    asm volatile("mma.sync.aligned.m16n8k16.row.col.f32.bf16.bf16.f32 " \
        "{%0,%1,%2,%3}, {%4,%5,%6,%7}, {%8,%9}, {%0,%1,%2,%3};" \
        : "+f"((d)[0]), "+f"((d)[1]), "+f"((d)[2]), "+f"((d)[3]) \
        : "r"((a)[0]), "r"((a)[1]), "r"((a)[2]), "r"((a)[3]), "r"(b0), "r"(b1))

// fp8 e4m3 MMA, k32, f16 accumulate (2 regs = 4 halves)
#define MMA8F16(c, a, b0, b1) \
    asm volatile("mma.sync.aligned.m16n8k32.row.col.f16.e4m3.e4m3.f16 " \
        "{%0,%1}, {%2,%3,%4,%5}, {%6,%7}, {%0,%1};" \
        : "+r"((c)[0]), "+r"((c)[1]) \
        : "r"((a)[0]), "r"((a)[1]), "r"((a)[2]), "r"((a)[3]), "r"(b0), "r"(b1))

__device__ __forceinline__ uint32_t pack_bf(bf16 a, bf16 b) {
    return (uint32_t)__bfloat16_as_ushort(a) | ((uint32_t)__bfloat16_as_ushort(b) << 16);
}
__device__ __forceinline__ void split1(float v, bf16& h, bf16& l) {
    h = __float2bfloat16_rn(v);
    l = __float2bfloat16_rn(v - __bfloat162float(h));
}
// low byte = e0, high byte = e1
__device__ __forceinline__ unsigned short cvt2_e4m3(float e0, float e1) {
    unsigned short r;
    asm("cvt.rn.satfinite.e4m3x2.f32 %0, %1, %2;" : "=h"(r) : "f"(e1), "f"(e0));
    return r;
}
__device__ __forceinline__ uint32_t pack4_e4m3(float a, float b, float c, float d) {
    return (uint32_t)cvt2_e4m3(a, b) | ((uint32_t)cvt2_e4m3(c, d) << 16);
}
__device__ __forceinline__ float2 unpack_h2(uint32_t u) {
    __half2 h = *reinterpret_cast<__half2*>(&u);
    return __half22float2(h);
}

// ---------------------------------------------------------------------------
// GEMM:  C(m,n) = alpha * (sum_k A(m,k)B(n,k)) + bias.   A,B K-major.
// CROSS=0: bf16 3-term (A2/B2 = bf16 lo arrays).
// CROSS=1: bf16 hi.hi + fp8 e4m3 cross terms (A2/B2 = fp8 arrays, row = [hi K | lo K],
//          row stride 2K bytes, batch stride 2*sA bytes). acc8 f16, epilogue adds us*acc8.
// CTA 128x256, warps 2x4 (64x64), K-chunk 64, 2-stage cp.async.
// OUT=0: fp32 Cf.  OUT=1: bf16 hi/lo Chi/Clo.  OUT=2: bf16 Chi + fp8 C8 (scales csh,csl).
// Stage: [Ahi 16K][A8|Alo 16K][Bhi 32K][B8|Blo 32K] = 96K
// ---------------------------------------------------------------------------
static constexpr int STAGE_BYTES = 98304;
static constexpr int SMEM_TOTAL  = 2 * STAGE_BYTES;

template <int CROSS, int OUT>
__global__ __launch_bounds__(256) void mma_gemm(
    const bf16* __restrict__ Ahi, const void* __restrict__ A2,
    const bf16* __restrict__ Bhi, const void* __restrict__ B2,
    float* __restrict__ Cf, bf16* __restrict__ Chi, bf16* __restrict__ Clo,
    uint8_t* __restrict__ C8,
    int K, int ldc, ll sA, ll sB, ll sC,
    float alpha, const float* __restrict__ bias, int bias_per_n,
    float us, float csh, float csl)
{
    extern __shared__ __align__(1024) char smem[];
    const uint32_t sb = smem_u32(smem);
    const int tid  = threadIdx.x;
    const int wid  = tid >> 5, lane = tid & 31;
    const ll  b    = blockIdx.z;
    const int m0   = blockIdx.y << 7;
    const int n0   = blockIdx.x << 8;

    const bf16* Ah = Ahi + b * sA;
    const bf16* Bh = Bhi + b * sB;
    const bf16* Albf = (CROSS == 0) ? ((const bf16*)A2 + b * sA) : nullptr;
    const bf16* Blbf = (CROSS == 0) ? ((const bf16*)B2 + b * sB) : nullptr;
    const uint8_t* A8g = (CROSS == 1) ? ((const uint8_t*)A2 + b * 2 * sA) : nullptr;
    const uint8_t* B8g = (CROSS == 1) ? ((const uint8_t*)B2 + b * 2 * sB) : nullptr;

    const int C = K >> 6;
    const int K2 = K * 2;

    auto load_chunk = [&](int ct, int stg) {
        const uint32_t base = sb + stg * STAGE_BYTES;
        const int kt = ct << 6;
#pragma unroll
        for (int i = 0; i < 4; ++i) {           // A rows
            int idx = tid + (i << 8);
            int row = idx >> 3, seg = idx & 7;
            uint32_t so = (uint32_t)((row << 7) + (seg << 4));
            so ^= (so >> 3) & 0x70;
            cpa16(base + so, Ah + (ll)(m0 + row) * K + kt + (seg << 3));
            if (CROSS == 0)
                cpa16(base + 16384 + so, Albf + (ll)(m0 + row) * K + kt + (seg << 3));
            else
                cpa16(base + 16384 + so, A8g + (ll)(m0 + row) * K2 +
                      (seg < 4 ? (kt + (seg << 4)) : (K + kt + ((seg - 4) << 4))));
        }
#pragma unroll
        for (int i = 0; i < 8; ++i) {           // B rows
            int idx = tid + (i << 8);
            int row = idx >> 3, seg = idx & 7;
            uint32_t so = (uint32_t)((row << 7) + (seg << 4));
            so ^= (so >> 3) & 0x70;
            cpa16(base + 32768 + so, Bh + (ll)(n0 + row) * K + kt + (seg << 3));
            if (CROSS == 0)
                cpa16(base + 65536 + so, Blbf + (ll)(n0 + row) * K + kt + (seg << 3));
            else
                cpa16(base + 65536 + so, B8g + (ll)(n0 + row) * K2 +
                      (seg < 4 ? (kt + (seg << 4)) : (K + kt + ((seg - 4) << 4))));
        }
    };

    load_chunk(0, 0); CP_COMMIT;

    const int wm = wid >> 2, wn = wid & 3;
    float acc[4][8][4];
#pragma unroll
    for (int i = 0; i < 4; ++i)
#pragma unroll
        for (int j = 0; j < 8; ++j)
#pragma unroll
            for (int q = 0; q < 4; ++q) acc[i][j][q] = 0.f;
    uint32_t acc8[4][8][2];
    if (CROSS == 1) {
#pragma unroll
        for (int i = 0; i < 4; ++i)
#pragma unroll
            for (int j = 0; j < 8; ++j) { acc8[i][j][0] = 0u; acc8[i][j][1] = 0u; }
    }

    // bf16 ldmatrix lane addressing
    const uint32_t a_row = (uint32_t)(wm * 64 + (lane & 15));
    const uint32_t a_sb  = (uint32_t)(lane >> 4);
    const uint32_t b_row = (uint32_t)(wn * 64 + ((lane >> 4) << 3) + (lane & 7));
    const uint32_t b_sb  = (uint32_t)((lane >> 3) & 1);
    // fp8 ldmatrix lane addressing
    const uint32_t f8a_r = (uint32_t)((lane & 7) + 8 * ((lane >> 3) & 1));
    const uint32_t f8a_k = (uint32_t)(16 * (lane >> 4));
    const uint32_t f8b_r = (uint32_t)((lane & 7) + 8 * (lane >> 4));
    const uint32_t f8b_k = (uint32_t)(16 * ((lane >> 3) & 1));

    for (int ct = 0; ct < C; ++ct) {
        const uint32_t sbase = sb + (ct & 1) * STAGE_BYTES;
        if (ct + 1 < C) { load_chunk(ct + 1, (ct + 1) & 1); CP_COMMIT; CP_WAIT1; }
        else            { CP_WAIT0; }
        __syncthreads();

        if (CROSS == 0) {
#pragma unroll
            for (int s = 0; s < 4; ++s) {
                uint32_t ah[4][4], al4[4][4];
#pragma unroll
                for (int mt = 0; mt < 4; ++mt) {
                    uint32_t off = ((a_row + mt * 16) << 7) + (((uint32_t)(s * 2) + a_sb) << 4);
                    off ^= (off >> 3) & 0x70;
                    LDSM4(ah[mt],  sbase + off);
                    LDSM4(al4[mt], sbase + 16384 + off);
                }
                uint32_t bh[4][4], bl4[4][4];
#pragma unroll
                for (int ng = 0; ng < 4; ++ng) {
                    uint32_t off = ((b_row + ng * 16) << 7) + (((uint32_t)(s * 2) + b_sb) << 4);
                    off ^= (off >> 3) & 0x70;
                    LDSM4(bh[ng],  sbase + 32768 + off);
                    LDSM4(bl4[ng], sbase + 65536 + off);
                }
#pragma unroll
                for (int mt = 0; mt < 4; ++mt)
#pragma unroll
                    for (int ng = 0; ng < 4; ++ng) {
                        float* d0 = acc[mt][2 * ng];
                        float* d1 = acc[mt][2 * ng + 1];
                        MMA16816(d0, ah[mt],  bh[ng][0],  bh[ng][1]);
                        MMA16816(d0, ah[mt],  bl4[ng][0], bl4[ng][1]);
                        MMA16816(d0, al4[mt], bh[ng][0],  bh[ng][1]);
                        MMA16816(d1, ah[mt],  bh[ng][2],  bh[ng][3]);
                        MMA16816(d1, ah[mt],  bl4[ng][2], bl4[ng][3]);
                        MMA16816(d1, al4[mt], bh[ng][2],  bh[ng][3]);
                    }
            }
        } else {
#pragma unroll
            for (int s32 = 0; s32 < 2; ++s32) {
                // --- bf16 hi.hi over two k16 steps ---
#pragma unroll
                for (int h = 0; h < 2; ++h) {
                    const int s = s32 * 2 + h;
                    uint32_t ah[4][4], bh[4][4];
#pragma unroll
                    for (int mt = 0; mt < 4; ++mt) {
                        uint32_t off = ((a_row + mt * 16) << 7) + (((uint32_t)(s * 2) + a_sb) << 4);
                        off ^= (off >> 3) & 0x70;
                        LDSM4(ah[mt], sbase + off);
                    }
#pragma unroll
                    for (int ng = 0; ng < 4; ++ng) {
                        uint32_t off = ((b_row + ng * 16) << 7) + (((uint32_t)(s * 2) + b_sb) << 4);
                        off ^= (off >> 3) & 0x70;
                        LDSM4(bh[ng], sbase + 32768 + off);
                    }
#pragma unroll
                    for (int mt = 0; mt < 4; ++mt)
#pragma unroll
                        for (int ng = 0; ng < 4; ++ng) {
                            MMA16816(acc[mt][2 * ng],     ah[mt], bh[ng][0], bh[ng][1]);
                            MMA16816(acc[mt][2 * ng + 1], ah[mt], bh[ng][2], bh[ng][3]);
                        }
                }
                // --- fp8 cross terms, one k32 ---
                uint32_t b8h[4][4], b8l[4][4];
#pragma unroll
                for (int ng = 0; ng < 4; ++ng) {
                    uint32_t base_off = ((uint32_t)(wn * 64 + ng * 16 + f8b_r) << 7)
                                      + (uint32_t)(s32 * 32) + f8b_k;
                    uint32_t oh = base_off;      oh ^= (oh >> 3) & 0x70;
                    uint32_t ol = base_off + 64; ol ^= (ol >> 3) & 0x70;
                    LDSM4(b8h[ng], sbase + 65536 + oh);
                    LDSM4(b8l[ng], sbase + 65536 + ol);
                }
#pragma unroll
                for (int mt = 0; mt < 4; ++mt) {
                    uint32_t base_off = ((uint32_t)(wm * 64 + mt * 16 + f8a_r) << 7)
                                      + (uint32_t)(s32 * 32) + f8a_k;
                    uint32_t oh = base_off;      oh ^= (oh >> 3) & 0x70;
                    uint32_t ol = base_off + 64; ol ^= (ol >> 3) & 0x70;
                    uint32_t a8h[4], a8l[4];
                    LDSM4(a8h, sbase + 16384 + oh);
                    LDSM4(a8l, sbase + 16384 + ol);
#pragma unroll
                    for (int ng = 0; ng < 4; ++ng) {
                        MMA8F16(acc8[mt][2 * ng],     a8h, b8l[ng][0], b8l[ng][1]);
                        MMA8F16(acc8[mt][2 * ng],     a8l, b8h[ng][0], b8h[ng][1]);
                        MMA8F16(acc8[mt][2 * ng + 1], a8h, b8l[ng][2], b8l[ng][3]);
                        MMA8F16(acc8[mt][2 * ng + 1], a8l, b8h[ng][2], b8h[ng][3]);
                    }
                }
            }
        }
        __syncthreads();
    }

    // ---- epilogue ----
    const int l4 = lane >> 2;
    const int l2 = (lane & 3) * 2;
#pragma unroll
    for (int mt = 0; mt < 4; ++mt) {
        const int m = m0 + wm * 64 + mt * 16 + l4;
        float bm0 = 0.f, bm8 = 0.f;
        if (bias && !bias_per_n) { bm0 = bias[m]; bm8 = bias[m + 8]; }
#pragma unroll
        for (int nt = 0; nt < 8; ++nt) {
            const int n = n0 + wn * 64 + nt * 8 + l2;
            float bn0 = 0.f, bn1 = 0.f;
            if (bias && bias_per_n) { bn0 = bias[n]; bn1 = bias[n + 1]; }
            const float* a4 = acc[mt][nt];
            float c8v0 = 0.f, c8v1 = 0.f, c8v2 = 0.f, c8v3 = 0.f;
            if (CROSS == 1) {
                float2 p0 = unpack_h2(acc8[mt][nt][0]);
                float2 p1 = unpack_h2(acc8[mt][nt][1]);
                c8v0 = p0.x; c8v1 = p0.y; c8v2 = p1.x; c8v3 = p1.y;
            }
            float v00 = (a4[0] + us * c8v0) * alpha;
            float v01 = (a4[1] + us * c8v1) * alpha;
            float v10 = (a4[2] + us * c8v2) * alpha;
            float v11 = (a4[3] + us * c8v3) * alpha;
            if (bias) {
                if (bias_per_n) { v00 += bn0; v01 += bn1; v10 += bn0; v11 += bn1; }
                else            { v00 += bm0; v01 += bm0; v10 += bm8; v11 += bm8; }
            }
            if (OUT == 0) {
                float* d0 = Cf + b * sC + (ll)m * ldc + n;
                float* d1 = Cf + b * sC + (ll)(m + 8) * ldc + n;
                *reinterpret_cast<float2*>(d0) = make_float2(v00, v01);
                *reinterpret_cast<float2*>(d1) = make_float2(v10, v11);
            } else if (OUT == 1) {
                bf16 h00, h01, h10, h11, l00, l01, l10, l11;
                split1(v00, h00, l00); split1(v01, h01, l01);
                split1(v10, h10, l10); split1(v11, h11, l11);
                ll o0 = b * sC + (ll)m * ldc + n;
                ll o1 = b * sC + (ll)(m + 8) * ldc + n;
                *reinterpret_cast<uint32_t*>(Chi + o0) = pack_bf(h00, h01);
                *reinterpret_cast<uint32_t*>(Chi + o1) = pack_bf(h10, h11);
                *reinterpret_cast<uint32_t*>(Clo + o0) = pack_bf(l00, l01);
                *reinterpret_cast<uint32_t*>(Clo + o1) = pack_bf(l10, l11);
            } else {   // OUT == 2: bf16 hi + fp8 [hi|lo] rows
                bf16 h00 = __float2bfloat16_rn(v00), h01 = __float2bfloat16_rn(v01);
                bf16 h10 = __float2bfloat16_rn(v10), h11 = __float2bfloat16_rn(v11);
                float r00 = v00 - __bfloat162float(h00), r01 = v01 - __bfloat162float(h01);
                float r10 = v10 - __bfloat162float(h10), r11 = v11 - __bfloat162float(h11);
                ll o0 = b * sC + (ll)m * ldc + n;
                ll o1 = b * sC + (ll)(m + 8) * ldc + n;
                *reinterpret_cast<uint32_t*>(Chi + o0) = pack_bf(h00, h01);
                *reinterpret_cast<uint32_t*>(Chi + o1) = pack_bf(h10, h11);
                uint8_t* base8 = C8 + b * 2 * sC;
                *reinterpret_cast<unsigned short*>(base8 + (ll)m * 2 * ldc + n) =
                    cvt2_e4m3(csh * __bfloat162float(h00), csh * __bfloat162float(h01));
                *reinterpret_cast<unsigned short*>(base8 + (ll)m * 2 * ldc + ldc + n) =
                    cvt2_e4m3(csl * r00, csl * r01);
                *reinterpret_cast<unsigned short*>(base8 + (ll)(m + 8) * 2 * ldc + n) =
                    cvt2_e4m3(csh * __bfloat162float(h10), csh * __bfloat162float(h11));
                *reinterpret_cast<unsigned short*>(base8 + (ll)(m + 8) * 2 * ldc + ldc + n) =
                    cvt2_e4m3(csl * r10, csl * r11);
            }
        }
    }
}

// ---------------------------------------------------------------------------
// Weight convert: fp32 (R x K) -> bf16 hi + fp8 row [hi K | lo K]. 8 elems/thread.
// ---------------------------------------------------------------------------
__global__ __launch_bounds__(256) void wsplit8_kernel(
    const float* __restrict__ in, bf16* __restrict__ whi, uint8_t* __restrict__ w8,
    int K, float sh, float sl)
{
    ll i = ((ll)blockIdx.x * 256 + threadIdx.x) * 8;
    int r = (int)(i / K), k = (int)(i % K);
    float4 a = *reinterpret_cast<const float4*>(in + i);
    float4 c = *reinterpret_cast<const float4*>(in + i + 4);
    float v[8] = {a.x, a.y, a.z, a.w, c.x, c.y, c.z, c.w};
    uint32_t hp[4];
    float hf[8], rf[8];
#pragma unroll
    for (int q = 0; q < 8; ++q) {
        bf16 h = __float2bfloat16_rn(v[q]);
        hf[q] = __bfloat162float(h);
        rf[q] = v[q] - hf[q];
        if (q & 1) hp[q >> 1] = pack_bf(__float2bfloat16_rn(v[q - 1]), h);
    }
    *reinterpret_cast<uint4*>(whi + i) = make_uint4(hp[0], hp[1], hp[2], hp[3]);
    uint2 h8 = make_uint2(pack4_e4m3(sh*hf[0], sh*hf[1], sh*hf[2], sh*hf[3]),
                          pack4_e4m3(sh*hf[4], sh*hf[5], sh*hf[6], sh*hf[7]));
    uint2 l8 = make_uint2(pack4_e4m3(sl*rf[0], sl*rf[1], sl*rf[2], sl*rf[3]),
                          pack4_e4m3(sl*rf[4], sl*rf[5], sl*rf[6], sl*rf[7]));
    uint8_t* row8 = w8 + (ll)r * 2 * K;
    *reinterpret_cast<uint2*>(row8 + k) = h8;
    *reinterpret_cast<uint2*>(row8 + K + k) = l8;
}

// ---------------------------------------------------------------------------
// Feature transpose+convert: in (b,R,X) fp32 -> (b,X,R): bf16 hi + fp8 [hi R|lo R]
// ---------------------------------------------------------------------------
__global__ __launch_bounds__(256) void transpose_split8_kernel(
    const float* __restrict__ in, bf16* __restrict__ hi, uint8_t* __restrict__ o8,
    int R, int X, float sh, float sl)
{
    __shared__ float t[64][65];
    const ll b = blockIdx.z;
    const float* ib = in + b * (ll)R * X;
    const int x0 = blockIdx.x << 6, r0 = blockIdx.y << 6;
    const int tx = threadIdx.x & 15;
    const int ty = threadIdx.x >> 4;
#pragma unroll
    for (int i = 0; i < 4; ++i) {
        int r = ty + 16 * i;
        float4 v = *reinterpret_cast<const float4*>(ib + (ll)(r0 + r) * X + x0 + tx * 4);
        t[r][tx * 4 + 0] = v.x; t[r][tx * 4 + 1] = v.y;
        t[r][tx * 4 + 2] = v.z; t[r][tx * 4 + 3] = v.w;
    }
    __syncthreads();
    const ll ob  = b * (ll)R * X;
    const ll ob8 = b * (ll)R * X * 2;
#pragma unroll
    for (int i = 0; i < 4; ++i) {
        int xr = ty + 16 * i;
        float w0 = t[tx * 4 + 0][xr], w1 = t[tx * 4 + 1][xr];
        float w2 = t[tx * 4 + 2][xr], w3 = t[tx * 4 + 3][xr];
        bf16 h0 = __float2bfloat16_rn(w0), h1 = __float2bfloat16_rn(w1);
        bf16 h2 = __float2bfloat16_rn(w2), h3 = __float2bfloat16_rn(w3);
        float f0 = __bfloat162float(h0), f1 = __bfloat162float(h1);
        float f2 = __bfloat162float(h2), f3 = __bfloat162float(h3);
        ll o = ob + (ll)(x0 + xr) * R + r0 + tx * 4;
        *reinterpret_cast<uint2*>(hi + o) = make_uint2(pack_bf(h0, h1), pack_bf(h2, h3));
        uint8_t* row8 = o8 + ob8 + (ll)(x0 + xr) * 2 * R + r0 + tx * 4;
        *reinterpret_cast<uint32_t*>(row8)     = pack4_e4m3(sh*f0, sh*f1, sh*f2, sh*f3);
        *reinterpret_cast<uint32_t*>(row8 + R) = pack4_e4m3(sl*(w0-f0), sl*(w1-f1), sl*(w2-f2), sl*(w3-f3));
    }
}

// ---------------------------------------------------------------------------
// Plain fp32 transpose (ln params)
// ---------------------------------------------------------------------------
__global__ __launch_bounds__(256) void transpose_f32_kernel(
    const float* __restrict__ in, float* __restrict__ out, int R, int X)
{
    __shared__ float t[32][33];
    const int x0 = blockIdx.x << 5, r0 = blockIdx.y << 5;
    const int tx = threadIdx.x & 31, ty = threadIdx.x >> 5;
#pragma unroll
    for (int i = 0; i < 4; ++i)
        t[ty + 8 * i][tx] = in[(ll)(r0 + ty + 8 * i) * X + x0 + tx];
    __syncthreads();
#pragma unroll
    for (int i = 0; i < 4; ++i)
        out[(ll)(x0 + ty + 8 * i) * R + r0 + tx] = t[tx][ty + 8 * i];
}

// ---------------------------------------------------------------------------
// Softmax over L + bf16 hi/lo split (for G5, bf16 path)
// ---------------------------------------------------------------------------
__global__ __launch_bounds__(256) void softmax_split_kernel(
    const float* __restrict__ x, bf16* __restrict__ phi_, bf16* __restrict__ plo_)
{
    const ll row = blockIdx.x;
    const int tid = threadIdx.x;
    const float* p = x + row * (ll)LL + tid * 8;
    float4 a = *reinterpret_cast<const float4*>(p);
    float4 c = *reinterpret_cast<const float4*>(p + 4);
    float v[8] = {a.x, a.y, a.z, a.w, c.x, c.y, c.z, c.w};

    float m = v[0];
#pragma unroll
    for (int i = 1; i < 8; ++i) m = fmaxf(m, v[i]);
#pragma unroll
    for (int o = 16; o > 0; o >>= 1) m = fmaxf(m, __shfl_xor_sync(0xffffffffu, m, o));
    __shared__ float sm[8];
    if ((tid & 31) == 0) sm[tid >> 5] = m;
    __syncthreads();
    float mx = sm[0];
#pragma unroll
    for (int i = 1; i < 8; ++i) mx = fmaxf(mx, sm[i]);

    float s = 0.f;
#pragma unroll
    for (int i = 0; i < 8; ++i) { v[i] = __expf(v[i] - mx); s += v[i]; }
#pragma unroll
    for (int o = 16; o > 0; o >>= 1) s += __shfl_xor_sync(0xffffffffu, s, o);
    __shared__ float ss[8];
    if ((tid & 31) == 0) ss[tid >> 5] = s;
    __syncthreads();
    float tot = 0.f;
#pragma unroll
    for (int i = 0; i < 8; ++i) tot += ss[i];
    float inv = 1.f / tot;

    uint32_t hp[4], lp[4];
#pragma unroll
    for (int q = 0; q < 4; ++q) {
        float r0 = v[2*q] * inv, r1 = v[2*q+1] * inv;
        bf16 h0, l0, h1, l1;
        split1(r0, h0, l0); split1(r1, h1, l1);
        hp[q] = pack_bf(h0, h1); lp[q] = pack_bf(l0, l1);
    }
    ll o = row * (ll)LL + tid * 8;
    *reinterpret_cast<uint4*>(phi_ + o) = make_uint4(hp[0], hp[1], hp[2], hp[3]);
    *reinterpret_cast<uint4*>(plo_ + o) = make_uint4(lp[0], lp[1], lp[2], lp[3]);
}

// ---------------------------------------------------------------------------
// LayerNorm stats per batch
// ---------------------------------------------------------------------------
__global__ __launch_bounds__(512) void stats_kernel(
    const float* __restrict__ att, float2* __restrict__ stats)
{
    const int n = blockIdx.x;
    const float* x = att + (ll)n * LAT * SS;
    const int tid = threadIdx.x;
    float s = 0.f, s2 = 0.f;
    for (int i = tid * 4; i < LAT * SS; i += 512 * 4) {
        float4 v = *reinterpret_cast<const float4*>(x + i);
        s  += v.x + v.y + v.z + v.w;
        s2 += v.x * v.x + v.y * v.y + v.z * v.z + v.w * v.w;
    }
#pragma unroll
    for (int o = 16; o > 0; o >>= 1) {
        s  += __shfl_xor_sync(0xffffffffu, s,  o);
        s2 += __shfl_xor_sync(0xffffffffu, s2, o);
    }
    __shared__ float rs[16], rs2[16];
    if ((tid & 31) == 0) { rs[tid >> 5] = s; rs2[tid >> 5] = s2; }
    __syncthreads();
    if (tid == 0) {
        float S = 0.f, S2 = 0.f;
#pragma unroll
        for (int i = 0; i < 16; ++i) { S += rs[i]; S2 += rs2[i]; }
        const float invM = 1.f / (float)(LAT * SS);
        float mu = S * invM;
        float var = S2 * invM - mu * mu;
        stats[n] = make_float2(mu, rsqrtf(var + LN_EPS));
    }
}

// ---------------------------------------------------------------------------
// LN affine + ReLU -> bf16 hi + fp8 [hi LAT | lo LAT]
// ---------------------------------------------------------------------------
__global__ __launch_bounds__(256) void affine_relu_split8_kernel(
    const float* __restrict__ att, const float* __restrict__ wT,
    const float* __restrict__ bT, const float2* __restrict__ stats,
    bf16* __restrict__ yhi, uint8_t* __restrict__ y8, float sh, float sl)
{
    const int r = threadIdx.x >> 6;
    const int c = (threadIdx.x & 63) * 8;
    const ll row = (ll)blockIdx.x * 4 + r;
    const int b = (int)(row >> 9), s = (int)(row & 511);
    const float2 st = stats[b];
    const float* xx = att + row * (ll)LAT + c;
    const float* ww = wT + (ll)s * LAT + c;
    const float* bb = bT + (ll)s * LAT + c;

    float4 x0 = *reinterpret_cast<const float4*>(xx);
    float4 x1 = *reinterpret_cast<const float4*>(xx + 4);
    float4 w0 = *reinterpret_cast<const float4*>(ww);
    float4 w1 = *reinterpret_cast<const float4*>(ww + 4);
    float4 b0 = *reinterpret_cast<const float4*>(bb);
    float4 b1 = *reinterpret_cast<const float4*>(bb + 4);
    float xv[8] = {x0.x, x0.y, x0.z, x0.w, x1.x, x1.y, x1.z, x1.w};
    float wv[8] = {w0.x, w0.y, w0.z, w0.w, w1.x, w1.y, w1.z, w1.w};
    float bv[8] = {b0.x, b0.y, b0.z, b0.w, b1.x, b1.y, b1.z, b1.w};

    uint32_t hp[4];
    float hf[8], rf[8];
#pragma unroll
    for (int q = 0; q < 8; ++q) {
        float v = fmaxf((xv[q] - st.x) * st.y * wv[q] + bv[q], 0.f);
        bf16 h = __float2bfloat16_rn(v);
        hf[q] = __bfloat162float(h);
        rf[q] = v - hf[q];
        if (q & 1) hp[q >> 1] = pack_bf(__float2bfloat16_rn(
            fmaxf((xv[q-1] - st.x) * st.y * wv[q-1] + bv[q-1], 0.f)), h);
    }
    ll o = row * (ll)LAT + c;
    *reinterpret_cast<uint4*>(yhi + o) = make_uint4(hp[0], hp[1], hp[2], hp[3]);
    uint8_t* row8 = y8 + row * (ll)(2 * LAT) + c;
    *reinterpret_cast<uint2*>(row8) = make_uint2(
        pack4_e4m3(sh*hf[0], sh*hf[1], sh*hf[2], sh*hf[3]),
        pack4_e4m3(sh*hf[4], sh*hf[5], sh*hf[6], sh*hf[7]));
    *reinterpret_cast<uint2*>(row8 + LAT) = make_uint2(
        pack4_e4m3(sl*rf[0], sl*rf[1], sl*rf[2], sl*rf[3]),
        pack4_e4m3(sl*rf[4], sl*rf[5], sl*rf[6], sl*rf[7]));
}

// ---------------------------------------------------------------------------
// Launch
// ---------------------------------------------------------------------------
extern "C" void kernel_launch(void* const* d_in, const int* in_sizes, int n_in,
                              void* d_out, int out_size)
{
    const float* st_feat = (const float*)d_in[0];
    const float* lt_feat = (const float*)d_in[1];
    const float* w_st    = (const float*)d_in[2];
    const float* b_st    = (const float*)d_in[3];
    const float* w_lt    = (const float*)d_in[4];
    const float* b_lt    = (const float*)d_in[5];
    const float* w_g     = (const float*)d_in[6];
    const float* b_g     = (const float*)d_in[7];
    const float* ln_w    = (const float*)d_in[8];
    const float* ln_b    = (const float*)d_in[9];
    const float* w_out   = (const float*)d_in[10];
    const float* b_out   = (const float*)d_in[11];
    float* out = (float*)d_out;

    unsigned char* pool;
    cudaGetSymbolAddress((void**)&pool, g_pool);
    bf16*    stT_hi = (bf16*)   (pool + O_STT_HI);
    uint8_t* stT_8  = (uint8_t*)(pool + O_STT_8);
    bf16*    ltT_hi = (bf16*)   (pool + O_LTT_HI);
    uint8_t* ltT_8  = (uint8_t*)(pool + O_LTT_8);
    bf16*    th_hi  = (bf16*)   (pool + O_TH_HI);
    uint8_t* th_8   = (uint8_t*)(pool + O_TH_8);
    bf16*    ph_hi  = (bf16*)   (pool + O_PH_HI);
    uint8_t* ph_8   = (uint8_t*)(pool + O_PH_8);
    bf16*    g_hi   = (bf16*)   (pool + O_G_HI);
    bf16*    g_lo   = (bf16*)   (pool + O_G_LO);
    float*   scores = (float*)  (pool + O_SCORE);
    bf16*    p_hi   = (bf16*)   (pool + O_P_HI);
    bf16*    p_lo   = (bf16*)   (pool + O_P_LO);
    float*   att    = (float*)  (pool + O_ATT);
    bf16*    y_hi   = (bf16*)   (pool + O_Y_HI);
    uint8_t* y_8    = (uint8_t*)(pool + O_Y_8);
    bf16*    wst_hi = (bf16*)   (pool + O_WST_HI);
    uint8_t* wst_8  = (uint8_t*)(pool + O_WST_8);
    bf16*    wlt_hi = (bf16*)   (pool + O_WLT_HI);
    uint8_t* wlt_8  = (uint8_t*)(pool + O_WLT_8);
    bf16*    wg_hi  = (bf16*)   (pool + O_WG_HI);
    uint8_t* wg_8   = (uint8_t*)(pool + O_WG_8);
    bf16*    wo_hi  = (bf16*)   (pool + O_WO_HI);
    uint8_t* wo_8   = (uint8_t*)(pool + O_WO_8);
    float*   lnw_t  = (float*)  (pool + O_LNW_T);
    float*   lnb_t  = (float*)  (pool + O_LNB_T);
    float2*  stats  = (float2*) (pool + O_STATS);

    cudaFuncSetAttribute(mma_gemm<0,0>, cudaFuncAttributeMaxDynamicSharedMemorySize, SMEM_TOTAL);
    cudaFuncSetAttribute(mma_gemm<1,0>, cudaFuncAttributeMaxDynamicSharedMemorySize, SMEM_TOTAL);
    cudaFuncSetAttribute(mma_gemm<1,1>, cudaFuncAttributeMaxDynamicSharedMemorySize, SMEM_TOTAL);
    cudaFuncSetAttribute(mma_gemm<1,2>, cudaFuncAttributeMaxDynamicSharedMemorySize, SMEM_TOTAL);

    const float inv_sqrt_lat = 0.044194173824159216f;
    // scales: hi = 2^e, lo = 2^(e+10); e: features 3, weights 9, theta/phi 3, y 4
    const float SH_F = 8.f,    SL_F = 8192.f;
    const float SH_W = 512.f,  SL_W = 524288.f;
    const float SH_T = 8.f,    SL_T = 8192.f;
    const float SH_Y = 16.f,   SL_Y = 16384.f;
    const float US_A = 1.f / 4194304.f;   // 2^-22  (G1,G2,G3)
    const float US_4 = 1.f / 65536.f;     // 2^-16  (G4)
    const float US_6 = 1.f / 8388608.f;   // 2^-23  (G6)

    // --- conversions ---
    wsplit8_kernel<<<512, 256>>>(w_st,  wst_hi, wst_8, C_ST, SH_W, SL_W);
    wsplit8_kernel<<<512, 256>>>(w_lt,  wlt_hi, wlt_8, C_LT, SH_W, SL_W);
    wsplit8_kernel<<<512, 256>>>(w_g,   wg_hi,  wg_8,  C_LT, SH_W, SL_W);
    wsplit8_kernel<<<512, 256>>>(w_out, wo_hi,  wo_8,  LAT,  SH_W, SL_W);
    transpose_split8_kernel<<<dim3(SS / 64, C_ST / 64, NB), 256>>>(
        st_feat, stT_hi, stT_8, C_ST, SS, SH_F, SL_F);
    transpose_split8_kernel<<<dim3(LL / 64, C_LT / 64, NB), 256>>>(
        lt_feat, ltT_hi, ltT_8, C_LT, LL, SH_F, SL_F);
    transpose_f32_kernel<<<dim3(SS / 32, LAT / 32), 256>>>(ln_w, lnw_t, LAT, SS);
    transpose_f32_kernel<<<dim3(SS / 32, LAT / 32), 256>>>(ln_b, lnb_t, LAT, SS);

    // --- G1: theta(s,lat) -> bf16 hi + fp8 ---
    mma_gemm<1,2><<<dim3(LAT / 256, SS / 128, NB), 256, SMEM_TOTAL>>>(
        stT_hi, stT_8, wst_hi, wst_8, nullptr, th_hi, nullptr, th_8,
        C_ST, LAT, (ll)SS * C_ST, 0, (ll)SS * LAT, 1.f, b_st, 1, US_A, SH_T, SL_T);

    // --- G2: phi(l,lat) -> bf16 hi + fp8 ---
    mma_gemm<1,2><<<dim3(LAT / 256, LL / 128, NB), 256, SMEM_TOTAL>>>(
        ltT_hi, ltT_8, wlt_hi, wlt_8, nullptr, ph_hi, nullptr, ph_8,
        C_LT, LAT, (ll)LL * C_LT, 0, (ll)LL * LAT, 1.f, b_lt, 1, US_A, SH_T, SL_T);

    // --- G3: g(lat,l) -> bf16 hi/lo (for bf16 G5) ---
    mma_gemm<1,1><<<dim3(LL / 256, LAT / 128, NB), 256, SMEM_TOTAL>>>(
        wg_hi, wg_8, ltT_hi, ltT_8, nullptr, g_hi, g_lo, nullptr,
        C_LT, LL, 0, (ll)LL * C_LT, (ll)LAT * LL, 1.f, b_g, 0, US_A, 0.f, 0.f);

    // --- G4: scores(s,l) fp32 ---
    mma_gemm<1,0><<<dim3(LL / 256, SS / 128, NB), 256, SMEM_TOTAL>>>(
        th_hi, th_8, ph_hi, ph_8, scores, nullptr, nullptr, nullptr,
        LAT, LL, (ll)SS * LAT, (ll)LL * LAT, (ll)SS * LL,
        inv_sqrt_lat, nullptr, 0, US_4, 0.f, 0.f);

    // --- softmax + bf16 split ---
    softmax_split_kernel<<<NB * SS, 256>>>(scores, p_hi, p_lo);

    // --- G5: att(s,lat) fp32, bf16 3-term ---
    mma_gemm<0,0><<<dim3(LAT / 256, SS / 128, NB), 256, SMEM_TOTAL>>>(
        p_hi, p_lo, g_hi, g_lo, att, nullptr, nullptr, nullptr,
        LL, LAT, (ll)SS * LL, (ll)LAT * LL, (ll)SS * LAT,
        1.f, nullptr, 0, 0.f, 0.f, 0.f);

    // --- LN stats + affine/relu -> bf16 hi + fp8 ---
    stats_kernel<<<NB, 512>>>(att, stats);
    affine_relu_split8_kernel<<<NB * SS / 4, 256>>>(
        att, lnw_t, lnb_t, stats, y_hi, y_8, SH_Y, SL_Y);

    // --- G6: out(c,s) fp32 -> d_out ---
    mma_gemm<1,0><<<dim3(SS / 256, C_ST / 128, NB), 256, SMEM_TOTAL>>>(
        wo_hi, wo_8, y_hi, y_8, out, nullptr, nullptr, nullptr,
        LAT, SS, 0, (ll)SS * LAT, (ll)C_ST * SS, 1.f, b_out, 0, US_6, 0.f, 0.f);
}

// round 9
// speedup vs baseline: 1.4743x; 1.4743x over previous
#include <cuda_runtime.h>
#include <cuda_bf16.h>
#include <cstdint>
#include <math.h>

// ---------------------------------------------------------------------------
// Problem constants
// ---------------------------------------------------------------------------
#define NB    32
#define C_ST  2048
#define C_LT  2048
#define LAT   512
#define SS    512
#define LL    2048
#define LN_EPS 1e-5f

typedef long long ll;
typedef __nv_bfloat16 bf16;

// ---------------------------------------------------------------------------
// Scratch pool (single __device__ global; offsets in bytes, 256-aligned)
// ---------------------------------------------------------------------------
static constexpr ll SZ_STT   = (ll)NB * SS  * C_ST * 2;   // one bf16 array
static constexpr ll SZ_LTT   = (ll)NB * LL  * C_LT * 2;
static constexpr ll SZ_THETA = (ll)NB * SS  * LAT  * 2;
static constexpr ll SZ_PHI   = (ll)NB * LL  * LAT  * 2;
static constexpr ll SZ_G     = (ll)NB * LAT * LL   * 2;
static constexpr ll SZ_SCORE = (ll)NB * SS  * LL   * 4;   // fp32
static constexpr ll SZ_P     = (ll)NB * SS  * LL   * 2;
static constexpr ll SZ_ATT   = (ll)NB * SS  * LAT  * 4;   // fp32
static constexpr ll SZ_Y     = (ll)NB * SS  * LAT  * 2;
static constexpr ll SZ_W     = (ll)LAT * C_ST * 2;        // each weight bf16 array
static constexpr ll SZ_LN    = (ll)LAT * SS * 4;          // transposed ln param fp32

static constexpr ll O_STT_HI   = 0;
static constexpr ll O_STT_LO   = O_STT_HI   + SZ_STT;
static constexpr ll O_LTT_HI   = O_STT_LO   + SZ_STT;
static constexpr ll O_LTT_LO   = O_LTT_HI   + SZ_LTT;
static constexpr ll O_THETA_HI = O_LTT_LO   + SZ_LTT;
static constexpr ll O_THETA_LO = O_THETA_HI + SZ_THETA;
static constexpr ll O_PHI_HI   = O_THETA_LO + SZ_THETA;
static constexpr ll O_PHI_LO   = O_PHI_HI   + SZ_PHI;
static constexpr ll O_G_HI     = O_PHI_LO   + SZ_PHI;
static constexpr ll O_G_LO     = O_G_HI     + SZ_G;
static constexpr ll O_SCORE    = O_G_LO     + SZ_G;
static constexpr ll O_P_HI     = O_SCORE    + SZ_SCORE;
static constexpr ll O_P_LO     = O_P_HI     + SZ_P;
static constexpr ll O_ATT      = O_P_LO     + SZ_P;
static constexpr ll O_Y_HI     = O_ATT      + SZ_ATT;
static constexpr ll O_Y_LO     = O_Y_HI     + SZ_Y;
static constexpr ll O_WST_HI   = O_Y_LO     + SZ_Y;
static constexpr ll O_WST_LO   = O_WST_HI   + SZ_W;
static constexpr ll O_WLT_HI   = O_WST_LO   + SZ_W;
static constexpr ll O_WLT_LO   = O_WLT_HI   + SZ_W;
static constexpr ll O_WG_HI    = O_WLT_LO   + SZ_W;
static constexpr ll O_WG_LO    = O_WG_HI    + SZ_W;
static constexpr ll O_WOUT_HI  = O_WG_LO    + SZ_W;
static constexpr ll O_WOUT_LO  = O_WOUT_HI  + SZ_W;
static constexpr ll O_LNW_T    = O_WOUT_LO  + SZ_W;
static constexpr ll O_LNB_T    = O_LNW_T    + SZ_LN;
static constexpr ll O_PSTAT    = O_LNB_T    + SZ_LN;      // 256 x float2 partials
static constexpr ll O_STATS    = O_PSTAT    + 256 * 8;
static constexpr ll POOL_BYTES = O_STATS + 256;

__device__ __align__(256) unsigned char g_pool[POOL_BYTES];

// ---------------------------------------------------------------------------
// PTX helpers (sm_80-compatible path: ldmatrix + mma.sync + cp.async)
// ---------------------------------------------------------------------------
__device__ __forceinline__ uint32_t smem_u32(const void* p) {
    uint32_t a;
    asm("{ .reg .u64 t; cvta.to.shared.u64 t, %1; cvt.u32.u64 %0, t; }"
        : "=r"(a) : "l"(p));
    return a;
}
__device__ __forceinline__ void cpa16(uint32_t s, const void* g) {
    asm volatile("cp.async.cg.shared.global [%0], [%1], 16;" :: "r"(s), "l"(g) : "memory");
}
#define CP_COMMIT asm volatile("cp.async.commit_group;" ::: "memory")
#define CP_WAIT1  asm volatile("cp.async.wait_group 1;" ::: "memory")
#define CP_WAIT0  asm volatile("cp.async.wait_group 0;" ::: "memory")

#define LDSM4(r, addr) \
    asm volatile("ldmatrix.sync.aligned.m8n8.x4.shared.b16 {%0,%1,%2,%3}, [%4];" \
        : "=r"((r)[0]), "=r"((r)[1]), "=r"((r)[2]), "=r"((r)[3]) : "r"(addr))

#define MMA16816(d, a, b0, b1) \
    asm volatile("mma.sync.aligned.m16n8k16.row.col.f32.bf16.bf16.f32 " \
        "{%0,%1,%2,%3}, {%4,%5,%6,%7}, {%8,%9}, {%0,%1,%2,%3};" \
        : "+f"((d)[0]), "+f"((d)[1]), "+f"((d)[2]), "+f"((d)[3]) \
        : "r"((a)[0]), "r"((a)[1]), "r"((a)[2]), "r"((a)[3]), "r"(b0), "r"(b1))

__device__ __forceinline__ uint32_t pack_bf(bf16 a, bf16 b) {
    return (uint32_t)__bfloat16_as_ushort(a) | ((uint32_t)__bfloat16_as_ushort(b) << 16);
}
__device__ __forceinline__ void split1(float v, bf16& h, bf16& l) {
    h = __float2bfloat16_rn(v);
    l = __float2bfloat16_rn(v - __bfloat162float(h));
}

// ---------------------------------------------------------------------------
// Tensor-core GEMM (mma.sync bf16, split hi/lo 3-term):
//   C(m,n) = alpha * sum_k (Ahi+Alo)(m,k)*(Bhi+Blo)(n,k) + bias   [lo*lo dropped]
//   A, B K-major (lda=ldb=K). CTA tile M=128, N=256, K-chunk 64.
//   Warp grid 2(m) x 4(n); warp tile 64x64. 2-stage cp.async double buffer.
//   OUT=0: fp32 to Cf.  OUT=1: split hi/lo bf16 to Chi/Clo.
// Stage layout: Ahi[0,16K) Alo[16K,32K) Bhi[32K,64K) Blo[64K,96K)
// ---------------------------------------------------------------------------
static constexpr int STAGE_BYTES = 98304;
static constexpr int STAGES      = 2;
static constexpr int SMEM_TOTAL  = STAGES * STAGE_BYTES;   // 196608

template <int OUT>
__global__ __launch_bounds__(256) void mma_gemm(
    const bf16* __restrict__ Ahi, const bf16* __restrict__ Alo,
    const bf16* __restrict__ Bhi, const bf16* __restrict__ Blo,
    float* __restrict__ Cf, bf16* __restrict__ Chi, bf16* __restrict__ Clo,
    int K, int ldc, ll sA, ll sB, ll sC,
    float alpha, const float* __restrict__ bias, int bias_per_n)
{
    extern __shared__ __align__(1024) char smem[];
    const uint32_t sb = smem_u32(smem);
    const int tid  = threadIdx.x;
    const int wid  = tid >> 5, lane = tid & 31;
    const ll  b    = blockIdx.z;
    const int m0   = blockIdx.y << 7;
    const int n0   = blockIdx.x << 8;

    const bf16* Ah = Ahi + b * sA;
    const bf16* Al = Alo + b * sA;
    const bf16* Bh = Bhi + b * sB;
    const bf16* Bl = Blo + b * sB;

    const int C = K >> 6;

    auto load_chunk = [&](int ct, int stg) {
        const uint32_t base = sb + stg * STAGE_BYTES;
        const int kt = ct << 6;
#pragma unroll
        for (int i = 0; i < 4; ++i) {           // A: 128 rows x 128B (each half)
            int idx = tid + (i << 8);
            int row = idx >> 3, seg = idx & 7;
            ll  go  = (ll)(m0 + row) * K + kt + (seg << 3);
            uint32_t so = (uint32_t)((row << 7) + (seg << 4));
            so ^= (so >> 3) & 0x70;
            cpa16(base + so,         Ah + go);
            cpa16(base + 16384 + so, Al + go);
        }
#pragma unroll
        for (int i = 0; i < 8; ++i) {           // B: 256 rows x 128B (each half)
            int idx = tid + (i << 8);
            int row = idx >> 3, seg = idx & 7;
            ll  go  = (ll)(n0 + row) * K + kt + (seg << 3);
            uint32_t so = (uint32_t)((row << 7) + (seg << 4));
            so ^= (so >> 3) & 0x70;
            cpa16(base + 32768 + so, Bh + go);
            cpa16(base + 65536 + so, Bl + go);
        }
    };

    load_chunk(0, 0); CP_COMMIT;

    // warp tiling: 2 (m) x 4 (n); each warp 64(m) x 64(n)
    const int wm = wid >> 2, wn = wid & 3;
    float acc[4][8][4];
#pragma unroll
    for (int i = 0; i < 4; ++i)
#pragma unroll
        for (int j = 0; j < 8; ++j)
#pragma unroll
            for (int q = 0; q < 4; ++q) acc[i][j][q] = 0.f;

    // ldmatrix lane addressing (within tile, before swizzle)
    const uint32_t a_row = (uint32_t)(wm * 64 + (lane & 15));
    const uint32_t a_sb  = (uint32_t)(lane >> 4);            // +seg for k8-15
    const uint32_t b_row = (uint32_t)(wn * 64 + ((lane >> 4) << 3) + (lane & 7));
    const uint32_t b_sb  = (uint32_t)((lane >> 3) & 1);

    for (int ct = 0; ct < C; ++ct) {
        const uint32_t sbase = sb + (ct & 1) * STAGE_BYTES;
        if (ct + 1 < C) { load_chunk(ct + 1, (ct + 1) & 1); CP_COMMIT; CP_WAIT1; }
        else            { CP_WAIT0; }
        __syncthreads();

#pragma unroll
        for (int s = 0; s < 4; ++s) {           // 4 x k16 per chunk
            uint32_t ah[4][4], al4[4][4];
#pragma unroll
            for (int mt = 0; mt < 4; ++mt) {
                uint32_t row = a_row + mt * 16;
                uint32_t seg = (uint32_t)(s * 2) + a_sb;
                uint32_t off = (row << 7) + (seg << 4);
                off ^= (off >> 3) & 0x70;
                LDSM4(ah[mt],  sbase + off);
                LDSM4(al4[mt], sbase + 16384 + off);
            }
            uint32_t bh[4][4], bl4[4][4];
#pragma unroll
            for (int ng = 0; ng < 4; ++ng) {
                uint32_t row = b_row + ng * 16;
                uint32_t seg = (uint32_t)(s * 2) + b_sb;
                uint32_t off = (row << 7) + (seg << 4);
                off ^= (off >> 3) & 0x70;
                LDSM4(bh[ng],  sbase + 32768 + off);
                LDSM4(bl4[ng], sbase + 65536 + off);
            }
#pragma unroll
            for (int mt = 0; mt < 4; ++mt) {
#pragma unroll
                for (int ng = 0; ng < 4; ++ng) {
                    float* d0 = acc[mt][2 * ng];
                    float* d1 = acc[mt][2 * ng + 1];
                    MMA16816(d0, ah[mt],  bh[ng][0],  bh[ng][1]);
                    MMA16816(d0, ah[mt],  bl4[ng][0], bl4[ng][1]);
                    MMA16816(d0, al4[mt], bh[ng][0],  bh[ng][1]);
                    MMA16816(d1, ah[mt],  bh[ng][2],  bh[ng][3]);
                    MMA16816(d1, ah[mt],  bl4[ng][2], bl4[ng][3]);
                    MMA16816(d1, al4[mt], bh[ng][2],  bh[ng][3]);
                }
            }
        }
        __syncthreads();
    }

    // ---- epilogue: registers -> global ----
    const int l4 = lane >> 2;
    const int l2 = (lane & 3) * 2;
#pragma unroll
    for (int mt = 0; mt < 4; ++mt) {
        const int m = m0 + wm * 64 + mt * 16 + l4;
        float bm0 = 0.f, bm8 = 0.f;
        if (bias && !bias_per_n) { bm0 = bias[m]; bm8 = bias[m + 8]; }
#pragma unroll
        for (int nt = 0; nt < 8; ++nt) {
            const int n = n0 + wn * 64 + nt * 8 + l2;
            float bn0 = 0.f, bn1 = 0.f;
            if (bias && bias_per_n) { bn0 = bias[n]; bn1 = bias[n + 1]; }
            const float* a4 = acc[mt][nt];
            float v00 = a4[0] * alpha, v01 = a4[1] * alpha;
            float v10 = a4[2] * alpha, v11 = a4[3] * alpha;
            if (bias) {
                if (bias_per_n) { v00 += bn0; v01 += bn1; v10 += bn0; v11 += bn1; }
                else            { v00 += bm0; v01 += bm0; v10 += bm8; v11 += bm8; }
            }
            if (OUT == 0) {
                float* d0 = Cf + b * sC + (ll)m * ldc + n;
                float* d1 = Cf + b * sC + (ll)(m + 8) * ldc + n;
                *reinterpret_cast<float2*>(d0) = make_float2(v00, v01);
                *reinterpret_cast<float2*>(d1) = make_float2(v10, v11);
            } else {
                bf16 h00, h01, h10, h11, l00, l01, l10, l11;
                split1(v00, h00, l00); split1(v01, h01, l01);
                split1(v10, h10, l10); split1(v11, h11, l11);
                ll o0 = b * sC + (ll)m * ldc + n;
                ll o1 = b * sC + (ll)(m + 8) * ldc + n;
                *reinterpret_cast<uint32_t*>(Chi + o0) = pack_bf(h00, h01);
                *reinterpret_cast<uint32_t*>(Chi + o1) = pack_bf(h10, h11);
                *reinterpret_cast<uint32_t*>(Clo + o0) = pack_bf(l00, l01);
                *reinterpret_cast<uint32_t*>(Clo + o1) = pack_bf(l10, l11);
            }
        }
    }
}

// ---------------------------------------------------------------------------
// fp32 -> (hi, lo) bf16 split, elementwise, 8 elems/thread, 16B stores.
// ---------------------------------------------------------------------------
__global__ __launch_bounds__(256) void split_kernel(
    const float* __restrict__ in, bf16* __restrict__ hi, bf16* __restrict__ lo)
{
    ll i = ((ll)blockIdx.x * 256 + threadIdx.x) * 8;
    float4 a = *reinterpret_cast<const float4*>(in + i);
    float4 c = *reinterpret_cast<const float4*>(in + i + 4);
    float v[8] = {a.x, a.y, a.z, a.w, c.x, c.y, c.z, c.w};
    uint32_t hp[4], lp[4];
#pragma unroll
    for (int q = 0; q < 4; ++q) {
        bf16 h0, l0, h1, l1;
        split1(v[2*q], h0, l0); split1(v[2*q+1], h1, l1);
        hp[q] = pack_bf(h0, h1); lp[q] = pack_bf(l0, l1);
    }
    *reinterpret_cast<uint4*>(hi + i) = make_uint4(hp[0], hp[1], hp[2], hp[3]);
    *reinterpret_cast<uint4*>(lo + i) = make_uint4(lp[0], lp[1], lp[2], lp[3]);
}

// ---------------------------------------------------------------------------
// Transpose + split: in (b, R, X) fp32 -> out (b, X, R) hi/lo bf16
// ---------------------------------------------------------------------------
__global__ __launch_bounds__(256) void transpose_split_kernel(
    const float* __restrict__ in, bf16* __restrict__ hi, bf16* __restrict__ lo,
    int R, int X)
{
    __shared__ float t[64][65];
    const ll b = blockIdx.z;
    const float* ib = in + b * (ll)R * X;
    const int x0 = blockIdx.x << 6, r0 = blockIdx.y << 6;
    const int tx = threadIdx.x & 15;
    const int ty = threadIdx.x >> 4;
#pragma unroll
    for (int i = 0; i < 4; ++i) {
        int r = ty + 16 * i;
        float4 v = *reinterpret_cast<const float4*>(
            ib + (ll)(r0 + r) * X + x0 + tx * 4);
        t[r][tx * 4 + 0] = v.x; t[r][tx * 4 + 1] = v.y;
        t[r][tx * 4 + 2] = v.z; t[r][tx * 4 + 3] = v.w;
    }
    __syncthreads();
    const ll ob = b * (ll)R * X;
#pragma unroll
    for (int i = 0; i < 4; ++i) {
        int xr = ty + 16 * i;
        float w0 = t[tx * 4 + 0][xr];
        float w1 = t[tx * 4 + 1][xr];
        float w2 = t[tx * 4 + 2][xr];
        float w3 = t[tx * 4 + 3][xr];
        bf16 h0, l0, h1, l1, h2, l2, h3, l3;
        split1(w0, h0, l0); split1(w1, h1, l1);
        split1(w2, h2, l2); split1(w3, h3, l3);
        ll o = ob + (ll)(x0 + xr) * R + r0 + tx * 4;
        *reinterpret_cast<uint2*>(hi + o) = make_uint2(pack_bf(h0, h1), pack_bf(h2, h3));
        *reinterpret_cast<uint2*>(lo + o) = make_uint2(pack_bf(l0, l1), pack_bf(l2, l3));
    }
}

// ---------------------------------------------------------------------------
// Plain fp32 transpose: in (R, X) -> out (X, R)   (for ln_w / ln_b)
// ---------------------------------------------------------------------------
__global__ __launch_bounds__(256) void transpose_f32_kernel(
    const float* __restrict__ in, float* __restrict__ out, int R, int X)
{
    __shared__ float t[32][33];
    const int x0 = blockIdx.x << 5, r0 = blockIdx.y << 5;
    const int tx = threadIdx.x & 31, ty = threadIdx.x >> 5;
#pragma unroll
    for (int i = 0; i < 4; ++i)
        t[ty + 8 * i][tx] = in[(ll)(r0 + ty + 8 * i) * X + x0 + tx];
    __syncthreads();
#pragma unroll
    for (int i = 0; i < 4; ++i)
        out[(ll)(x0 + ty + 8 * i) * R + r0 + tx] = t[tx][ty + 8 * i];
}

// ---------------------------------------------------------------------------
// Softmax over L (=2048) + split write (packed 16B stores).
// ---------------------------------------------------------------------------
__global__ __launch_bounds__(256) void softmax_split_kernel(
    const float* __restrict__ x, bf16* __restrict__ phi_, bf16* __restrict__ plo_)
{
    const ll row = blockIdx.x;
    const int tid = threadIdx.x;
    const float* p = x + row * (ll)LL + tid * 8;

    float4 a = *reinterpret_cast<const float4*>(p);
    float4 c = *reinterpret_cast<const float4*>(p + 4);
    float v[8] = {a.x, a.y, a.z, a.w, c.x, c.y, c.z, c.w};

    float m = v[0];
#pragma unroll
    for (int i = 1; i < 8; ++i) m = fmaxf(m, v[i]);
#pragma unroll
    for (int o = 16; o > 0; o >>= 1) m = fmaxf(m, __shfl_xor_sync(0xffffffffu, m, o));
    __shared__ float sm[8];
    if ((tid & 31) == 0) sm[tid >> 5] = m;
    __syncthreads();
    float mx = sm[0];
#pragma unroll
    for (int i = 1; i < 8; ++i) mx = fmaxf(mx, sm[i]);

    float s = 0.f;
#pragma unroll
    for (int i = 0; i < 8; ++i) { v[i] = __expf(v[i] - mx); s += v[i]; }
#pragma unroll
    for (int o = 16; o > 0; o >>= 1) s += __shfl_xor_sync(0xffffffffu, s, o);
    __shared__ float ss[8];
    if ((tid & 31) == 0) ss[tid >> 5] = s;
    __syncthreads();
    float tot = 0.f;
#pragma unroll
    for (int i = 0; i < 8; ++i) tot += ss[i];
    float inv = 1.f / tot;

    uint32_t hp[4], lp[4];
#pragma unroll
    for (int q = 0; q < 4; ++q) {
        float r0 = v[2*q] * inv, r1 = v[2*q+1] * inv;
        bf16 h0, l0, h1, l1;
        split1(r0, h0, l0); split1(r1, h1, l1);
        hp[q] = pack_bf(h0, h1); lp[q] = pack_bf(l0, l1);
    }
    ll o = row * (ll)LL + tid * 8;
    *reinterpret_cast<uint4*>(phi_ + o) = make_uint4(hp[0], hp[1], hp[2], hp[3]);
    *reinterpret_cast<uint4*>(plo_ + o) = make_uint4(lp[0], lp[1], lp[2], lp[3]);
}

// ---------------------------------------------------------------------------
// LayerNorm stats, two-phase.
// Phase 1: 256 blocks (8 per batch), each reduces 32768 elements.
// Phase 2: 1 block combines 8 partials per batch.
// ---------------------------------------------------------------------------
__global__ __launch_bounds__(256) void stats1_kernel(
    const float* __restrict__ att, float2* __restrict__ part)
{
    const int blk = blockIdx.x;            // 0..255; batch = blk>>3, chunk = blk&7
    const int n = blk >> 3, ch = blk & 7;
    const float* x = att + (ll)n * LAT * SS + (ll)ch * 32768;
    const int tid = threadIdx.x;
    float s = 0.f, s2 = 0.f;
#pragma unroll
    for (int i = 0; i < 32; ++i) {         // 256 thr * 4 elem * 32 iters = 32768
        float4 v = *reinterpret_cast<const float4*>(x + (ll)(i * 256 + tid) * 4);
        s  += v.x + v.y + v.z + v.w;
        s2 += v.x * v.x + v.y * v.y + v.z * v.z + v.w * v.w;
    }
#pragma unroll
    for (int o = 16; o > 0; o >>= 1) {
        s  += __shfl_xor_sync(0xffffffffu, s,  o);
        s2 += __shfl_xor_sync(0xffffffffu, s2, o);
    }
    __shared__ float rs[8], rs2[8];
    if ((tid & 31) == 0) { rs[tid >> 5] = s; rs2[tid >> 5] = s2; }
    __syncthreads();
    if (tid == 0) {
        float S = 0.f, S2 = 0.f;
#pragma unroll
        for (int i = 0; i < 8; ++i) { S += rs[i]; S2 += rs2[i]; }
        part[blk] = make_float2(S, S2);
    }
}

__global__ __launch_bounds__(32) void stats2_kernel(
    const float2* __restrict__ part, float2* __restrict__ stats)
{
    const int n = threadIdx.x;             // 0..31
    float S = 0.f, S2 = 0.f;
#pragma unroll
    for (int i = 0; i < 8; ++i) {
        float2 p = part[n * 8 + i];
        S += p.x; S2 += p.y;
    }
    const float invM = 1.f / (float)(LAT * SS);
    float mu = S * invM;
    float var = S2 * invM - mu * mu;
    stats[n] = make_float2(mu, rsqrtf(var + LN_EPS));
}

// ---------------------------------------------------------------------------
// LN affine + ReLU + split; wT/bT pre-transposed to (S, LAT).
// ---------------------------------------------------------------------------
__global__ __launch_bounds__(256) void affine_relu_split_kernel(
    const float* __restrict__ att, const float* __restrict__ wT,
    const float* __restrict__ bT, const float2* __restrict__ stats,
    bf16* __restrict__ yhi, bf16* __restrict__ ylo)
{
    const int r = threadIdx.x >> 6;               // 0..3
    const int c = (threadIdx.x & 63) * 8;         // 0..504
    const ll row = (ll)blockIdx.x * 4 + r;        // b*SS + s
    const int b = (int)(row >> 9), s = (int)(row & 511);
    const float2 st = stats[b];
    const float* xx = att + row * (ll)LAT + c;
    const float* ww = wT + (ll)s * LAT + c;
    const float* bb = bT + (ll)s * LAT + c;

    float4 x0 = *reinterpret_cast<const float4*>(xx);
    float4 x1 = *reinterpret_cast<const float4*>(xx + 4);
    float4 w0 = *reinterpret_cast<const float4*>(ww);
    float4 w1 = *reinterpret_cast<const float4*>(ww + 4);
    float4 b0 = *reinterpret_cast<const float4*>(bb);
    float4 b1 = *reinterpret_cast<const float4*>(bb + 4);
    float xv[8] = {x0.x, x0.y, x0.z, x0.w, x1.x, x1.y, x1.z, x1.w};
    float wv[8] = {w0.x, w0.y, w0.z, w0.w, w1.x, w1.y, w1.z, w1.w};
    float bv[8] = {b0.x, b0.y, b0.z, b0.w, b1.x, b1.y, b1.z, b1.w};

    uint32_t hp[4], lp[4];
#pragma unroll
    for (int q = 0; q < 4; ++q) {
        float v0 = fmaxf((xv[2*q]   - st.x) * st.y * wv[2*q]   + bv[2*q],   0.f);
        float v1 = fmaxf((xv[2*q+1] - st.x) * st.y * wv[2*q+1] + bv[2*q+1], 0.f);
        bf16 h0, l0, h1, l1;
        split1(v0, h0, l0); split1(v1, h1, l1);
        hp[q] = pack_bf(h0, h1); lp[q] = pack_bf(l0, l1);
    }
    ll o = row * (ll)LAT + c;
    *reinterpret_cast<uint4*>(yhi + o) = make_uint4(hp[0], hp[1], hp[2], hp[3]);
    *reinterpret_cast<uint4*>(ylo + o) = make_uint4(lp[0], lp[1], lp[2], lp[3]);
}

// ---------------------------------------------------------------------------
// Launch
// ---------------------------------------------------------------------------
extern "C" void kernel_launch(void* const* d_in, const int* in_sizes, int n_in,
                              void* d_out, int out_size)
{
    const float* st_feat = (const float*)d_in[0];
    const float* lt_feat = (const float*)d_in[1];
    const float* w_st    = (const float*)d_in[2];
    const float* b_st    = (const float*)d_in[3];
    const float* w_lt    = (const float*)d_in[4];
    const float* b_lt    = (const float*)d_in[5];
    const float* w_g     = (const float*)d_in[6];
    const float* b_g     = (const float*)d_in[7];
    const float* ln_w    = (const float*)d_in[8];
    const float* ln_b    = (const float*)d_in[9];
    const float* w_out   = (const float*)d_in[10];
    const float* b_out   = (const float*)d_in[11];
    float* out = (float*)d_out;

    unsigned char* pool;
    cudaGetSymbolAddress((void**)&pool, g_pool);
    bf16* stT_hi   = (bf16*)(pool + O_STT_HI);
    bf16* stT_lo   = (bf16*)(pool + O_STT_LO);
    bf16* ltT_hi   = (bf16*)(pool + O_LTT_HI);
    bf16* ltT_lo   = (bf16*)(pool + O_LTT_LO);
    bf16* theta_hi = (bf16*)(pool + O_THETA_HI);
    bf16* theta_lo = (bf16*)(pool + O_THETA_LO);
    bf16* phi_hi   = (bf16*)(pool + O_PHI_HI);
    bf16* phi_lo   = (bf16*)(pool + O_PHI_LO);
    bf16* g_hi     = (bf16*)(pool + O_G_HI);
    bf16* g_lo     = (bf16*)(pool + O_G_LO);
    float* scores  = (float*)(pool + O_SCORE);
    bf16* p_hi     = (bf16*)(pool + O_P_HI);
    bf16* p_lo     = (bf16*)(pool + O_P_LO);
    float* att     = (float*)(pool + O_ATT);
    bf16* y_hi     = (bf16*)(pool + O_Y_HI);
    bf16* y_lo     = (bf16*)(pool + O_Y_LO);
    bf16* wst_hi   = (bf16*)(pool + O_WST_HI);
    bf16* wst_lo   = (bf16*)(pool + O_WST_LO);
    bf16* wlt_hi   = (bf16*)(pool + O_WLT_HI);
    bf16* wlt_lo   = (bf16*)(pool + O_WLT_LO);
    bf16* wg_hi    = (bf16*)(pool + O_WG_HI);
    bf16* wg_lo    = (bf16*)(pool + O_WG_LO);
    bf16* wout_hi  = (bf16*)(pool + O_WOUT_HI);
    bf16* wout_lo  = (bf16*)(pool + O_WOUT_LO);
    float* lnw_t   = (float*)(pool + O_LNW_T);
    float* lnb_t   = (float*)(pool + O_LNB_T);
    float2* pstat  = (float2*)(pool + O_PSTAT);
    float2* stats  = (float2*)(pool + O_STATS);

    cudaFuncSetAttribute(mma_gemm<0>, cudaFuncAttributeMaxDynamicSharedMemorySize, SMEM_TOTAL);
    cudaFuncSetAttribute(mma_gemm<1>, cudaFuncAttributeMaxDynamicSharedMemorySize, SMEM_TOTAL);

    const float inv_sqrt_lat = 0.044194173824159216f;   // 1/sqrt(512)

    // --- operand conversion ---
    split_kernel<<<512, 256>>>(w_st,  wst_hi,  wst_lo);
    split_kernel<<<512, 256>>>(w_lt,  wlt_hi,  wlt_lo);
    split_kernel<<<512, 256>>>(w_g,   wg_hi,   wg_lo);
    split_kernel<<<512, 256>>>(w_out, wout_hi, wout_lo);
    transpose_split_kernel<<<dim3(SS / 64, C_ST / 64, NB), 256>>>(st_feat, stT_hi, stT_lo, C_ST, SS);
    transpose_split_kernel<<<dim3(LL / 64, C_LT / 64, NB), 256>>>(lt_feat, ltT_hi, ltT_lo, C_LT, LL);
    transpose_f32_kernel<<<dim3(SS / 32, LAT / 32), 256>>>(ln_w, lnw_t, LAT, SS);
    transpose_f32_kernel<<<dim3(SS / 32, LAT / 32), 256>>>(ln_b, lnb_t, LAT, SS);

    // --- G1: theta(s,lat) = stT(s,c) . w_st(lat,c) + b_st  -> split ---
    mma_gemm<1><<<dim3(LAT / 256, SS / 128, NB), 256, SMEM_TOTAL>>>(
        stT_hi, stT_lo, wst_hi, wst_lo, nullptr, theta_hi, theta_lo,
        C_ST, LAT, (ll)SS * C_ST, 0, (ll)SS * LAT, 1.f, b_st, 1);

    // --- G2: phi(l,lat) = ltT(l,c) . w_lt(lat,c) + b_lt  -> split ---
    mma_gemm<1><<<dim3(LAT / 256, LL / 128, NB), 256, SMEM_TOTAL>>>(
        ltT_hi, ltT_lo, wlt_hi, wlt_lo, nullptr, phi_hi, phi_lo,
        C_LT, LAT, (ll)LL * C_LT, 0, (ll)LL * LAT, 1.f, b_lt, 1);

    // --- G3: g(lat,l) = w_g(lat,c) . ltT(l,c) + b_g  -> split ---
    mma_gemm<1><<<dim3(LL / 256, LAT / 128, NB), 256, SMEM_TOTAL>>>(
        wg_hi, wg_lo, ltT_hi, ltT_lo, nullptr, g_hi, g_lo,
        C_LT, LL, 0, (ll)LL * C_LT, (ll)LAT * LL, 1.f, b_g, 0);

    // --- G4: scores(s,l) = theta(s,.) . phi(l,.) / sqrt(LAT)  -> fp32 ---
    mma_gemm<0><<<dim3(LL / 256, SS / 128, NB), 256, SMEM_TOTAL>>>(
        theta_hi, theta_lo, phi_hi, phi_lo, scores, nullptr, nullptr,
        LAT, LL, (ll)SS * LAT, (ll)LL * LAT, (ll)SS * LL, inv_sqrt_lat, nullptr, 0);

    // --- softmax over L + split ---
    softmax_split_kernel<<<NB * SS, 256>>>(scores, p_hi, p_lo);

    // --- G5: att(s,lat) = p(s,l) . g(lat,l)  -> fp32 ---
    mma_gemm<0><<<dim3(LAT / 256, SS / 128, NB), 256, SMEM_TOTAL>>>(
        p_hi, p_lo, g_hi, g_lo, att, nullptr, nullptr,
        LL, LAT, (ll)SS * LL, (ll)LAT * LL, (ll)SS * LAT, 1.f, nullptr, 0);

    // --- LayerNorm stats (two-phase) + affine + relu + split ---
    stats1_kernel<<<256, 256>>>(att, pstat);
    stats2_kernel<<<1, 32>>>(pstat, stats);
    affine_relu_split_kernel<<<NB * SS / 4, 256>>>(att, lnw_t, lnb_t, stats, y_hi, y_lo);

    // --- G6: out(c,s) = w_out(c,lat) . y(s,lat) + b_out  -> fp32 (d_out) ---
    mma_gemm<0><<<dim3(SS / 256, C_ST / 128, NB), 256, SMEM_TOTAL>>>(
        wout_hi, wout_lo, y_hi, y_lo, out, nullptr, nullptr,
        LAT, SS, 0, (ll)SS * LAT, (ll)C_ST * SS, 1.f, b_out, 0);
}

// round 10
// speedup vs baseline: 2.1215x; 1.4390x over previous
#include <cuda_runtime.h>
#include <cuda_fp16.h>
#include <cstdint>
#include <math.h>

// ---------------------------------------------------------------------------
// Problem constants
// ---------------------------------------------------------------------------
#define NB    32
#define C_ST  2048
#define C_LT  2048
#define LAT   512
#define SS    512
#define LL    2048
#define LN_EPS 1e-5f

typedef long long ll;
typedef __half fp16;

// ---------------------------------------------------------------------------
// Scratch pool (single __device__ global; offsets in bytes, 256-aligned)
// ---------------------------------------------------------------------------
static constexpr ll SZ_STT   = (ll)NB * SS  * C_ST * 2;
static constexpr ll SZ_LTT   = (ll)NB * LL  * C_LT * 2;
static constexpr ll SZ_THETA = (ll)NB * SS  * LAT  * 2;
static constexpr ll SZ_PHI   = (ll)NB * LL  * LAT  * 2;
static constexpr ll SZ_G     = (ll)NB * LAT * LL   * 2;
static constexpr ll SZ_SCORE = (ll)NB * SS  * LL   * 4;   // fp32
static constexpr ll SZ_P     = (ll)NB * SS  * LL   * 2;
static constexpr ll SZ_ATT   = (ll)NB * SS  * LAT  * 4;   // fp32
static constexpr ll SZ_Y     = (ll)NB * SS  * LAT  * 2;
static constexpr ll SZ_W     = (ll)LAT * C_ST * 2;
static constexpr ll SZ_LN    = (ll)LAT * SS * 4;

static constexpr ll O_STT_HI   = 0;
static constexpr ll O_STT_LO   = O_STT_HI   + SZ_STT;
static constexpr ll O_LTT_HI   = O_STT_LO   + SZ_STT;
static constexpr ll O_LTT_LO   = O_LTT_HI   + SZ_LTT;
static constexpr ll O_THETA_HI = O_LTT_LO   + SZ_LTT;
static constexpr ll O_THETA_LO = O_THETA_HI + SZ_THETA;
static constexpr ll O_PHI_HI   = O_THETA_LO + SZ_THETA;
static constexpr ll O_G_HI     = O_PHI_HI   + SZ_PHI;
static constexpr ll O_SCORE    = O_G_HI     + SZ_G;
static constexpr ll O_P_HI     = O_SCORE    + SZ_SCORE;
static constexpr ll O_P_LO     = O_P_HI     + SZ_P;
static constexpr ll O_ATT      = O_P_LO     + SZ_P;
static constexpr ll O_Y_HI     = O_ATT      + SZ_ATT;
static constexpr ll O_WST_HI   = O_Y_HI     + SZ_Y;
static constexpr ll O_WST_LO   = O_WST_HI   + SZ_W;
static constexpr ll O_WLT_HI   = O_WST_LO   + SZ_W;
static constexpr ll O_WLT_LO   = O_WLT_HI   + SZ_W;
static constexpr ll O_WG_HI    = O_WLT_LO   + SZ_W;
static constexpr ll O_WG_LO    = O_WG_HI    + SZ_W;
static constexpr ll O_WOUT_HI  = O_WG_LO    + SZ_W;
static constexpr ll O_WOUT_LO  = O_WOUT_HI  + SZ_W;
static constexpr ll O_LNW_T    = O_WOUT_LO  + SZ_W;
static constexpr ll O_LNB_T    = O_LNW_T    + SZ_LN;
static constexpr ll O_PSTAT    = O_LNB_T    + SZ_LN;
static constexpr ll O_STATS    = O_PSTAT    + 256 * 8;
static constexpr ll POOL_BYTES = O_STATS + 256;

__device__ __align__(256) unsigned char g_pool[POOL_BYTES];

// ---------------------------------------------------------------------------
// PTX helpers
// ---------------------------------------------------------------------------
__device__ __forceinline__ uint32_t smem_u32(const void* p) {
    uint32_t a;
    asm("{ .reg .u64 t; cvta.to.shared.u64 t, %1; cvt.u32.u64 %0, t; }"
        : "=r"(a) : "l"(p));
    return a;
}
__device__ __forceinline__ void cpa16(uint32_t s, const void* g) {
    asm volatile("cp.async.cg.shared.global [%0], [%1], 16;" :: "r"(s), "l"(g) : "memory");
}
#define CP_COMMIT asm volatile("cp.async.commit_group;" ::: "memory")
#define CP_WAIT1  asm volatile("cp.async.wait_group 1;" ::: "memory")
#define CP_WAIT0  asm volatile("cp.async.wait_group 0;" ::: "memory")

#define LDSM4(r, addr) \
    asm volatile("ldmatrix.sync.aligned.m8n8.x4.shared.b16 {%0,%1,%2,%3}, [%4];" \
        : "=r"((r)[0]), "=r"((r)[1]), "=r"((r)[2]), "=r"((r)[3]) : "r"(addr))

// fp16 MMA, k16, fp32 accumulate (full-rate HMMA class)
#define MMAH(d, a, b0, b1) \
    asm volatile("mma.sync.aligned.m16n8k16.row.col.f32.f16.f16.f32 " \
        "{%0,%1,%2,%3}, {%4,%5,%6,%7}, {%8,%9}, {%0,%1,%2,%3};" \
        : "+f"((d)[0]), "+f"((d)[1]), "+f"((d)[2]), "+f"((d)[3]) \
        : "r"((a)[0]), "r"((a)[1]), "r"((a)[2]), "r"((a)[3]), "r"(b0), "r"(b1))

__device__ __forceinline__ uint32_t pack_h(fp16 a, fp16 b) {
    return (uint32_t)__half_as_ushort(a) | ((uint32_t)__half_as_ushort(b) << 16);
}
__device__ __forceinline__ void split1h(float v, fp16& h, fp16& l) {
    h = __float2half_rn(v);
    l = __float2half_rn(v - __half2float(h));
}

// ---------------------------------------------------------------------------
// Tensor-core GEMM (fp16 2-term):  C(m,n) = alpha*sum_k (Ahi+Alo)(m,k)*Bhi(n,k) + bias
//   A split fp16 hi/lo (near-exact); B single fp16 (the rounding event).
//   A, B K-major (lda=ldb=K). CTA tile M=128, N=256, K-chunk 64.
//   Warp grid 2(m) x 4(n); warp tile 64x64. 2-stage cp.async double buffer.
//   OUT=0: fp32 Cf.  OUT=1: split fp16 hi/lo Chi/Clo.  OUT=2: fp16 hi only.
// Stage layout: Ahi[0,16K) Alo[16K,32K) Bhi[32K,64K)
// ---------------------------------------------------------------------------
static constexpr int STAGE_BYTES = 65536;
static constexpr int SMEM_TOTAL  = 2 * STAGE_BYTES;   // 131072

template <int OUT>
__global__ __launch_bounds__(256) void mma_gemm(
    const fp16* __restrict__ Ahi, const fp16* __restrict__ Alo,
    const fp16* __restrict__ Bhi,
    float* __restrict__ Cf, fp16* __restrict__ Chi, fp16* __restrict__ Clo,
    int K, int ldc, ll sA, ll sB, ll sC,
    float alpha, const float* __restrict__ bias, int bias_per_n)
{
    extern __shared__ __align__(1024) char smem[];
    const uint32_t sb = smem_u32(smem);
    const int tid  = threadIdx.x;
    const int wid  = tid >> 5, lane = tid & 31;
    const ll  b    = blockIdx.z;
    const int m0   = blockIdx.y << 7;
    const int n0   = blockIdx.x << 8;

    const fp16* Ah = Ahi + b * sA;
    const fp16* Al = Alo + b * sA;
    const fp16* Bh = Bhi + b * sB;

    const int C = K >> 6;

    auto load_chunk = [&](int ct, int stg) {
        const uint32_t base = sb + stg * STAGE_BYTES;
        const int kt = ct << 6;
#pragma unroll
        for (int i = 0; i < 4; ++i) {           // A: 128 rows x 128B (hi + lo)
            int idx = tid + (i << 8);
            int row = idx >> 3, seg = idx & 7;
            ll  go  = (ll)(m0 + row) * K + kt + (seg << 3);
            uint32_t so = (uint32_t)((row << 7) + (seg << 4));
            so ^= (so >> 3) & 0x70;
            cpa16(base + so,         Ah + go);
            cpa16(base + 16384 + so, Al + go);
        }
#pragma unroll
        for (int i = 0; i < 8; ++i) {           // B: 256 rows x 128B (hi only)
            int idx = tid + (i << 8);
            int row = idx >> 3, seg = idx & 7;
            ll  go  = (ll)(n0 + row) * K + kt + (seg << 3);
            uint32_t so = (uint32_t)((row << 7) + (seg << 4));
            so ^= (so >> 3) & 0x70;
            cpa16(base + 32768 + so, Bh + go);
        }
    };

    load_chunk(0, 0); CP_COMMIT;

    // warp tiling: 2 (m) x 4 (n); each warp 64(m) x 64(n)
    const int wm = wid >> 2, wn = wid & 3;
    float acc[4][8][4];
#pragma unroll
    for (int i = 0; i < 4; ++i)
#pragma unroll
        for (int j = 0; j < 8; ++j)
#pragma unroll
            for (int q = 0; q < 4; ++q) acc[i][j][q] = 0.f;

    const uint32_t a_row = (uint32_t)(wm * 64 + (lane & 15));
    const uint32_t a_sb  = (uint32_t)(lane >> 4);
    const uint32_t b_row = (uint32_t)(wn * 64 + ((lane >> 4) << 3) + (lane & 7));
    const uint32_t b_sb  = (uint32_t)((lane >> 3) & 1);

    for (int ct = 0; ct < C; ++ct) {
        const uint32_t sbase = sb + (ct & 1) * STAGE_BYTES;
        if (ct + 1 < C) { load_chunk(ct + 1, (ct + 1) & 1); CP_COMMIT; CP_WAIT1; }
        else            { CP_WAIT0; }
        __syncthreads();

#pragma unroll
        for (int s = 0; s < 4; ++s) {           // 4 x k16 per chunk
            uint32_t ah[4][4], al4[4][4];
#pragma unroll
            for (int mt = 0; mt < 4; ++mt) {
                uint32_t row = a_row + mt * 16;
                uint32_t seg = (uint32_t)(s * 2) + a_sb;
                uint32_t off = (row << 7) + (seg << 4);
                off ^= (off >> 3) & 0x70;
                LDSM4(ah[mt],  sbase + off);
                LDSM4(al4[mt], sbase + 16384 + off);
            }
            uint32_t bh[4][4];
#pragma unroll
            for (int ng = 0; ng < 4; ++ng) {
                uint32_t row = b_row + ng * 16;
                uint32_t seg = (uint32_t)(s * 2) + b_sb;
                uint32_t off = (row << 7) + (seg << 4);
                off ^= (off >> 3) & 0x70;
                LDSM4(bh[ng], sbase + 32768 + off);
            }
#pragma unroll
            for (int mt = 0; mt < 4; ++mt) {
#pragma unroll
                for (int ng = 0; ng < 4; ++ng) {
                    float* d0 = acc[mt][2 * ng];
                    float* d1 = acc[mt][2 * ng + 1];
                    MMAH(d0, ah[mt],  bh[ng][0], bh[ng][1]);
                    MMAH(d0, al4[mt], bh[ng][0], bh[ng][1]);
                    MMAH(d1, ah[mt],  bh[ng][2], bh[ng][3]);
                    MMAH(d1, al4[mt], bh[ng][2], bh[ng][3]);
                }
            }
        }
        __syncthreads();
    }

    // ---- epilogue ----
    const int l4 = lane >> 2;
    const int l2 = (lane & 3) * 2;
#pragma unroll
    for (int mt = 0; mt < 4; ++mt) {
        const int m = m0 + wm * 64 + mt * 16 + l4;
        float bm0 = 0.f, bm8 = 0.f;
        if (bias && !bias_per_n) { bm0 = bias[m]; bm8 = bias[m + 8]; }
#pragma unroll
        for (int nt = 0; nt < 8; ++nt) {
            const int n = n0 + wn * 64 + nt * 8 + l2;
            float bn0 = 0.f, bn1 = 0.f;
            if (bias && bias_per_n) { bn0 = bias[n]; bn1 = bias[n + 1]; }
            const float* a4 = acc[mt][nt];
            float v00 = a4[0] * alpha, v01 = a4[1] * alpha;
            float v10 = a4[2] * alpha, v11 = a4[3] * alpha;
            if (bias) {
                if (bias_per_n) { v00 += bn0; v01 += bn1; v10 += bn0; v11 += bn1; }
                else            { v00 += bm0; v01 += bm0; v10 += bm8; v11 += bm8; }
            }
            ll o0 = b * sC + (ll)m * ldc + n;
            ll o1 = b * sC + (ll)(m + 8) * ldc + n;
            if (OUT == 0) {
                *reinterpret_cast<float2*>(Cf + o0) = make_float2(v00, v01);
                *reinterpret_cast<float2*>(Cf + o1) = make_float2(v10, v11);
            } else if (OUT == 1) {
                fp16 h00, h01, h10, h11, l00, l01, l10, l11;
                split1h(v00, h00, l00); split1h(v01, h01, l01);
                split1h(v10, h10, l10); split1h(v11, h11, l11);
                *reinterpret_cast<uint32_t*>(Chi + o0) = pack_h(h00, h01);
                *reinterpret_cast<uint32_t*>(Chi + o1) = pack_h(h10, h11);
                *reinterpret_cast<uint32_t*>(Clo + o0) = pack_h(l00, l01);
                *reinterpret_cast<uint32_t*>(Clo + o1) = pack_h(l10, l11);
            } else {          // OUT == 2: fp16 hi only
                *reinterpret_cast<uint32_t*>(Chi + o0) =
                    pack_h(__float2half_rn(v00), __float2half_rn(v01));
                *reinterpret_cast<uint32_t*>(Chi + o1) =
                    pack_h(__float2half_rn(v10), __float2half_rn(v11));
            }
        }
    }
}

// ---------------------------------------------------------------------------
// fp32 -> scaled fp16 (hi, lo) split, 8 elems/thread, 16B stores.
// ---------------------------------------------------------------------------
__global__ __launch_bounds__(256) void split_kernel(
    const float* __restrict__ in, fp16* __restrict__ hi, fp16* __restrict__ lo,
    float scale)
{
    ll i = ((ll)blockIdx.x * 256 + threadIdx.x) * 8;
    float4 a = *reinterpret_cast<const float4*>(in + i);
    float4 c = *reinterpret_cast<const float4*>(in + i + 4);
    float v[8] = {a.x, a.y, a.z, a.w, c.x, c.y, c.z, c.w};
    uint32_t hp[4], lp[4];
#pragma unroll
    for (int q = 0; q < 4; ++q) {
        fp16 h0, l0, h1, l1;
        split1h(v[2*q] * scale, h0, l0); split1h(v[2*q+1] * scale, h1, l1);
        hp[q] = pack_h(h0, h1); lp[q] = pack_h(l0, l1);
    }
    *reinterpret_cast<uint4*>(hi + i) = make_uint4(hp[0], hp[1], hp[2], hp[3]);
    *reinterpret_cast<uint4*>(lo + i) = make_uint4(lp[0], lp[1], lp[2], lp[3]);
}

// ---------------------------------------------------------------------------
// Transpose + split: in (b, R, X) fp32 -> out (b, X, R) hi/lo fp16
// ---------------------------------------------------------------------------
__global__ __launch_bounds__(256) void transpose_split_kernel(
    const float* __restrict__ in, fp16* __restrict__ hi, fp16* __restrict__ lo,
    int R, int X)
{
    __shared__ float t[64][65];
    const ll b = blockIdx.z;
    const float* ib = in + b * (ll)R * X;
    const int x0 = blockIdx.x << 6, r0 = blockIdx.y << 6;
    const int tx = threadIdx.x & 15;
    const int ty = threadIdx.x >> 4;
#pragma unroll
    for (int i = 0; i < 4; ++i) {
        int r = ty + 16 * i;
        float4 v = *reinterpret_cast<const float4*>(
            ib + (ll)(r0 + r) * X + x0 + tx * 4);
        t[r][tx * 4 + 0] = v.x; t[r][tx * 4 + 1] = v.y;
        t[r][tx * 4 + 2] = v.z; t[r][tx * 4 + 3] = v.w;
    }
    __syncthreads();
    const ll ob = b * (ll)R * X;
#pragma unroll
    for (int i = 0; i < 4; ++i) {
        int xr = ty + 16 * i;
        float w0 = t[tx * 4 + 0][xr];
        float w1 = t[tx * 4 + 1][xr];
        float w2 = t[tx * 4 + 2][xr];
        float w3 = t[tx * 4 + 3][xr];
        fp16 h0, l0, h1, l1, h2, l2, h3, l3;
        split1h(w0, h0, l0); split1h(w1, h1, l1);
        split1h(w2, h2, l2); split1h(w3, h3, l3);
        ll o = ob + (ll)(x0 + xr) * R + r0 + tx * 4;
        *reinterpret_cast<uint2*>(hi + o) = make_uint2(pack_h(h0, h1), pack_h(h2, h3));
        *reinterpret_cast<uint2*>(lo + o) = make_uint2(pack_h(l0, l1), pack_h(l2, l3));
    }
}

// ---------------------------------------------------------------------------
// Plain fp32 transpose (ln params)
// ---------------------------------------------------------------------------
__global__ __launch_bounds__(256) void transpose_f32_kernel(
    const float* __restrict__ in, float* __restrict__ out, int R, int X)
{
    __shared__ float t[32][33];
    const int x0 = blockIdx.x << 5, r0 = blockIdx.y << 5;
    const int tx = threadIdx.x & 31, ty = threadIdx.x >> 5;
#pragma unroll
    for (int i = 0; i < 4; ++i)
        t[ty + 8 * i][tx] = in[(ll)(r0 + ty + 8 * i) * X + x0 + tx];
    __syncthreads();
#pragma unroll
    for (int i = 0; i < 4; ++i)
        out[(ll)(x0 + ty + 8 * i) * R + r0 + tx] = t[tx][ty + 8 * i];
}

// ---------------------------------------------------------------------------
// Softmax over L (=2048); p scaled x1024, split fp16 hi/lo (16B stores).
// ---------------------------------------------------------------------------
__global__ __launch_bounds__(256) void softmax_split_kernel(
    const float* __restrict__ x, fp16* __restrict__ phi_, fp16* __restrict__ plo_)
{
    const ll row = blockIdx.x;
    const int tid = threadIdx.x;
    const float* p = x + row * (ll)LL + tid * 8;

    float4 a = *reinterpret_cast<const float4*>(p);
    float4 c = *reinterpret_cast<const float4*>(p + 4);
    float v[8] = {a.x, a.y, a.z, a.w, c.x, c.y, c.z, c.w};

    float m = v[0];
#pragma unroll
    for (int i = 1; i < 8; ++i) m = fmaxf(m, v[i]);
#pragma unroll
    for (int o = 16; o > 0; o >>= 1) m = fmaxf(m, __shfl_xor_sync(0xffffffffu, m, o));
    __shared__ float sm[8];
    if ((tid & 31) == 0) sm[tid >> 5] = m;
    __syncthreads();
    float mx = sm[0];
#pragma unroll
    for (int i = 1; i < 8; ++i) mx = fmaxf(mx, sm[i]);

    float s = 0.f;
#pragma unroll
    for (int i = 0; i < 8; ++i) { v[i] = __expf(v[i] - mx); s += v[i]; }
#pragma unroll
    for (int o = 16; o > 0; o >>= 1) s += __shfl_xor_sync(0xffffffffu, s, o);
    __shared__ float ss[8];
    if ((tid & 31) == 0) ss[tid >> 5] = s;
    __syncthreads();
    float tot = 0.f;
#pragma unroll
    for (int i = 0; i < 8; ++i) tot += ss[i];
    float inv = 1024.f / tot;     // p scaled by 1024 (undone by alpha in G5)

    uint32_t hp[4], lp[4];
#pragma unroll
    for (int q = 0; q < 4; ++q) {
        fp16 h0, l0, h1, l1;
        split1h(v[2*q] * inv, h0, l0); split1h(v[2*q+1] * inv, h1, l1);
        hp[q] = pack_h(h0, h1); lp[q] = pack_h(l0, l1);
    }
    ll o = row * (ll)LL + tid * 8;
    *reinterpret_cast<uint4*>(phi_ + o) = make_uint4(hp[0], hp[1], hp[2], hp[3]);
    *reinterpret_cast<uint4*>(plo_ + o) = make_uint4(lp[0], lp[1], lp[2], lp[3]);
}

// ---------------------------------------------------------------------------
// LayerNorm stats, two-phase.
// ---------------------------------------------------------------------------
__global__ __launch_bounds__(256) void stats1_kernel(
    const float* __restrict__ att, float2* __restrict__ part)
{
    const int blk = blockIdx.x;
    const int n = blk >> 3, ch = blk & 7;
    const float* x = att + (ll)n * LAT * SS + (ll)ch * 32768;
    const int tid = threadIdx.x;
    float s = 0.f, s2 = 0.f;
#pragma unroll
    for (int i = 0; i < 32; ++i) {
        float4 v = *reinterpret_cast<const float4*>(x + (ll)(i * 256 + tid) * 4);
        s  += v.x + v.y + v.z + v.w;
        s2 += v.x * v.x + v.y * v.y + v.z * v.z + v.w * v.w;
    }
#pragma unroll
    for (int o = 16; o > 0; o >>= 1) {
        s  += __shfl_xor_sync(0xffffffffu, s,  o);
        s2 += __shfl_xor_sync(0xffffffffu, s2, o);
    }
    __shared__ float rs[8], rs2[8];
    if ((tid & 31) == 0) { rs[tid >> 5] = s; rs2[tid >> 5] = s2; }
    __syncthreads();
    if (tid == 0) {
        float S = 0.f, S2 = 0.f;
#pragma unroll
        for (int i = 0; i < 8; ++i) { S += rs[i]; S2 += rs2[i]; }
        part[blk] = make_float2(S, S2);
    }
}

__global__ __launch_bounds__(32) void stats2_kernel(
    const float2* __restrict__ part, float2* __restrict__ stats)
{
    const int n = threadIdx.x;
    float S = 0.f, S2 = 0.f;
#pragma unroll
    for (int i = 0; i < 8; ++i) {
        float2 p = part[n * 8 + i];
        S += p.x; S2 += p.y;
    }
    const float invM = 1.f / (float)(LAT * SS);
    float mu = S * invM;
    float var = S2 * invM - mu * mu;
    stats[n] = make_float2(mu, rsqrtf(var + LN_EPS));
}

// ---------------------------------------------------------------------------
// LN affine + ReLU -> fp16 hi only (y used only as B operand in G6)
// ---------------------------------------------------------------------------
__global__ __launch_bounds__(256) void affine_relu_kernel(
    const float* __restrict__ att, const float* __restrict__ wT,
    const float* __restrict__ bT, const float2* __restrict__ stats,
    fp16* __restrict__ yhi)
{
    const int r = threadIdx.x >> 6;
    const int c = (threadIdx.x & 63) * 8;
    const ll row = (ll)blockIdx.x * 4 + r;
    const int b = (int)(row >> 9), s = (int)(row & 511);
    const float2 st = stats[b];
    const float* xx = att + row * (ll)LAT + c;
    const float* ww = wT + (ll)s * LAT + c;
    const float* bb = bT + (ll)s * LAT + c;

    float4 x0 = *reinterpret_cast<const float4*>(xx);
    float4 x1 = *reinterpret_cast<const float4*>(xx + 4);
    float4 w0 = *reinterpret_cast<const float4*>(ww);
    float4 w1 = *reinterpret_cast<const float4*>(ww + 4);
    float4 b0 = *reinterpret_cast<const float4*>(bb);
    float4 b1 = *reinterpret_cast<const float4*>(bb + 4);
    float xv[8] = {x0.x, x0.y, x0.z, x0.w, x1.x, x1.y, x1.z, x1.w};
    float wv[8] = {w0.x, w0.y, w0.z, w0.w, w1.x, w1.y, w1.z, w1.w};
    float bv[8] = {b0.x, b0.y, b0.z, b0.w, b1.x, b1.y, b1.z, b1.w};

    uint32_t hp[4];
#pragma unroll
    for (int q = 0; q < 4; ++q) {
        float v0 = fmaxf((xv[2*q]   - st.x) * st.y * wv[2*q]   + bv[2*q],   0.f);
        float v1 = fmaxf((xv[2*q+1] - st.x) * st.y * wv[2*q+1] + bv[2*q+1], 0.f);
        hp[q] = pack_h(__float2half_rn(v0), __float2half_rn(v1));
    }
    ll o = row * (ll)LAT + c;
    *reinterpret_cast<uint4*>(yhi + o) = make_uint4(hp[0], hp[1], hp[2], hp[3]);
}

// ---------------------------------------------------------------------------
// Launch
// ---------------------------------------------------------------------------
extern "C" void kernel_launch(void* const* d_in, const int* in_sizes, int n_in,
                              void* d_out, int out_size)
{
    const float* st_feat = (const float*)d_in[0];
    const float* lt_feat = (const float*)d_in[1];
    const float* w_st    = (const float*)d_in[2];
    const float* b_st    = (const float*)d_in[3];
    const float* w_lt    = (const float*)d_in[4];
    const float* b_lt    = (const float*)d_in[5];
    const float* w_g     = (const float*)d_in[6];
    const float* b_g     = (const float*)d_in[7];
    const float* ln_w    = (const float*)d_in[8];
    const float* ln_b    = (const float*)d_in[9];
    const float* w_out   = (const float*)d_in[10];
    const float* b_out   = (const float*)d_in[11];
    float* out = (float*)d_out;

    unsigned char* pool;
    cudaGetSymbolAddress((void**)&pool, g_pool);
    fp16* stT_hi   = (fp16*)(pool + O_STT_HI);
    fp16* stT_lo   = (fp16*)(pool + O_STT_LO);
    fp16* ltT_hi   = (fp16*)(pool + O_LTT_HI);
    fp16* ltT_lo   = (fp16*)(pool + O_LTT_LO);
    fp16* theta_hi = (fp16*)(pool + O_THETA_HI);
    fp16* theta_lo = (fp16*)(pool + O_THETA_LO);
    fp16* phi_hi   = (fp16*)(pool + O_PHI_HI);
    fp16* g_hi     = (fp16*)(pool + O_G_HI);
    float* scores  = (float*)(pool + O_SCORE);
    fp16* p_hi     = (fp16*)(pool + O_P_HI);
    fp16* p_lo     = (fp16*)(pool + O_P_LO);
    float* att     = (float*)(pool + O_ATT);
    fp16* y_hi     = (fp16*)(pool + O_Y_HI);
    fp16* wst_hi   = (fp16*)(pool + O_WST_HI);
    fp16* wst_lo   = (fp16*)(pool + O_WST_LO);
    fp16* wlt_hi   = (fp16*)(pool + O_WLT_HI);
    fp16* wlt_lo   = (fp16*)(pool + O_WLT_LO);
    fp16* wg_hi    = (fp16*)(pool + O_WG_HI);
    fp16* wg_lo    = (fp16*)(pool + O_WG_LO);
    fp16* wout_hi  = (fp16*)(pool + O_WOUT_HI);
    fp16* wout_lo  = (fp16*)(pool + O_WOUT_LO);
    float* lnw_t   = (float*)(pool + O_LNW_T);
    float* lnb_t   = (float*)(pool + O_LNB_T);
    float2* pstat  = (float2*)(pool + O_PSTAT);
    float2* stats  = (float2*)(pool + O_STATS);

    cudaFuncSetAttribute(mma_gemm<0>, cudaFuncAttributeMaxDynamicSharedMemorySize, SMEM_TOTAL);
    cudaFuncSetAttribute(mma_gemm<1>, cudaFuncAttributeMaxDynamicSharedMemorySize, SMEM_TOTAL);
    cudaFuncSetAttribute(mma_gemm<2>, cudaFuncAttributeMaxDynamicSharedMemorySize, SMEM_TOTAL);

    const float inv_sqrt_lat = 0.044194173824159216f;   // 1/sqrt(512)
    const float WS = 64.f, IWS = 1.f / 64.f;            // weight pre-scale
    const float IPS = 1.f / 1024.f;                     // p pre-scale undo

    // --- operand conversion ---
    split_kernel<<<512, 256>>>(w_st,  wst_hi,  wst_lo,  WS);
    split_kernel<<<512, 256>>>(w_lt,  wlt_hi,  wlt_lo,  WS);
    split_kernel<<<512, 256>>>(w_g,   wg_hi,   wg_lo,   WS);
    split_kernel<<<512, 256>>>(w_out, wout_hi, wout_lo, WS);
    transpose_split_kernel<<<dim3(SS / 64, C_ST / 64, NB), 256>>>(st_feat, stT_hi, stT_lo, C_ST, SS);
    transpose_split_kernel<<<dim3(LL / 64, C_LT / 64, NB), 256>>>(lt_feat, ltT_hi, ltT_lo, C_LT, LL);
    transpose_f32_kernel<<<dim3(SS / 32, LAT / 32), 256>>>(ln_w, lnw_t, LAT, SS);
    transpose_f32_kernel<<<dim3(SS / 32, LAT / 32), 256>>>(ln_b, lnb_t, LAT, SS);

    // --- G1: theta(s,lat) = stT(s,c) . w_st(lat,c)/64 + b_st  -> fp16 hi/lo ---
    mma_gemm<1><<<dim3(LAT / 256, SS / 128, NB), 256, SMEM_TOTAL>>>(
        stT_hi, stT_lo, wst_hi, nullptr, theta_hi, theta_lo,
        C_ST, LAT, (ll)SS * C_ST, 0, (ll)SS * LAT, IWS, b_st, 1);

    // --- G2: phi(l,lat) = ltT(l,c) . w_lt(lat,c)/64 + b_lt  -> fp16 hi ---
    mma_gemm<2><<<dim3(LAT / 256, LL / 128, NB), 256, SMEM_TOTAL>>>(
        ltT_hi, ltT_lo, wlt_hi, nullptr, phi_hi, nullptr,
        C_LT, LAT, (ll)LL * C_LT, 0, (ll)LL * LAT, IWS, b_lt, 1);

    // --- G3: g(lat,l) = w_g(lat,c)/64 . ltT(l,c) + b_g  -> fp16 hi ---
    mma_gemm<2><<<dim3(LL / 256, LAT / 128, NB), 256, SMEM_TOTAL>>>(
        wg_hi, wg_lo, ltT_hi, nullptr, g_hi, nullptr,
        C_LT, LL, 0, (ll)LL * C_LT, (ll)LAT * LL, IWS, b_g, 0);

    // --- G4: scores(s,l) = theta(s,.) . phi(l,.) / sqrt(LAT)  -> fp32 ---
    mma_gemm<0><<<dim3(LL / 256, SS / 128, NB), 256, SMEM_TOTAL>>>(
        theta_hi, theta_lo, phi_hi, scores, nullptr, nullptr,
        LAT, LL, (ll)SS * LAT, (ll)LL * LAT, (ll)SS * LL, inv_sqrt_lat, nullptr, 0);

    // --- softmax over L (+x1024 scale) + fp16 split ---
    softmax_split_kernel<<<NB * SS, 256>>>(scores, p_hi, p_lo);

    // --- G5: att(s,lat) = p(s,l)/1024 . g(lat,l)  -> fp32 ---
    mma_gemm<0><<<dim3(LAT / 256, SS / 128, NB), 256, SMEM_TOTAL>>>(
        p_hi, p_lo, g_hi, att, nullptr, nullptr,
        LL, LAT, (ll)SS * LL, (ll)LAT * LL, (ll)SS * LAT, IPS, nullptr, 0);

    // --- LayerNorm stats (two-phase) + affine + relu -> fp16 hi ---
    stats1_kernel<<<256, 256>>>(att, pstat);
    stats2_kernel<<<1, 32>>>(pstat, stats);
    affine_relu_kernel<<<NB * SS / 4, 256>>>(att, lnw_t, lnb_t, stats, y_hi);

    // --- G6: out(c,s) = w_out(c,lat)/64 . y(s,lat) + b_out  -> fp32 (d_out) ---
    mma_gemm<0><<<dim3(SS / 256, C_ST / 128, NB), 256, SMEM_TOTAL>>>(
        wout_hi, wout_lo, y_hi, out, nullptr, nullptr,
        LAT, SS, 0, (ll)SS * LAT, (ll)C_ST * SS, IWS, b_out, 0);
}

// round 11
// speedup vs baseline: 2.1521x; 1.0144x over previous
#include <cuda_runtime.h>
#include <cuda_fp16.h>
#include <cstdint>
#include <math.h>

// ---------------------------------------------------------------------------
// Problem constants
// ---------------------------------------------------------------------------
#define NB    32
#define C_ST  2048
#define C_LT  2048
#define LAT   512
#define SS    512
#define LL    2048
#define LN_EPS 1e-5f

typedef long long ll;
typedef __half fp16;

// ---------------------------------------------------------------------------
// Scratch pool (single __device__ global; offsets in bytes, 256-aligned)
// ---------------------------------------------------------------------------
static constexpr ll SZ_STT   = (ll)NB * SS  * C_ST * 2;   // hi only
static constexpr ll SZ_LTT   = (ll)NB * LL  * C_LT * 2;   // hi only
static constexpr ll SZ_THETA = (ll)NB * SS  * LAT  * 2;
static constexpr ll SZ_PHI   = (ll)NB * LL  * LAT  * 2;
static constexpr ll SZ_G     = (ll)NB * LAT * LL   * 2;
static constexpr ll SZ_SCORE = (ll)NB * SS  * LL   * 4;   // fp32
static constexpr ll SZ_P     = (ll)NB * SS  * LL   * 2;
static constexpr ll SZ_ATT   = (ll)NB * SS  * LAT  * 4;   // fp32
static constexpr ll SZ_Y     = (ll)NB * SS  * LAT  * 2;
static constexpr ll SZ_W     = (ll)LAT * C_ST * 2;
static constexpr ll SZ_LN    = (ll)LAT * SS * 4;

static constexpr ll O_STT_HI   = 0;
static constexpr ll O_LTT_HI   = O_STT_HI   + SZ_STT;
static constexpr ll O_THETA_HI = O_LTT_HI   + SZ_LTT;
static constexpr ll O_THETA_LO = O_THETA_HI + SZ_THETA;
static constexpr ll O_PHI_HI   = O_THETA_LO + SZ_THETA;
static constexpr ll O_G_HI     = O_PHI_HI   + SZ_PHI;
static constexpr ll O_SCORE    = O_G_HI     + SZ_G;
static constexpr ll O_P_HI     = O_SCORE    + SZ_SCORE;
static constexpr ll O_P_LO     = O_P_HI     + SZ_P;
static constexpr ll O_ATT      = O_P_LO     + SZ_P;
static constexpr ll O_Y_HI     = O_ATT      + SZ_ATT;
static constexpr ll O_WST_HI   = O_Y_HI     + SZ_Y;
static constexpr ll O_WST_LO   = O_WST_HI   + SZ_W;
static constexpr ll O_WLT_HI   = O_WST_LO   + SZ_W;
static constexpr ll O_WLT_LO   = O_WLT_HI   + SZ_W;
static constexpr ll O_WG_HI    = O_WLT_LO   + SZ_W;
static constexpr ll O_WG_LO    = O_WG_HI    + SZ_W;
static constexpr ll O_WOUT_HI  = O_WG_LO    + SZ_W;
static constexpr ll O_WOUT_LO  = O_WOUT_HI  + SZ_W;
static constexpr ll O_LNW_T    = O_WOUT_LO  + SZ_W;
static constexpr ll O_LNB_T    = O_LNW_T    + SZ_LN;
static constexpr ll O_PSTAT    = O_LNB_T    + SZ_LN;
static constexpr ll O_STATS    = O_PSTAT    + 256 * 8;
static constexpr ll POOL_BYTES = O_STATS + 256;

__device__ __align__(256) unsigned char g_pool[POOL_BYTES];

// ---------------------------------------------------------------------------
// PTX helpers
// ---------------------------------------------------------------------------
__device__ __forceinline__ uint32_t smem_u32(const void* p) {
    uint32_t a;
    asm("{ .reg .u64 t; cvta.to.shared.u64 t, %1; cvt.u32.u64 %0, t; }"
        : "=r"(a) : "l"(p));
    return a;
}
__device__ __forceinline__ void cpa16(uint32_t s, const void* g) {
    asm volatile("cp.async.cg.shared.global [%0], [%1], 16;" :: "r"(s), "l"(g) : "memory");
}
#define CP_COMMIT asm volatile("cp.async.commit_group;" ::: "memory")
#define CP_WAIT1  asm volatile("cp.async.wait_group 1;" ::: "memory")
#define CP_WAIT0  asm volatile("cp.async.wait_group 0;" ::: "memory")

#define LDSM4(r, addr) \
    asm volatile("ldmatrix.sync.aligned.m8n8.x4.shared.b16 {%0,%1,%2,%3}, [%4];" \
        : "=r"((r)[0]), "=r"((r)[1]), "=r"((r)[2]), "=r"((r)[3]) : "r"(addr))

// fp16 MMA, k16, fp32 accumulate (full-rate HMMA class)
#define MMAH(d, a, b0, b1) \
    asm volatile("mma.sync.aligned.m16n8k16.row.col.f32.f16.f16.f32 " \
        "{%0,%1,%2,%3}, {%4,%5,%6,%7}, {%8,%9}, {%0,%1,%2,%3};" \
        : "+f"((d)[0]), "+f"((d)[1]), "+f"((d)[2]), "+f"((d)[3]) \
        : "r"((a)[0]), "r"((a)[1]), "r"((a)[2]), "r"((a)[3]), "r"(b0), "r"(b1))

__device__ __forceinline__ uint32_t pack_h(fp16 a, fp16 b) {
    return (uint32_t)__half_as_ushort(a) | ((uint32_t)__half_as_ushort(b) << 16);
}
__device__ __forceinline__ void split1h(float v, fp16& h, fp16& l) {
    h = __float2half_rn(v);
    l = __float2half_rn(v - __half2float(h));
}

// ---------------------------------------------------------------------------
// Tensor-core GEMM (fp16 2-term):  C(m,n) = alpha*sum_k A(m,k)*B(n,k) + bias
//   SPLITB=0: A = Ahi+Alo (exact), B = Bhi (rounded).
//   SPLITB=1: A = Ahi (rounded),  B = Bhi+Blo (exact).
//   A, B K-major (lda=ldb=K). CTA tile M=128, N=256, K-chunk 64.
//   Warp grid 2(m) x 4(n); warp tile 64x64. 2-stage cp.async double buffer.
//   OUT=0: fp32 Cf.  OUT=1: split fp16 hi/lo Chi/Clo.  OUT=2: fp16 hi only.
// Stage layouts:
//   SPLITB=0: Ahi[0,16K) Alo[16K,32K) Bhi[32K,64K)            -> 64K/stage
//   SPLITB=1: Ahi[0,16K) Bhi[16K,48K) Blo[48K,80K)            -> 80K/stage
// ---------------------------------------------------------------------------
template <int SPLITB, int OUT>
__global__ __launch_bounds__(256) void mma_gemm(
    const fp16* __restrict__ Ahi, const fp16* __restrict__ Alo,
    const fp16* __restrict__ Bhi, const fp16* __restrict__ Blo,
    float* __restrict__ Cf, fp16* __restrict__ Chi, fp16* __restrict__ Clo,
    int K, int ldc, ll sA, ll sB, ll sC,
    float alpha, const float* __restrict__ bias, int bias_per_n)
{
    constexpr uint32_t OFF_A_HI = 0;
    constexpr uint32_t OFF_A_LO = 16384;                      // SPLITB==0 only
    constexpr uint32_t OFF_B_HI = SPLITB ? 16384u : 32768u;
    constexpr uint32_t OFF_B_LO = 49152;                      // SPLITB==1 only
    constexpr uint32_t STAGE    = SPLITB ? 81920u : 65536u;

    extern __shared__ __align__(1024) char smem[];
    const uint32_t sb = smem_u32(smem);
    const int tid  = threadIdx.x;
    const int wid  = tid >> 5, lane = tid & 31;
    const ll  b    = blockIdx.z;
    const int m0   = blockIdx.y << 7;
    const int n0   = blockIdx.x << 8;

    const fp16* Ah = Ahi + b * sA;
    const fp16* Al = (SPLITB == 0) ? Alo + b * sA : nullptr;
    const fp16* Bh = Bhi + b * sB;
    const fp16* Bl = (SPLITB == 1) ? Blo + b * sB : nullptr;

    const int C = K >> 6;

    auto load_chunk = [&](int ct, int stg) {
        const uint32_t base = sb + stg * STAGE;
        const int kt = ct << 6;
#pragma unroll
        for (int i = 0; i < 4; ++i) {           // A: 128 rows x 128B
            int idx = tid + (i << 8);
            int row = idx >> 3, seg = idx & 7;
            ll  go  = (ll)(m0 + row) * K + kt + (seg << 3);
            uint32_t so = (uint32_t)((row << 7) + (seg << 4));
            so ^= (so >> 3) & 0x70;
            cpa16(base + OFF_A_HI + so, Ah + go);
            if (SPLITB == 0) cpa16(base + OFF_A_LO + so, Al + go);
        }
#pragma unroll
        for (int i = 0; i < 8; ++i) {           // B: 256 rows x 128B
            int idx = tid + (i << 8);
            int row = idx >> 3, seg = idx & 7;
            ll  go  = (ll)(n0 + row) * K + kt + (seg << 3);
            uint32_t so = (uint32_t)((row << 7) + (seg << 4));
            so ^= (so >> 3) & 0x70;
            cpa16(base + OFF_B_HI + so, Bh + go);
            if (SPLITB == 1) cpa16(base + OFF_B_LO + so, Bl + go);
        }
    };

    load_chunk(0, 0); CP_COMMIT;

    // warp tiling: 2 (m) x 4 (n); each warp 64(m) x 64(n)
    const int wm = wid >> 2, wn = wid & 3;
    float acc[4][8][4];
#pragma unroll
    for (int i = 0; i < 4; ++i)
#pragma unroll
        for (int j = 0; j < 8; ++j)
#pragma unroll
            for (int q = 0; q < 4; ++q) acc[i][j][q] = 0.f;

    const uint32_t a_row = (uint32_t)(wm * 64 + (lane & 15));
    const uint32_t a_sb  = (uint32_t)(lane >> 4);
    const uint32_t b_row = (uint32_t)(wn * 64 + ((lane >> 4) << 3) + (lane & 7));
    const uint32_t b_sb  = (uint32_t)((lane >> 3) & 1);

    for (int ct = 0; ct < C; ++ct) {
        const uint32_t sbase = sb + (ct & 1) * STAGE;
        if (ct + 1 < C) { load_chunk(ct + 1, (ct + 1) & 1); CP_COMMIT; CP_WAIT1; }
        else            { CP_WAIT0; }
        __syncthreads();

#pragma unroll
        for (int s = 0; s < 4; ++s) {           // 4 x k16 per chunk
            uint32_t ah[4][4], a2[4][4];
#pragma unroll
            for (int mt = 0; mt < 4; ++mt) {
                uint32_t row = a_row + mt * 16;
                uint32_t seg = (uint32_t)(s * 2) + a_sb;
                uint32_t off = (row << 7) + (seg << 4);
                off ^= (off >> 3) & 0x70;
                LDSM4(ah[mt], sbase + OFF_A_HI + off);
                if (SPLITB == 0) LDSM4(a2[mt], sbase + OFF_A_LO + off);
            }
            uint32_t bh[4][4], b2[4][4];
#pragma unroll
            for (int ng = 0; ng < 4; ++ng) {
                uint32_t row = b_row + ng * 16;
                uint32_t seg = (uint32_t)(s * 2) + b_sb;
                uint32_t off = (row << 7) + (seg << 4);
                off ^= (off >> 3) & 0x70;
                LDSM4(bh[ng], sbase + OFF_B_HI + off);
                if (SPLITB == 1) LDSM4(b2[ng], sbase + OFF_B_LO + off);
            }
#pragma unroll
            for (int mt = 0; mt < 4; ++mt) {
#pragma unroll
                for (int ng = 0; ng < 4; ++ng) {
                    float* d0 = acc[mt][2 * ng];
                    float* d1 = acc[mt][2 * ng + 1];
                    if (SPLITB == 0) {
                        MMAH(d0, ah[mt], bh[ng][0], bh[ng][1]);
                        MMAH(d0, a2[mt], bh[ng][0], bh[ng][1]);
                        MMAH(d1, ah[mt], bh[ng][2], bh[ng][3]);
                        MMAH(d1, a2[mt], bh[ng][2], bh[ng][3]);
                    } else {
                        MMAH(d0, ah[mt], bh[ng][0], bh[ng][1]);
                        MMAH(d0, ah[mt], b2[ng][0], b2[ng][1]);
                        MMAH(d1, ah[mt], bh[ng][2], bh[ng][3]);
                        MMAH(d1, ah[mt], b2[ng][2], b2[ng][3]);
                    }
                }
            }
        }
        __syncthreads();
    }

    // ---- epilogue ----
    const int l4 = lane >> 2;
    const int l2 = (lane & 3) * 2;
#pragma unroll
    for (int mt = 0; mt < 4; ++mt) {
        const int m = m0 + wm * 64 + mt * 16 + l4;
        float bm0 = 0.f, bm8 = 0.f;
        if (bias && !bias_per_n) { bm0 = bias[m]; bm8 = bias[m + 8]; }
#pragma unroll
        for (int nt = 0; nt < 8; ++nt) {
            const int n = n0 + wn * 64 + nt * 8 + l2;
            float bn0 = 0.f, bn1 = 0.f;
            if (bias && bias_per_n) { bn0 = bias[n]; bn1 = bias[n + 1]; }
            const float* a4 = acc[mt][nt];
            float v00 = a4[0] * alpha, v01 = a4[1] * alpha;
            float v10 = a4[2] * alpha, v11 = a4[3] * alpha;
            if (bias) {
                if (bias_per_n) { v00 += bn0; v01 += bn1; v10 += bn0; v11 += bn1; }
                else            { v00 += bm0; v01 += bm0; v10 += bm8; v11 += bm8; }
            }
            ll o0 = b * sC + (ll)m * ldc + n;
            ll o1 = b * sC + (ll)(m + 8) * ldc + n;
            if (OUT == 0) {
                *reinterpret_cast<float2*>(Cf + o0) = make_float2(v00, v01);
                *reinterpret_cast<float2*>(Cf + o1) = make_float2(v10, v11);
            } else if (OUT == 1) {
                fp16 h00, h01, h10, h11, l00, l01, l10, l11;
                split1h(v00, h00, l00); split1h(v01, h01, l01);
                split1h(v10, h10, l10); split1h(v11, h11, l11);
                *reinterpret_cast<uint32_t*>(Chi + o0) = pack_h(h00, h01);
                *reinterpret_cast<uint32_t*>(Chi + o1) = pack_h(h10, h11);
                *reinterpret_cast<uint32_t*>(Clo + o0) = pack_h(l00, l01);
                *reinterpret_cast<uint32_t*>(Clo + o1) = pack_h(l10, l11);
            } else {          // OUT == 2: fp16 hi only
                *reinterpret_cast<uint32_t*>(Chi + o0) =
                    pack_h(__float2half_rn(v00), __float2half_rn(v01));
                *reinterpret_cast<uint32_t*>(Chi + o1) =
                    pack_h(__float2half_rn(v10), __float2half_rn(v11));
            }
        }
    }
}

// ---------------------------------------------------------------------------
// fp32 -> scaled fp16 (hi, lo) split, 8 elems/thread, 16B stores.
// ---------------------------------------------------------------------------
__global__ __launch_bounds__(256) void split_kernel(
    const float* __restrict__ in, fp16* __restrict__ hi, fp16* __restrict__ lo,
    float scale)
{
    ll i = ((ll)blockIdx.x * 256 + threadIdx.x) * 8;
    float4 a = *reinterpret_cast<const float4*>(in + i);
    float4 c = *reinterpret_cast<const float4*>(in + i + 4);
    float v[8] = {a.x, a.y, a.z, a.w, c.x, c.y, c.z, c.w};
    uint32_t hp[4], lp[4];
#pragma unroll
    for (int q = 0; q < 4; ++q) {
        fp16 h0, l0, h1, l1;
        split1h(v[2*q] * scale, h0, l0); split1h(v[2*q+1] * scale, h1, l1);
        hp[q] = pack_h(h0, h1); lp[q] = pack_h(l0, l1);
    }
    *reinterpret_cast<uint4*>(hi + i) = make_uint4(hp[0], hp[1], hp[2], hp[3]);
    *reinterpret_cast<uint4*>(lo + i) = make_uint4(lp[0], lp[1], lp[2], lp[3]);
}

// ---------------------------------------------------------------------------
// Transpose + fp16 round (hi only): in (b, R, X) fp32 -> out (b, X, R) fp16
// ---------------------------------------------------------------------------
__global__ __launch_bounds__(256) void transpose_h_kernel(
    const float* __restrict__ in, fp16* __restrict__ hi, int R, int X)
{
    __shared__ float t[64][65];
    const ll b = blockIdx.z;
    const float* ib = in + b * (ll)R * X;
    const int x0 = blockIdx.x << 6, r0 = blockIdx.y << 6;
    const int tx = threadIdx.x & 15;
    const int ty = threadIdx.x >> 4;
#pragma unroll
    for (int i = 0; i < 4; ++i) {
        int r = ty + 16 * i;
        float4 v = *reinterpret_cast<const float4*>(
            ib + (ll)(r0 + r) * X + x0 + tx * 4);
        t[r][tx * 4 + 0] = v.x; t[r][tx * 4 + 1] = v.y;
        t[r][tx * 4 + 2] = v.z; t[r][tx * 4 + 3] = v.w;
    }
    __syncthreads();
    const ll ob = b * (ll)R * X;
#pragma unroll
    for (int i = 0; i < 4; ++i) {
        int xr = ty + 16 * i;
        fp16 h0 = __float2half_rn(t[tx * 4 + 0][xr]);
        fp16 h1 = __float2half_rn(t[tx * 4 + 1][xr]);
        fp16 h2 = __float2half_rn(t[tx * 4 + 2][xr]);
        fp16 h3 = __float2half_rn(t[tx * 4 + 3][xr]);
        ll o = ob + (ll)(x0 + xr) * R + r0 + tx * 4;
        *reinterpret_cast<uint2*>(hi + o) = make_uint2(pack_h(h0, h1), pack_h(h2, h3));
    }
}

// ---------------------------------------------------------------------------
// Plain fp32 transpose (ln params)
// ---------------------------------------------------------------------------
__global__ __launch_bounds__(256) void transpose_f32_kernel(
    const float* __restrict__ in, float* __restrict__ out, int R, int X)
{
    __shared__ float t[32][33];
    const int x0 = blockIdx.x << 5, r0 = blockIdx.y << 5;
    const int tx = threadIdx.x & 31, ty = threadIdx.x >> 5;
#pragma unroll
    for (int i = 0; i < 4; ++i)
        t[ty + 8 * i][tx] = in[(ll)(r0 + ty + 8 * i) * X + x0 + tx];
    __syncthreads();
#pragma unroll
    for (int i = 0; i < 4; ++i)
        out[(ll)(x0 + ty + 8 * i) * R + r0 + tx] = t[tx][ty + 8 * i];
}

// ---------------------------------------------------------------------------
// Softmax over L (=2048); p scaled x1024, split fp16 hi/lo (16B stores).
// ---------------------------------------------------------------------------
__global__ __launch_bounds__(256) void softmax_split_kernel(
    const float* __restrict__ x, fp16* __restrict__ phi_, fp16* __restrict__ plo_)
{
    const ll row = blockIdx.x;
    const int tid = threadIdx.x;
    const float* p = x + row * (ll)LL + tid * 8;

    float4 a = *reinterpret_cast<const float4*>(p);
    float4 c = *reinterpret_cast<const float4*>(p + 4);
    float v[8] = {a.x, a.y, a.z, a.w, c.x, c.y, c.z, c.w};

    float m = v[0];
#pragma unroll
    for (int i = 1; i < 8; ++i) m = fmaxf(m, v[i]);
#pragma unroll
    for (int o = 16; o > 0; o >>= 1) m = fmaxf(m, __shfl_xor_sync(0xffffffffu, m, o));
    __shared__ float sm[8];
    if ((tid & 31) == 0) sm[tid >> 5] = m;
    __syncthreads();
    float mx = sm[0];
#pragma unroll
    for (int i = 1; i < 8; ++i) mx = fmaxf(mx, sm[i]);

    float s = 0.f;
#pragma unroll
    for (int i = 0; i < 8; ++i) { v[i] = __expf(v[i] - mx); s += v[i]; }
#pragma unroll
    for (int o = 16; o > 0; o >>= 1) s += __shfl_xor_sync(0xffffffffu, s, o);
    __shared__ float ss[8];
    if ((tid & 31) == 0) ss[tid >> 5] = s;
    __syncthreads();
    float tot = 0.f;
#pragma unroll
    for (int i = 0; i < 8; ++i) tot += ss[i];
    float inv = 1024.f / tot;     // p scaled by 1024 (undone by alpha in G5)

    uint32_t hp[4], lp[4];
#pragma unroll
    for (int q = 0; q < 4; ++q) {
        fp16 h0, l0, h1, l1;
        split1h(v[2*q] * inv, h0, l0); split1h(v[2*q+1] * inv, h1, l1);
        hp[q] = pack_h(h0, h1); lp[q] = pack_h(l0, l1);
    }
    ll o = row * (ll)LL + tid * 8;
    *reinterpret_cast<uint4*>(phi_ + o) = make_uint4(hp[0], hp[1], hp[2], hp[3]);
    *reinterpret_cast<uint4*>(plo_ + o) = make_uint4(lp[0], lp[1], lp[2], lp[3]);
}

// ---------------------------------------------------------------------------
// LayerNorm stats, two-phase.
// ---------------------------------------------------------------------------
__global__ __launch_bounds__(256) void stats1_kernel(
    const float* __restrict__ att, float2* __restrict__ part)
{
    const int blk = blockIdx.x;
    const int n = blk >> 3, ch = blk & 7;
    const float* x = att + (ll)n * LAT * SS + (ll)ch * 32768;
    const int tid = threadIdx.x;
    float s = 0.f, s2 = 0.f;
#pragma unroll
    for (int i = 0; i < 32; ++i) {
        float4 v = *reinterpret_cast<const float4*>(x + (ll)(i * 256 + tid) * 4);
        s  += v.x + v.y + v.z + v.w;
        s2 += v.x * v.x + v.y * v.y + v.z * v.z + v.w * v.w;
    }
#pragma unroll
    for (int o = 16; o > 0; o >>= 1) {
        s  += __shfl_xor_sync(0xffffffffu, s,  o);
        s2 += __shfl_xor_sync(0xffffffffu, s2, o);
    }
    __shared__ float rs[8], rs2[8];
    if ((tid & 31) == 0) { rs[tid >> 5] = s; rs2[tid >> 5] = s2; }
    __syncthreads();
    if (tid == 0) {
        float S = 0.f, S2 = 0.f;
#pragma unroll
        for (int i = 0; i < 8; ++i) { S += rs[i]; S2 += rs2[i]; }
        part[blk] = make_float2(S, S2);
    }
}

__global__ __launch_bounds__(32) void stats2_kernel(
    const float2* __restrict__ part, float2* __restrict__ stats)
{
    const int n = threadIdx.x;
    float S = 0.f, S2 = 0.f;
#pragma unroll
    for (int i = 0; i < 8; ++i) {
        float2 p = part[n * 8 + i];
        S += p.x; S2 += p.y;
    }
    const float invM = 1.f / (float)(LAT * SS);
    float mu = S * invM;
    float var = S2 * invM - mu * mu;
    stats[n] = make_float2(mu, rsqrtf(var + LN_EPS));
}

// ---------------------------------------------------------------------------
// LN affine + ReLU -> fp16 hi only (y used only as B operand... A-hi in G6)
// ---------------------------------------------------------------------------
__global__ __launch_bounds__(256) void affine_relu_kernel(
    const float* __restrict__ att, const float* __restrict__ wT,
    const float* __restrict__ bT, const float2* __restrict__ stats,
    fp16* __restrict__ yhi)
{
    const int r = threadIdx.x >> 6;
    const int c = (threadIdx.x & 63) * 8;
    const ll row = (ll)blockIdx.x * 4 + r;
    const int b = (int)(row >> 9), s = (int)(row & 511);
    const float2 st = stats[b];
    const float* xx = att + row * (ll)LAT + c;
    const float* ww = wT + (ll)s * LAT + c;
    const float* bb = bT + (ll)s * LAT + c;

    float4 x0 = *reinterpret_cast<const float4*>(xx);
    float4 x1 = *reinterpret_cast<const float4*>(xx + 4);
    float4 w0 = *reinterpret_cast<const float4*>(ww);
    float4 w1 = *reinterpret_cast<const float4*>(ww + 4);
    float4 b0 = *reinterpret_cast<const float4*>(bb);
    float4 b1 = *reinterpret_cast<const float4*>(bb + 4);
    float xv[8] = {x0.x, x0.y, x0.z, x0.w, x1.x, x1.y, x1.z, x1.w};
    float wv[8] = {w0.x, w0.y, w0.z, w0.w, w1.x, w1.y, w1.z, w1.w};
    float bv[8] = {b0.x, b0.y, b0.z, b0.w, b1.x, b1.y, b1.z, b1.w};

    uint32_t hp[4];
#pragma unroll
    for (int q = 0; q < 4; ++q) {
        float v0 = fmaxf((xv[2*q]   - st.x) * st.y * wv[2*q]   + bv[2*q],   0.f);
        float v1 = fmaxf((xv[2*q+1] - st.x) * st.y * wv[2*q+1] + bv[2*q+1], 0.f);
        hp[q] = pack_h(__float2half_rn(v0), __float2half_rn(v1));
    }
    ll o = row * (ll)LAT + c;
    *reinterpret_cast<uint4*>(yhi + o) = make_uint4(hp[0], hp[1], hp[2], hp[3]);
}

// ---------------------------------------------------------------------------
// Launch
// ---------------------------------------------------------------------------
extern "C" void kernel_launch(void* const* d_in, const int* in_sizes, int n_in,
                              void* d_out, int out_size)
{
    const float* st_feat = (const float*)d_in[0];
    const float* lt_feat = (const float*)d_in[1];
    const float* w_st    = (const float*)d_in[2];
    const float* b_st    = (const float*)d_in[3];
    const float* w_lt    = (const float*)d_in[4];
    const float* b_lt    = (const float*)d_in[5];
    const float* w_g     = (const float*)d_in[6];
    const float* b_g     = (const float*)d_in[7];
    const float* ln_w    = (const float*)d_in[8];
    const float* ln_b    = (const float*)d_in[9];
    const float* w_out   = (const float*)d_in[10];
    const float* b_out   = (const float*)d_in[11];
    float* out = (float*)d_out;

    unsigned char* pool;
    cudaGetSymbolAddress((void**)&pool, g_pool);
    fp16* stT_hi   = (fp16*)(pool + O_STT_HI);
    fp16* ltT_hi   = (fp16*)(pool + O_LTT_HI);
    fp16* theta_hi = (fp16*)(pool + O_THETA_HI);
    fp16* theta_lo = (fp16*)(pool + O_THETA_LO);
    fp16* phi_hi   = (fp16*)(pool + O_PHI_HI);
    fp16* g_hi     = (fp16*)(pool + O_G_HI);
    float* scores  = (float*)(pool + O_SCORE);
    fp16* p_hi     = (fp16*)(pool + O_P_HI);
    fp16* p_lo     = (fp16*)(pool + O_P_LO);
    float* att     = (float*)(pool + O_ATT);
    fp16* y_hi     = (fp16*)(pool + O_Y_HI);
    fp16* wst_hi   = (fp16*)(pool + O_WST_HI);
    fp16* wst_lo   = (fp16*)(pool + O_WST_LO);
    fp16* wlt_hi   = (fp16*)(pool + O_WLT_HI);
    fp16* wlt_lo   = (fp16*)(pool + O_WLT_LO);
    fp16* wg_hi    = (fp16*)(pool + O_WG_HI);
    fp16* wg_lo    = (fp16*)(pool + O_WG_LO);
    fp16* wout_hi  = (fp16*)(pool + O_WOUT_HI);
    fp16* wout_lo  = (fp16*)(pool + O_WOUT_LO);
    float* lnw_t   = (float*)(pool + O_LNW_T);
    float* lnb_t   = (float*)(pool + O_LNB_T);
    float2* pstat  = (float2*)(pool + O_PSTAT);
    float2* stats  = (float2*)(pool + O_STATS);

    const int SM_A = 2 * 65536;   // SPLITB=0 variants
    const int SM_B = 2 * 81920;   // SPLITB=1 variants
    cudaFuncSetAttribute(mma_gemm<0,0>, cudaFuncAttributeMaxDynamicSharedMemorySize, SM_A);
    cudaFuncSetAttribute(mma_gemm<0,2>, cudaFuncAttributeMaxDynamicSharedMemorySize, SM_A);
    cudaFuncSetAttribute(mma_gemm<1,1>, cudaFuncAttributeMaxDynamicSharedMemorySize, SM_B);
    cudaFuncSetAttribute(mma_gemm<1,2>, cudaFuncAttributeMaxDynamicSharedMemorySize, SM_B);

    const float inv_sqrt_lat = 0.044194173824159216f;   // 1/sqrt(512)
    const float WS = 64.f, IWS = 1.f / 64.f;            // weight pre-scale
    const float IPS = 1.f / 1024.f;                     // p pre-scale undo

    // --- operand conversion ---
    split_kernel<<<512, 256>>>(w_st,  wst_hi,  wst_lo,  WS);
    split_kernel<<<512, 256>>>(w_lt,  wlt_hi,  wlt_lo,  WS);
    split_kernel<<<512, 256>>>(w_g,   wg_hi,   wg_lo,   WS);
    split_kernel<<<512, 256>>>(w_out, wout_hi, wout_lo, WS);
    transpose_h_kernel<<<dim3(SS / 64, C_ST / 64, NB), 256>>>(st_feat, stT_hi, C_ST, SS);
    transpose_h_kernel<<<dim3(LL / 64, C_LT / 64, NB), 256>>>(lt_feat, ltT_hi, C_LT, LL);
    transpose_f32_kernel<<<dim3(SS / 32, LAT / 32), 256>>>(ln_w, lnw_t, LAT, SS);
    transpose_f32_kernel<<<dim3(SS / 32, LAT / 32), 256>>>(ln_b, lnb_t, LAT, SS);

    // --- G1: theta(s,lat) = stT_hi(s,c) . (wst_hi+wst_lo)(lat,c)/64 + b_st -> fp16 hi/lo ---
    mma_gemm<1,1><<<dim3(LAT / 256, SS / 128, NB), 256, SM_B>>>(
        stT_hi, nullptr, wst_hi, wst_lo, nullptr, theta_hi, theta_lo,
        C_ST, LAT, (ll)SS * C_ST, 0, (ll)SS * LAT, IWS, b_st, 1);

    // --- G2: phi(l,lat) = ltT_hi(l,c) . (wlt_hi+wlt_lo)(lat,c)/64 + b_lt -> fp16 hi ---
    mma_gemm<1,2><<<dim3(LAT / 256, LL / 128, NB), 256, SM_B>>>(
        ltT_hi, nullptr, wlt_hi, wlt_lo, nullptr, phi_hi, nullptr,
        C_LT, LAT, (ll)LL * C_LT, 0, (ll)LL * LAT, IWS, b_lt, 1);

    // --- G3: g(lat,l) = (wg_hi+wg_lo)(lat,c)/64 . ltT_hi(l,c) + b_g -> fp16 hi ---
    mma_gemm<0,2><<<dim3(LL / 256, LAT / 128, NB), 256, SM_A>>>(
        wg_hi, wg_lo, ltT_hi, nullptr, nullptr, g_hi, nullptr,
        C_LT, LL, 0, (ll)LL * C_LT, (ll)LAT * LL, IWS, b_g, 0);

    // --- G4: scores(s,l) = (theta_hi+theta_lo)(s,.) . phi_hi(l,.) / sqrt(LAT) -> fp32 ---
    mma_gemm<0,0><<<dim3(LL / 256, SS / 128, NB), 256, SM_A>>>(
        theta_hi, theta_lo, phi_hi, nullptr, scores, nullptr, nullptr,
        LAT, LL, (ll)SS * LAT, (ll)LL * LAT, (ll)SS * LL, inv_sqrt_lat, nullptr, 0);

    // --- softmax over L (+x1024 scale) + fp16 split ---
    softmax_split_kernel<<<NB * SS, 256>>>(scores, p_hi, p_lo);

    // --- G5: att(s,lat) = (p_hi+p_lo)(s,l)/1024 . g_hi(lat,l) -> fp32 ---
    mma_gemm<0,0><<<dim3(LAT / 256, SS / 128, NB), 256, SM_A>>>(
        p_hi, p_lo, g_hi, nullptr, att, nullptr, nullptr,
        LL, LAT, (ll)SS * LL, (ll)LAT * LL, (ll)SS * LAT, IPS, nullptr, 0);

    // --- LayerNorm stats (two-phase) + affine + relu -> fp16 hi ---
    stats1_kernel<<<256, 256>>>(att, pstat);
    stats2_kernel<<<1, 32>>>(pstat, stats);
    affine_relu_kernel<<<NB * SS / 4, 256>>>(att, lnw_t, lnb_t, stats, y_hi);

    // --- G6: out(c,s) = (wout_hi+wout_lo)(c,lat)/64 . y_hi(s,lat) + b_out -> fp32 ---
    mma_gemm<0,0><<<dim3(SS / 256, C_ST / 128, NB), 256, SM_A>>>(
        wout_hi, wout_lo, y_hi, nullptr, out, nullptr, nullptr,
        LAT, SS, 0, (ll)SS * LAT, (ll)C_ST * SS, IWS, b_out, 0);
}

// round 12
// speedup vs baseline: 3.4193x; 1.5888x over previous
#include <cuda_runtime.h>
#include <cuda_fp16.h>
#include <cstdint>
#include <math.h>

// ---------------------------------------------------------------------------
// Problem constants
// ---------------------------------------------------------------------------
#define NB    32
#define C_ST  2048
#define C_LT  2048
#define LAT   512
#define SS    512
#define LL    2048
#define LN_EPS 1e-5f

typedef long long ll;
typedef __half fp16;

// ---------------------------------------------------------------------------
// Scratch pool (single __device__ global; offsets in bytes, 256-aligned)
// ---------------------------------------------------------------------------
static constexpr ll SZ_STT   = (ll)NB * SS  * C_ST * 2;
static constexpr ll SZ_LTT   = (ll)NB * LL  * C_LT * 2;
static constexpr ll SZ_THETA = (ll)NB * SS  * LAT  * 2;
static constexpr ll SZ_PHI   = (ll)NB * LL  * LAT  * 2;
static constexpr ll SZ_G     = (ll)NB * LAT * LL   * 2;
static constexpr ll SZ_SCORE = (ll)NB * SS  * LL   * 4;   // fp32
static constexpr ll SZ_P     = (ll)NB * SS  * LL   * 2;
static constexpr ll SZ_ATT   = (ll)NB * SS  * LAT  * 4;   // fp32
static constexpr ll SZ_Y     = (ll)NB * SS  * LAT  * 2;
static constexpr ll SZ_W     = (ll)LAT * C_ST * 2;
static constexpr ll SZ_LN    = (ll)LAT * SS * 4;

static constexpr ll O_STT    = 0;
static constexpr ll O_LTT    = O_STT   + SZ_STT;
static constexpr ll O_THETA  = O_LTT   + SZ_LTT;
static constexpr ll O_PHI    = O_THETA + SZ_THETA;
static constexpr ll O_G      = O_PHI   + SZ_PHI;
static constexpr ll O_SCORE  = O_G     + SZ_G;
static constexpr ll O_P      = O_SCORE + SZ_SCORE;
static constexpr ll O_ATT    = O_P     + SZ_P;
static constexpr ll O_Y      = O_ATT   + SZ_ATT;
static constexpr ll O_WST    = O_Y     + SZ_Y;
static constexpr ll O_WLT    = O_WST   + SZ_W;
static constexpr ll O_WG     = O_WLT   + SZ_W;
static constexpr ll O_WOUT   = O_WG    + SZ_W;
static constexpr ll O_LNW_T  = O_WOUT  + SZ_W;
static constexpr ll O_LNB_T  = O_LNW_T + SZ_LN;
static constexpr ll O_PSTAT  = O_LNB_T + SZ_LN;
static constexpr ll O_STATS  = O_PSTAT + 256 * 8;
static constexpr ll POOL_BYTES = O_STATS + 256;

__device__ __align__(256) unsigned char g_pool[POOL_BYTES];

// ---------------------------------------------------------------------------
// PTX helpers
// ---------------------------------------------------------------------------
__device__ __forceinline__ uint32_t smem_u32(const void* p) {
    uint32_t a;
    asm("{ .reg .u64 t; cvta.to.shared.u64 t, %1; cvt.u32.u64 %0, t; }"
        : "=r"(a) : "l"(p));
    return a;
}
__device__ __forceinline__ void cpa16(uint32_t s, const void* g) {
    asm volatile("cp.async.cg.shared.global [%0], [%1], 16;" :: "r"(s), "l"(g) : "memory");
}
#define CP_COMMIT asm volatile("cp.async.commit_group;" ::: "memory")
#define CP_WAIT1  asm volatile("cp.async.wait_group 1;" ::: "memory")
#define CP_WAIT0  asm volatile("cp.async.wait_group 0;" ::: "memory")

#define LDSM4(r, addr) \
    asm volatile("ldmatrix.sync.aligned.m8n8.x4.shared.b16 {%0,%1,%2,%3}, [%4];" \
        : "=r"((r)[0]), "=r"((r)[1]), "=r"((r)[2]), "=r"((r)[3]) : "r"(addr))

// fp16 MMA, k16, fp32 accumulate (full-rate HMMA class)
#define MMAH(d, a, b0, b1) \
    asm volatile("mma.sync.aligned.m16n8k16.row.col.f32.f16.f16.f32 " \
        "{%0,%1,%2,%3}, {%4,%5,%6,%7}, {%8,%9}, {%0,%1,%2,%3};" \
        : "+f"((d)[0]), "+f"((d)[1]), "+f"((d)[2]), "+f"((d)[3]) \
        : "r"((a)[0]), "r"((a)[1]), "r"((a)[2]), "r"((a)[3]), "r"(b0), "r"(b1))

__device__ __forceinline__ uint32_t pack_h(fp16 a, fp16 b) {
    return (uint32_t)__half_as_ushort(a) | ((uint32_t)__half_as_ushort(b) << 16);
}

// ---------------------------------------------------------------------------
// Tensor-core GEMM (plain fp16):  C(m,n) = alpha*sum_k A(m,k)*B(n,k) + bias
//   A, B K-major fp16 (lda=ldb=K). CTA tile M=128, N=256, K-chunk 64.
//   Warp grid 2(m) x 4(n); warp tile 64x64. 2-stage cp.async double buffer.
//   OUT=0: fp32 Cf.  OUT=2: fp16 Ch.
// Stage: A[0,16K) B[16K,48K) -> 48K/stage, 96K total.
// ---------------------------------------------------------------------------
static constexpr uint32_t STAGE = 49152;
static constexpr int SMEM_TOTAL = 2 * (int)STAGE;

template <int OUT>
__global__ __launch_bounds__(256) void mma_gemm(
    const fp16* __restrict__ A, const fp16* __restrict__ B,
    float* __restrict__ Cf, fp16* __restrict__ Ch,
    int K, int ldc, ll sA, ll sB, ll sC,
    float alpha, const float* __restrict__ bias, int bias_per_n)
{
    extern __shared__ __align__(1024) char smem[];
    const uint32_t sb = smem_u32(smem);
    const int tid  = threadIdx.x;
    const int wid  = tid >> 5, lane = tid & 31;
    const ll  b    = blockIdx.z;
    const int m0   = blockIdx.y << 7;
    const int n0   = blockIdx.x << 8;

    const fp16* Ab = A + b * sA;
    const fp16* Bb = B + b * sB;

    const int C = K >> 6;

    auto load_chunk = [&](int ct, int stg) {
        const uint32_t base = sb + stg * STAGE;
        const int kt = ct << 6;
#pragma unroll
        for (int i = 0; i < 4; ++i) {           // A: 128 rows x 128B
            int idx = tid + (i << 8);
            int row = idx >> 3, seg = idx & 7;
            uint32_t so = (uint32_t)((row << 7) + (seg << 4));
            so ^= (so >> 3) & 0x70;
            cpa16(base + so, Ab + (ll)(m0 + row) * K + kt + (seg << 3));
        }
#pragma unroll
        for (int i = 0; i < 8; ++i) {           // B: 256 rows x 128B
            int idx = tid + (i << 8);
            int row = idx >> 3, seg = idx & 7;
            uint32_t so = (uint32_t)((row << 7) + (seg << 4));
            so ^= (so >> 3) & 0x70;
            cpa16(base + 16384 + so, Bb + (ll)(n0 + row) * K + kt + (seg << 3));
        }
    };

    load_chunk(0, 0); CP_COMMIT;

    // warp tiling: 2 (m) x 4 (n); each warp 64(m) x 64(n)
    const int wm = wid >> 2, wn = wid & 3;
    float acc[4][8][4];
#pragma unroll
    for (int i = 0; i < 4; ++i)
#pragma unroll
        for (int j = 0; j < 8; ++j)
#pragma unroll
            for (int q = 0; q < 4; ++q) acc[i][j][q] = 0.f;

    const uint32_t a_row = (uint32_t)(wm * 64 + (lane & 15));
    const uint32_t a_sb  = (uint32_t)(lane >> 4);
    const uint32_t b_row = (uint32_t)(wn * 64 + ((lane >> 4) << 3) + (lane & 7));
    const uint32_t b_sb  = (uint32_t)((lane >> 3) & 1);

    for (int ct = 0; ct < C; ++ct) {
        const uint32_t sbase = sb + (ct & 1) * STAGE;
        if (ct + 1 < C) { load_chunk(ct + 1, (ct + 1) & 1); CP_COMMIT; CP_WAIT1; }
        else            { CP_WAIT0; }
        __syncthreads();

#pragma unroll
        for (int s = 0; s < 4; ++s) {           // 4 x k16 per chunk
            uint32_t ah[4][4];
#pragma unroll
            for (int mt = 0; mt < 4; ++mt) {
                uint32_t row = a_row + mt * 16;
                uint32_t seg = (uint32_t)(s * 2) + a_sb;
                uint32_t off = (row << 7) + (seg << 4);
                off ^= (off >> 3) & 0x70;
                LDSM4(ah[mt], sbase + off);
            }
            uint32_t bh[4][4];
#pragma unroll
            for (int ng = 0; ng < 4; ++ng) {
                uint32_t row = b_row + ng * 16;
                uint32_t seg = (uint32_t)(s * 2) + b_sb;
                uint32_t off = (row << 7) + (seg << 4);
                off ^= (off >> 3) & 0x70;
                LDSM4(bh[ng], sbase + 16384 + off);
            }
#pragma unroll
            for (int mt = 0; mt < 4; ++mt) {
#pragma unroll
                for (int ng = 0; ng < 4; ++ng) {
                    MMAH(acc[mt][2 * ng],     ah[mt], bh[ng][0], bh[ng][1]);
                    MMAH(acc[mt][2 * ng + 1], ah[mt], bh[ng][2], bh[ng][3]);
                }
            }
        }
        __syncthreads();
    }

    // ---- epilogue ----
    const int l4 = lane >> 2;
    const int l2 = (lane & 3) * 2;
#pragma unroll
    for (int mt = 0; mt < 4; ++mt) {
        const int m = m0 + wm * 64 + mt * 16 + l4;
        float bm0 = 0.f, bm8 = 0.f;
        if (bias && !bias_per_n) { bm0 = bias[m]; bm8 = bias[m + 8]; }
#pragma unroll
        for (int nt = 0; nt < 8; ++nt) {
            const int n = n0 + wn * 64 + nt * 8 + l2;
            float bn0 = 0.f, bn1 = 0.f;
            if (bias && bias_per_n) { bn0 = bias[n]; bn1 = bias[n + 1]; }
            const float* a4 = acc[mt][nt];
            float v00 = a4[0] * alpha, v01 = a4[1] * alpha;
            float v10 = a4[2] * alpha, v11 = a4[3] * alpha;
            if (bias) {
                if (bias_per_n) { v00 += bn0; v01 += bn1; v10 += bn0; v11 += bn1; }
                else            { v00 += bm0; v01 += bm0; v10 += bm8; v11 += bm8; }
            }
            ll o0 = b * sC + (ll)m * ldc + n;
            ll o1 = b * sC + (ll)(m + 8) * ldc + n;
            if (OUT == 0) {
                *reinterpret_cast<float2*>(Cf + o0) = make_float2(v00, v01);
                *reinterpret_cast<float2*>(Cf + o1) = make_float2(v10, v11);
            } else {
                *reinterpret_cast<uint32_t*>(Ch + o0) =
                    pack_h(__float2half_rn(v00), __float2half_rn(v01));
                *reinterpret_cast<uint32_t*>(Ch + o1) =
                    pack_h(__float2half_rn(v10), __float2half_rn(v11));
            }
        }
    }
}

// ---------------------------------------------------------------------------
// fp32 -> scaled fp16 round, 8 elems/thread, 8B stores.
// ---------------------------------------------------------------------------
__global__ __launch_bounds__(256) void round_kernel(
    const float* __restrict__ in, fp16* __restrict__ out, float scale)
{
    ll i = ((ll)blockIdx.x * 256 + threadIdx.x) * 8;
    float4 a = *reinterpret_cast<const float4*>(in + i);
    float4 c = *reinterpret_cast<const float4*>(in + i + 4);
    float v[8] = {a.x, a.y, a.z, a.w, c.x, c.y, c.z, c.w};
    uint32_t hp[4];
#pragma unroll
    for (int q = 0; q < 4; ++q)
        hp[q] = pack_h(__float2half_rn(v[2*q] * scale), __float2half_rn(v[2*q+1] * scale));
    *reinterpret_cast<uint4*>(out + i) = make_uint4(hp[0], hp[1], hp[2], hp[3]);
}

// ---------------------------------------------------------------------------
// Transpose + fp16 round: in (b, R, X) fp32 -> out (b, X, R) fp16
// ---------------------------------------------------------------------------
__global__ __launch_bounds__(256) void transpose_h_kernel(
    const float* __restrict__ in, fp16* __restrict__ hi, int R, int X)
{
    __shared__ float t[64][65];
    const ll b = blockIdx.z;
    const float* ib = in + b * (ll)R * X;
    const int x0 = blockIdx.x << 6, r0 = blockIdx.y << 6;
    const int tx = threadIdx.x & 15;
    const int ty = threadIdx.x >> 4;
#pragma unroll
    for (int i = 0; i < 4; ++i) {
        int r = ty + 16 * i;
        float4 v = *reinterpret_cast<const float4*>(
            ib + (ll)(r0 + r) * X + x0 + tx * 4);
        t[r][tx * 4 + 0] = v.x; t[r][tx * 4 + 1] = v.y;
        t[r][tx * 4 + 2] = v.z; t[r][tx * 4 + 3] = v.w;
    }
    __syncthreads();
    const ll ob = b * (ll)R * X;
#pragma unroll
    for (int i = 0; i < 4; ++i) {
        int xr = ty + 16 * i;
        fp16 h0 = __float2half_rn(t[tx * 4 + 0][xr]);
        fp16 h1 = __float2half_rn(t[tx * 4 + 1][xr]);
        fp16 h2 = __float2half_rn(t[tx * 4 + 2][xr]);
        fp16 h3 = __float2half_rn(t[tx * 4 + 3][xr]);
        ll o = ob + (ll)(x0 + xr) * R + r0 + tx * 4;
        *reinterpret_cast<uint2*>(hi + o) = make_uint2(pack_h(h0, h1), pack_h(h2, h3));
    }
}

// ---------------------------------------------------------------------------
// Plain fp32 transpose (ln params)
// ---------------------------------------------------------------------------
__global__ __launch_bounds__(256) void transpose_f32_kernel(
    const float* __restrict__ in, float* __restrict__ out, int R, int X)
{
    __shared__ float t[32][33];
    const int x0 = blockIdx.x << 5, r0 = blockIdx.y << 5;
    const int tx = threadIdx.x & 31, ty = threadIdx.x >> 5;
#pragma unroll
    for (int i = 0; i < 4; ++i)
        t[ty + 8 * i][tx] = in[(ll)(r0 + ty + 8 * i) * X + x0 + tx];
    __syncthreads();
#pragma unroll
    for (int i = 0; i < 4; ++i)
        out[(ll)(x0 + ty + 8 * i) * R + r0 + tx] = t[tx][ty + 8 * i];
}

// ---------------------------------------------------------------------------
// Softmax over L (=2048); p scaled x1024, fp16 out (16B stores).
// ---------------------------------------------------------------------------
__global__ __launch_bounds__(256) void softmax_kernel(
    const float* __restrict__ x, fp16* __restrict__ ph)
{
    const ll row = blockIdx.x;
    const int tid = threadIdx.x;
    const float* p = x + row * (ll)LL + tid * 8;

    float4 a = *reinterpret_cast<const float4*>(p);
    float4 c = *reinterpret_cast<const float4*>(p + 4);
    float v[8] = {a.x, a.y, a.z, a.w, c.x, c.y, c.z, c.w};

    float m = v[0];
#pragma unroll
    for (int i = 1; i < 8; ++i) m = fmaxf(m, v[i]);
#pragma unroll
    for (int o = 16; o > 0; o >>= 1) m = fmaxf(m, __shfl_xor_sync(0xffffffffu, m, o));
    __shared__ float sm[8];
    if ((tid & 31) == 0) sm[tid >> 5] = m;
    __syncthreads();
    float mx = sm[0];
#pragma unroll
    for (int i = 1; i < 8; ++i) mx = fmaxf(mx, sm[i]);

    float s = 0.f;
#pragma unroll
    for (int i = 0; i < 8; ++i) { v[i] = __expf(v[i] - mx); s += v[i]; }
#pragma unroll
    for (int o = 16; o > 0; o >>= 1) s += __shfl_xor_sync(0xffffffffu, s, o);
    __shared__ float ss[8];
    if ((tid & 31) == 0) ss[tid >> 5] = s;
    __syncthreads();
    float tot = 0.f;
#pragma unroll
    for (int i = 0; i < 8; ++i) tot += ss[i];
    float inv = 1024.f / tot;     // p scaled by 1024 (undone by alpha in G5)

    uint32_t hp[4];
#pragma unroll
    for (int q = 0; q < 4; ++q)
        hp[q] = pack_h(__float2half_rn(v[2*q] * inv), __float2half_rn(v[2*q+1] * inv));
    ll o = row * (ll)LL + tid * 8;
    *reinterpret_cast<uint4*>(ph + o) = make_uint4(hp[0], hp[1], hp[2], hp[3]);
}

// ---------------------------------------------------------------------------
// LayerNorm stats, two-phase.
// ---------------------------------------------------------------------------
__global__ __launch_bounds__(256) void stats1_kernel(
    const float* __restrict__ att, float2* __restrict__ part)
{
    const int blk = blockIdx.x;
    const int n = blk >> 3, ch = blk & 7;
    const float* x = att + (ll)n * LAT * SS + (ll)ch * 32768;
    const int tid = threadIdx.x;
    float s = 0.f, s2 = 0.f;
#pragma unroll
    for (int i = 0; i < 32; ++i) {
        float4 v = *reinterpret_cast<const float4*>(x + (ll)(i * 256 + tid) * 4);
        s  += v.x + v.y + v.z + v.w;
        s2 += v.x * v.x + v.y * v.y + v.z * v.z + v.w * v.w;
    }
#pragma unroll
    for (int o = 16; o > 0; o >>= 1) {
        s  += __shfl_xor_sync(0xffffffffu, s,  o);
        s2 += __shfl_xor_sync(0xffffffffu, s2, o);
    }
    __shared__ float rs[8], rs2[8];
    if ((tid & 31) == 0) { rs[tid >> 5] = s; rs2[tid >> 5] = s2; }
    __syncthreads();
    if (tid == 0) {
        float S = 0.f, S2 = 0.f;
#pragma unroll
        for (int i = 0; i < 8; ++i) { S += rs[i]; S2 += rs2[i]; }
        part[blk] = make_float2(S, S2);
    }
}

__global__ __launch_bounds__(32) void stats2_kernel(
    const float2* __restrict__ part, float2* __restrict__ stats)
{
    const int n = threadIdx.x;
    float S = 0.f, S2 = 0.f;
#pragma unroll
    for (int i = 0; i < 8; ++i) {
        float2 p = part[n * 8 + i];
        S += p.x; S2 += p.y;
    }
    const float invM = 1.f / (float)(LAT * SS);
    float mu = S * invM;
    float var = S2 * invM - mu * mu;
    stats[n] = make_float2(mu, rsqrtf(var + LN_EPS));
}

// ---------------------------------------------------------------------------
// LN affine + ReLU -> fp16
// ---------------------------------------------------------------------------
__global__ __launch_bounds__(256) void affine_relu_kernel(
    const float* __restrict__ att, const float* __restrict__ wT,
    const float* __restrict__ bT, const float2* __restrict__ stats,
    fp16* __restrict__ yh)
{
    const int r = threadIdx.x >> 6;
    const int c = (threadIdx.x & 63) * 8;
    const ll row = (ll)blockIdx.x * 4 + r;
    const int b = (int)(row >> 9), s = (int)(row & 511);
    const float2 st = stats[b];
    const float* xx = att + row * (ll)LAT + c;
    const float* ww = wT + (ll)s * LAT + c;
    const float* bb = bT + (ll)s * LAT + c;

    float4 x0 = *reinterpret_cast<const float4*>(xx);
    float4 x1 = *reinterpret_cast<const float4*>(xx + 4);
    float4 w0 = *reinterpret_cast<const float4*>(ww);
    float4 w1 = *reinterpret_cast<const float4*>(ww + 4);
    float4 b0 = *reinterpret_cast<const float4*>(bb);
    float4 b1 = *reinterpret_cast<const float4*>(bb + 4);
    float xv[8] = {x0.x, x0.y, x0.z, x0.w, x1.x, x1.y, x1.z, x1.w};
    float wv[8] = {w0.x, w0.y, w0.z, w0.w, w1.x, w1.y, w1.z, w1.w};
    float bv[8] = {b0.x, b0.y, b0.z, b0.w, b1.x, b1.y, b1.z, b1.w};

    uint32_t hp[4];
#pragma unroll
    for (int q = 0; q < 4; ++q) {
        float v0 = fmaxf((xv[2*q]   - st.x) * st.y * wv[2*q]   + bv[2*q],   0.f);
        float v1 = fmaxf((xv[2*q+1] - st.x) * st.y * wv[2*q+1] + bv[2*q+1], 0.f);
        hp[q] = pack_h(__float2half_rn(v0), __float2half_rn(v1));
    }
    ll o = row * (ll)LAT + c;
    *reinterpret_cast<uint4*>(yh + o) = make_uint4(hp[0], hp[1], hp[2], hp[3]);
}

// ---------------------------------------------------------------------------
// Launch
// ---------------------------------------------------------------------------
extern "C" void kernel_launch(void* const* d_in, const int* in_sizes, int n_in,
                              void* d_out, int out_size)
{
    const float* st_feat = (const float*)d_in[0];
    const float* lt_feat = (const float*)d_in[1];
    const float* w_st    = (const float*)d_in[2];
    const float* b_st    = (const float*)d_in[3];
    const float* w_lt    = (const float*)d_in[4];
    const float* b_lt    = (const float*)d_in[5];
    const float* w_g     = (const float*)d_in[6];
    const float* b_g     = (const float*)d_in[7];
    const float* ln_w    = (const float*)d_in[8];
    const float* ln_b    = (const float*)d_in[9];
    const float* w_out   = (const float*)d_in[10];
    const float* b_out   = (const float*)d_in[11];
    float* out = (float*)d_out;

    unsigned char* pool;
    cudaGetSymbolAddress((void**)&pool, g_pool);
    fp16* stT    = (fp16*)(pool + O_STT);
    fp16* ltT    = (fp16*)(pool + O_LTT);
    fp16* theta  = (fp16*)(pool + O_THETA);
    fp16* phi    = (fp16*)(pool + O_PHI);
    fp16* g      = (fp16*)(pool + O_G);
    float* scores= (float*)(pool + O_SCORE);
    fp16* p      = (fp16*)(pool + O_P);
    float* att   = (float*)(pool + O_ATT);
    fp16* y      = (fp16*)(pool + O_Y);
    fp16* wst    = (fp16*)(pool + O_WST);
    fp16* wlt    = (fp16*)(pool + O_WLT);
    fp16* wg     = (fp16*)(pool + O_WG);
    fp16* wout   = (fp16*)(pool + O_WOUT);
    float* lnw_t = (float*)(pool + O_LNW_T);
    float* lnb_t = (float*)(pool + O_LNB_T);
    float2* pstat= (float2*)(pool + O_PSTAT);
    float2* stats= (float2*)(pool + O_STATS);

    cudaFuncSetAttribute(mma_gemm<0>, cudaFuncAttributeMaxDynamicSharedMemorySize, SMEM_TOTAL);
    cudaFuncSetAttribute(mma_gemm<2>, cudaFuncAttributeMaxDynamicSharedMemorySize, SMEM_TOTAL);

    const float inv_sqrt_lat = 0.044194173824159216f;   // 1/sqrt(512)
    const float WS = 64.f, IWS = 1.f / 64.f;            // weight pre-scale
    const float IPS = 1.f / 1024.f;                     // p pre-scale undo

    // --- operand conversion ---
    round_kernel<<<512, 256>>>(w_st,  wst,  WS);
    round_kernel<<<512, 256>>>(w_lt,  wlt,  WS);
    round_kernel<<<512, 256>>>(w_g,   wg,   WS);
    round_kernel<<<512, 256>>>(w_out, wout, WS);
    transpose_h_kernel<<<dim3(SS / 64, C_ST / 64, NB), 256>>>(st_feat, stT, C_ST, SS);
    transpose_h_kernel<<<dim3(LL / 64, C_LT / 64, NB), 256>>>(lt_feat, ltT, C_LT, LL);
    transpose_f32_kernel<<<dim3(SS / 32, LAT / 32), 256>>>(ln_w, lnw_t, LAT, SS);
    transpose_f32_kernel<<<dim3(SS / 32, LAT / 32), 256>>>(ln_b, lnb_t, LAT, SS);

    // --- G1: theta(s,lat) = stT(s,c) . wst(lat,c)/64 + b_st -> fp16 ---
    mma_gemm<2><<<dim3(LAT / 256, SS / 128, NB), 256, SMEM_TOTAL>>>(
        stT, wst, nullptr, theta,
        C_ST, LAT, (ll)SS * C_ST, 0, (ll)SS * LAT, IWS, b_st, 1);

    // --- G2: phi(l,lat) = ltT(l,c) . wlt(lat,c)/64 + b_lt -> fp16 ---
    mma_gemm<2><<<dim3(LAT / 256, LL / 128, NB), 256, SMEM_TOTAL>>>(
        ltT, wlt, nullptr, phi,
        C_LT, LAT, (ll)LL * C_LT, 0, (ll)LL * LAT, IWS, b_lt, 1);

    // --- G3: g(lat,l) = wg(lat,c)/64 . ltT(l,c) + b_g -> fp16 ---
    mma_gemm<2><<<dim3(LL / 256, LAT / 128, NB), 256, SMEM_TOTAL>>>(
        wg, ltT, nullptr, g,
        C_LT, LL, 0, (ll)LL * C_LT, (ll)LAT * LL, IWS, b_g, 0);

    // --- G4: scores(s,l) = theta(s,.) . phi(l,.) / sqrt(LAT) -> fp32 ---
    mma_gemm<0><<<dim3(LL / 256, SS / 128, NB), 256, SMEM_TOTAL>>>(
        theta, phi, scores, nullptr,
        LAT, LL, (ll)SS * LAT, (ll)LL * LAT, (ll)SS * LL, inv_sqrt_lat, nullptr, 0);

    // --- softmax over L (+x1024 scale) -> fp16 ---
    softmax_kernel<<<NB * SS, 256>>>(scores, p);

    // --- G5: att(s,lat) = p(s,l)/1024 . g(lat,l) -> fp32 ---
    mma_gemm<0><<<dim3(LAT / 256, SS / 128, NB), 256, SMEM_TOTAL>>>(
        p, g, att, nullptr,
        LL, LAT, (ll)SS * LL, (ll)LAT * LL, (ll)SS * LAT, IPS, nullptr, 0);

    // --- LayerNorm stats (two-phase) + affine + relu -> fp16 ---
    stats1_kernel<<<256, 256>>>(att, pstat);
    stats2_kernel<<<1, 32>>>(pstat, stats);
    affine_relu_kernel<<<NB * SS / 4, 256>>>(att, lnw_t, lnb_t, stats, y);

    // --- G6: out(c,s) = wout(c,lat)/64 . y(s,lat) + b_out -> fp32 ---
    mma_gemm<0><<<dim3(SS / 256, C_ST / 128, NB), 256, SMEM_TOTAL>>>(
        wout, y, out, nullptr,
        LAT, SS, 0, (ll)SS * LAT, (ll)C_ST * SS, IWS, b_out, 0);
}

// round 13
// speedup vs baseline: 3.4631x; 1.0128x over previous
#include <cuda_runtime.h>
#include <cuda_fp16.h>
#include <cstdint>
#include <math.h>

// ---------------------------------------------------------------------------
// Problem constants
// ---------------------------------------------------------------------------
#define NB    32
#define C_ST  2048
#define C_LT  2048
#define LAT   512
#define SS    512
#define LL    2048
#define LN_EPS 1e-5f

typedef long long ll;
typedef __half fp16;

// ---------------------------------------------------------------------------
// Scratch pool (single __device__ global; offsets in bytes, 256-aligned)
// ---------------------------------------------------------------------------
static constexpr ll SZ_STT   = (ll)NB * SS  * C_ST * 2;
static constexpr ll SZ_LTT   = (ll)NB * LL  * C_LT * 2;
static constexpr ll SZ_THETA = (ll)NB * SS  * LAT  * 2;
static constexpr ll SZ_PHI   = (ll)NB * LL  * LAT  * 2;
static constexpr ll SZ_G     = (ll)NB * LAT * LL   * 2;
static constexpr ll SZ_SCORE = (ll)NB * SS  * LL   * 4;   // fp32
static constexpr ll SZ_P     = (ll)NB * SS  * LL   * 2;
static constexpr ll SZ_ATT   = (ll)NB * SS  * LAT  * 2;   // fp16 now
static constexpr ll SZ_Y     = (ll)NB * SS  * LAT  * 2;
static constexpr ll SZ_W     = (ll)LAT * C_ST * 2;
static constexpr ll SZ_LN    = (ll)LAT * SS * 4;

static constexpr ll O_STT    = 0;
static constexpr ll O_LTT    = O_STT   + SZ_STT;
static constexpr ll O_THETA  = O_LTT   + SZ_LTT;
static constexpr ll O_PHI    = O_THETA + SZ_THETA;
static constexpr ll O_G      = O_PHI   + SZ_PHI;
static constexpr ll O_SCORE  = O_G     + SZ_G;
static constexpr ll O_P      = O_SCORE + SZ_SCORE;
static constexpr ll O_ATT    = O_P     + SZ_P;
static constexpr ll O_Y      = O_ATT   + SZ_ATT;
static constexpr ll O_WST    = O_Y     + SZ_Y;
static constexpr ll O_WLT    = O_WST   + SZ_W;
static constexpr ll O_WG     = O_WLT   + SZ_W;
static constexpr ll O_WOUT   = O_WG    + SZ_W;
static constexpr ll O_LNW_T  = O_WOUT  + SZ_W;
static constexpr ll O_LNB_T  = O_LNW_T + SZ_LN;
static constexpr ll O_PSTAT  = O_LNB_T + SZ_LN;
static constexpr ll O_STATS  = O_PSTAT + 256 * 8;
static constexpr ll POOL_BYTES = O_STATS + 256;

__device__ __align__(256) unsigned char g_pool[POOL_BYTES];

// ---------------------------------------------------------------------------
// PTX helpers
// ---------------------------------------------------------------------------
__device__ __forceinline__ uint32_t smem_u32(const void* p) {
    uint32_t a;
    asm("{ .reg .u64 t; cvta.to.shared.u64 t, %1; cvt.u32.u64 %0, t; }"
        : "=r"(a) : "l"(p));
    return a;
}
__device__ __forceinline__ void cpa16(uint32_t s, const void* g) {
    asm volatile("cp.async.cg.shared.global [%0], [%1], 16;" :: "r"(s), "l"(g) : "memory");
}
#define CP_COMMIT asm volatile("cp.async.commit_group;" ::: "memory")
#define CP_WAIT2  asm volatile("cp.async.wait_group 2;" ::: "memory")
#define CP_WAIT1  asm volatile("cp.async.wait_group 1;" ::: "memory")
#define CP_WAIT0  asm volatile("cp.async.wait_group 0;" ::: "memory")

#define LDSM4(r, addr) \
    asm volatile("ldmatrix.sync.aligned.m8n8.x4.shared.b16 {%0,%1,%2,%3}, [%4];" \
        : "=r"((r)[0]), "=r"((r)[1]), "=r"((r)[2]), "=r"((r)[3]) : "r"(addr))

// fp16 MMA, k16, fp32 accumulate (full-rate HMMA class)
#define MMAH(d, a, b0, b1) \
    asm volatile("mma.sync.aligned.m16n8k16.row.col.f32.f16.f16.f32 " \
        "{%0,%1,%2,%3}, {%4,%5,%6,%7}, {%8,%9}, {%0,%1,%2,%3};" \
        : "+f"((d)[0]), "+f"((d)[1]), "+f"((d)[2]), "+f"((d)[3]) \
        : "r"((a)[0]), "r"((a)[1]), "r"((a)[2]), "r"((a)[3]), "r"(b0), "r"(b1))

__device__ __forceinline__ uint32_t pack_h(fp16 a, fp16 b) {
    return (uint32_t)__half_as_ushort(a) | ((uint32_t)__half_as_ushort(b) << 16);
}
__device__ __forceinline__ float2 h2f(uint32_t u) {
    __half2 h = *reinterpret_cast<__half2*>(&u);
    return __half22float2(h);
}

// ---------------------------------------------------------------------------
// Tensor-core GEMM (plain fp16):  C(m,n) = alpha*sum_k A(m,k)*B(n,k) + bias
//   A, B K-major fp16 (lda=ldb=K). CTA tile M=128, N=256, K-chunk 64.
//   Warp grid 2(m) x 4(n); warp tile 64x64. 3-stage cp.async ring.
//   OUT=0: fp32 Cf.  OUT=2: fp16 Ch.
// Stage: A[0,16K) B[16K,48K) -> 48K/stage, 144K total.
// ---------------------------------------------------------------------------
static constexpr uint32_t STAGE = 49152;
static constexpr int SMEM_TOTAL = 3 * (int)STAGE;

template <int OUT>
__global__ __launch_bounds__(256) void mma_gemm(
    const fp16* __restrict__ A, const fp16* __restrict__ B,
    float* __restrict__ Cf, fp16* __restrict__ Ch,
    int K, int ldc, ll sA, ll sB, ll sC,
    float alpha, const float* __restrict__ bias, int bias_per_n)
{
    extern __shared__ __align__(1024) char smem[];
    const uint32_t sb = smem_u32(smem);
    const int tid  = threadIdx.x;
    const int wid  = tid >> 5, lane = tid & 31;
    const ll  b    = blockIdx.z;
    const int m0   = blockIdx.y << 7;
    const int n0   = blockIdx.x << 8;

    const fp16* Ab = A + b * sA;
    const fp16* Bb = B + b * sB;

    const int C = K >> 6;

    auto load_chunk = [&](int ct, int stg) {
        const uint32_t base = sb + stg * STAGE;
        const int kt = ct << 6;
#pragma unroll
        for (int i = 0; i < 4; ++i) {           // A: 128 rows x 128B
            int idx = tid + (i << 8);
            int row = idx >> 3, seg = idx & 7;
            uint32_t so = (uint32_t)((row << 7) + (seg << 4));
            so ^= (so >> 3) & 0x70;
            cpa16(base + so, Ab + (ll)(m0 + row) * K + kt + (seg << 3));
        }
#pragma unroll
        for (int i = 0; i < 8; ++i) {           // B: 256 rows x 128B
            int idx = tid + (i << 8);
            int row = idx >> 3, seg = idx & 7;
            uint32_t so = (uint32_t)((row << 7) + (seg << 4));
            so ^= (so >> 3) & 0x70;
            cpa16(base + 16384 + so, Bb + (ll)(n0 + row) * K + kt + (seg << 3));
        }
    };

    load_chunk(0, 0); CP_COMMIT;
    if (C > 1) { load_chunk(1, 1); CP_COMMIT; }

    // warp tiling: 2 (m) x 4 (n); each warp 64(m) x 64(n)
    const int wm = wid >> 2, wn = wid & 3;
    float acc[4][8][4];
#pragma unroll
    for (int i = 0; i < 4; ++i)
#pragma unroll
        for (int j = 0; j < 8; ++j)
#pragma unroll
            for (int q = 0; q < 4; ++q) acc[i][j][q] = 0.f;

    const uint32_t a_row = (uint32_t)(wm * 64 + (lane & 15));
    const uint32_t a_sb  = (uint32_t)(lane >> 4);
    const uint32_t b_row = (uint32_t)(wn * 64 + ((lane >> 4) << 3) + (lane & 7));
    const uint32_t b_sb  = (uint32_t)((lane >> 3) & 1);

    for (int ct = 0; ct < C; ++ct) {
        // issue-ahead-2 into the stage freed two iterations ago
        if (ct + 2 < C) { load_chunk(ct + 2, (ct + 2) % 3); CP_COMMIT; CP_WAIT2; }
        else if (ct + 1 < C) { CP_WAIT1; }
        else { CP_WAIT0; }
        __syncthreads();
        const uint32_t sbase = sb + (ct % 3) * STAGE;

#pragma unroll
        for (int s = 0; s < 4; ++s) {           // 4 x k16 per chunk
            uint32_t ah[4][4];
#pragma unroll
            for (int mt = 0; mt < 4; ++mt) {
                uint32_t row = a_row + mt * 16;
                uint32_t seg = (uint32_t)(s * 2) + a_sb;
                uint32_t off = (row << 7) + (seg << 4);
                off ^= (off >> 3) & 0x70;
                LDSM4(ah[mt], sbase + off);
            }
            uint32_t bh[4][4];
#pragma unroll
            for (int ng = 0; ng < 4; ++ng) {
                uint32_t row = b_row + ng * 16;
                uint32_t seg = (uint32_t)(s * 2) + b_sb;
                uint32_t off = (row << 7) + (seg << 4);
                off ^= (off >> 3) & 0x70;
                LDSM4(bh[ng], sbase + 16384 + off);
            }
#pragma unroll
            for (int mt = 0; mt < 4; ++mt) {
#pragma unroll
                for (int ng = 0; ng < 4; ++ng) {
                    MMAH(acc[mt][2 * ng],     ah[mt], bh[ng][0], bh[ng][1]);
                    MMAH(acc[mt][2 * ng + 1], ah[mt], bh[ng][2], bh[ng][3]);
                }
            }
        }
        __syncthreads();
    }

    // ---- epilogue ----
    const int l4 = lane >> 2;
    const int l2 = (lane & 3) * 2;
#pragma unroll
    for (int mt = 0; mt < 4; ++mt) {
        const int m = m0 + wm * 64 + mt * 16 + l4;
        float bm0 = 0.f, bm8 = 0.f;
        if (bias && !bias_per_n) { bm0 = bias[m]; bm8 = bias[m + 8]; }
#pragma unroll
        for (int nt = 0; nt < 8; ++nt) {
            const int n = n0 + wn * 64 + nt * 8 + l2;
            float bn0 = 0.f, bn1 = 0.f;
            if (bias && bias_per_n) { bn0 = bias[n]; bn1 = bias[n + 1]; }
            const float* a4 = acc[mt][nt];
            float v00 = a4[0] * alpha, v01 = a4[1] * alpha;
            float v10 = a4[2] * alpha, v11 = a4[3] * alpha;
            if (bias) {
                if (bias_per_n) { v00 += bn0; v01 += bn1; v10 += bn0; v11 += bn1; }
                else            { v00 += bm0; v01 += bm0; v10 += bm8; v11 += bm8; }
            }
            ll o0 = b * sC + (ll)m * ldc + n;
            ll o1 = b * sC + (ll)(m + 8) * ldc + n;
            if (OUT == 0) {
                *reinterpret_cast<float2*>(Cf + o0) = make_float2(v00, v01);
                *reinterpret_cast<float2*>(Cf + o1) = make_float2(v10, v11);
            } else {
                *reinterpret_cast<uint32_t*>(Ch + o0) =
                    pack_h(__float2half_rn(v00), __float2half_rn(v01));
                *reinterpret_cast<uint32_t*>(Ch + o1) =
                    pack_h(__float2half_rn(v10), __float2half_rn(v11));
            }
        }
    }
}

// ---------------------------------------------------------------------------
// fp32 -> scaled fp16 round, 8 elems/thread, 16B stores.
// ---------------------------------------------------------------------------
__global__ __launch_bounds__(256) void round_kernel(
    const float* __restrict__ in, fp16* __restrict__ out, float scale)
{
    ll i = ((ll)blockIdx.x * 256 + threadIdx.x) * 8;
    float4 a = *reinterpret_cast<const float4*>(in + i);
    float4 c = *reinterpret_cast<const float4*>(in + i + 4);
    float v[8] = {a.x, a.y, a.z, a.w, c.x, c.y, c.z, c.w};
    uint32_t hp[4];
#pragma unroll
    for (int q = 0; q < 4; ++q)
        hp[q] = pack_h(__float2half_rn(v[2*q] * scale), __float2half_rn(v[2*q+1] * scale));
    *reinterpret_cast<uint4*>(out + i) = make_uint4(hp[0], hp[1], hp[2], hp[3]);
}

// ---------------------------------------------------------------------------
// Transpose + fp16 round: in (b, R, X) fp32 -> out (b, X, R) fp16
// ---------------------------------------------------------------------------
__global__ __launch_bounds__(256) void transpose_h_kernel(
    const float* __restrict__ in, fp16* __restrict__ hi, int R, int X)
{
    __shared__ float t[64][65];
    const ll b = blockIdx.z;
    const float* ib = in + b * (ll)R * X;
    const int x0 = blockIdx.x << 6, r0 = blockIdx.y << 6;
    const int tx = threadIdx.x & 15;
    const int ty = threadIdx.x >> 4;
#pragma unroll
    for (int i = 0; i < 4; ++i) {
        int r = ty + 16 * i;
        float4 v = *reinterpret_cast<const float4*>(
            ib + (ll)(r0 + r) * X + x0 + tx * 4);
        t[r][tx * 4 + 0] = v.x; t[r][tx * 4 + 1] = v.y;
        t[r][tx * 4 + 2] = v.z; t[r][tx * 4 + 3] = v.w;
    }
    __syncthreads();
    const ll ob = b * (ll)R * X;
#pragma unroll
    for (int i = 0; i < 4; ++i) {
        int xr = ty + 16 * i;
        fp16 h0 = __float2half_rn(t[tx * 4 + 0][xr]);
        fp16 h1 = __float2half_rn(t[tx * 4 + 1][xr]);
        fp16 h2 = __float2half_rn(t[tx * 4 + 2][xr]);
        fp16 h3 = __float2half_rn(t[tx * 4 + 3][xr]);
        ll o = ob + (ll)(x0 + xr) * R + r0 + tx * 4;
        *reinterpret_cast<uint2*>(hi + o) = make_uint2(pack_h(h0, h1), pack_h(h2, h3));
    }
}

// ---------------------------------------------------------------------------
// Plain fp32 transpose (ln params)
// ---------------------------------------------------------------------------
__global__ __launch_bounds__(256) void transpose_f32_kernel(
    const float* __restrict__ in, float* __restrict__ out, int R, int X)
{
    __shared__ float t[32][33];
    const int x0 = blockIdx.x << 5, r0 = blockIdx.y << 5;
    const int tx = threadIdx.x & 31, ty = threadIdx.x >> 5;
#pragma unroll
    for (int i = 0; i < 4; ++i)
        t[ty + 8 * i][tx] = in[(ll)(r0 + ty + 8 * i) * X + x0 + tx];
    __syncthreads();
#pragma unroll
    for (int i = 0; i < 4; ++i)
        out[(ll)(x0 + ty + 8 * i) * R + r0 + tx] = t[tx][ty + 8 * i];
}

// ---------------------------------------------------------------------------
// Softmax over L (=2048); p scaled x1024, fp16 out (16B stores).
// ---------------------------------------------------------------------------
__global__ __launch_bounds__(256) void softmax_kernel(
    const float* __restrict__ x, fp16* __restrict__ ph)
{
    const ll row = blockIdx.x;
    const int tid = threadIdx.x;
    const float* p = x + row * (ll)LL + tid * 8;

    float4 a = *reinterpret_cast<const float4*>(p);
    float4 c = *reinterpret_cast<const float4*>(p + 4);
    float v[8] = {a.x, a.y, a.z, a.w, c.x, c.y, c.z, c.w};

    float m = v[0];
#pragma unroll
    for (int i = 1; i < 8; ++i) m = fmaxf(m, v[i]);
#pragma unroll
    for (int o = 16; o > 0; o >>= 1) m = fmaxf(m, __shfl_xor_sync(0xffffffffu, m, o));
    __shared__ float sm[8];
    if ((tid & 31) == 0) sm[tid >> 5] = m;
    __syncthreads();
    float mx = sm[0];
#pragma unroll
    for (int i = 1; i < 8; ++i) mx = fmaxf(mx, sm[i]);

    float s = 0.f;
#pragma unroll
    for (int i = 0; i < 8; ++i) { v[i] = __expf(v[i] - mx); s += v[i]; }
#pragma unroll
    for (int o = 16; o > 0; o >>= 1) s += __shfl_xor_sync(0xffffffffu, s, o);
    __shared__ float ss[8];
    if ((tid & 31) == 0) ss[tid >> 5] = s;
    __syncthreads();
    float tot = 0.f;
#pragma unroll
    for (int i = 0; i < 8; ++i) tot += ss[i];
    float inv = 1024.f / tot;     // p scaled by 1024 (undone by alpha in G5)

    uint32_t hp[4];
#pragma unroll
    for (int q = 0; q < 4; ++q)
        hp[q] = pack_h(__float2half_rn(v[2*q] * inv), __float2half_rn(v[2*q+1] * inv));
    ll o = row * (ll)LL + tid * 8;
    *reinterpret_cast<uint4*>(ph + o) = make_uint4(hp[0], hp[1], hp[2], hp[3]);
}

// ---------------------------------------------------------------------------
// LayerNorm stats, two-phase, att fp16.
// Phase 1: 256 blocks (8/batch) x 256 thr, each thread 128 halves (16 uint4).
// ---------------------------------------------------------------------------
__global__ __launch_bounds__(256) void stats1_kernel(
    const fp16* __restrict__ att, float2* __restrict__ part)
{
    const int blk = blockIdx.x;
    const int n = blk >> 3, ch = blk & 7;
    const fp16* x = att + (ll)n * LAT * SS + (ll)ch * 32768;
    const int tid = threadIdx.x;
    float s = 0.f, s2 = 0.f;
#pragma unroll
    for (int i = 0; i < 16; ++i) {
        uint4 u = *reinterpret_cast<const uint4*>(x + (ll)(i * 256 + tid) * 8);
        float2 f0 = h2f(u.x), f1 = h2f(u.y), f2 = h2f(u.z), f3 = h2f(u.w);
        s  += f0.x + f0.y + f1.x + f1.y + f2.x + f2.y + f3.x + f3.y;
        s2 += f0.x*f0.x + f0.y*f0.y + f1.x*f1.x + f1.y*f1.y
            + f2.x*f2.x + f2.y*f2.y + f3.x*f3.x + f3.y*f3.y;
    }
#pragma unroll
    for (int o = 16; o > 0; o >>= 1) {
        s  += __shfl_xor_sync(0xffffffffu, s,  o);
        s2 += __shfl_xor_sync(0xffffffffu, s2, o);
    }
    __shared__ float rs[8], rs2[8];
    if ((tid & 31) == 0) { rs[tid >> 5] = s; rs2[tid >> 5] = s2; }
    __syncthreads();
    if (tid == 0) {
        float S = 0.f, S2 = 0.f;
#pragma unroll
        for (int i = 0; i < 8; ++i) { S += rs[i]; S2 += rs2[i]; }
        part[blk] = make_float2(S, S2);
    }
}

__global__ __launch_bounds__(32) void stats2_kernel(
    const float2* __restrict__ part, float2* __restrict__ stats)
{
    const int n = threadIdx.x;
    float S = 0.f, S2 = 0.f;
#pragma unroll
    for (int i = 0; i < 8; ++i) {
        float2 p = part[n * 8 + i];
        S += p.x; S2 += p.y;
    }
    const float invM = 1.f / (float)(LAT * SS);
    float mu = S * invM;
    float var = S2 * invM - mu * mu;
    stats[n] = make_float2(mu, rsqrtf(var + LN_EPS));
}

// ---------------------------------------------------------------------------
// LN affine + ReLU, att fp16 -> y fp16
// ---------------------------------------------------------------------------
__global__ __launch_bounds__(256) void affine_relu_kernel(
    const fp16* __restrict__ att, const float* __restrict__ wT,
    const float* __restrict__ bT, const float2* __restrict__ stats,
    fp16* __restrict__ yh)
{
    const int r = threadIdx.x >> 6;
    const int c = (threadIdx.x & 63) * 8;
    const ll row = (ll)blockIdx.x * 4 + r;
    const int b = (int)(row >> 9), s = (int)(row & 511);
    const float2 st = stats[b];
    const fp16* xx = att + row * (ll)LAT + c;
    const float* ww = wT + (ll)s * LAT + c;
    const float* bb = bT + (ll)s * LAT + c;

    uint4 xu = *reinterpret_cast<const uint4*>(xx);
    float2 xf0 = h2f(xu.x), xf1 = h2f(xu.y), xf2 = h2f(xu.z), xf3 = h2f(xu.w);
    float xv[8] = {xf0.x, xf0.y, xf1.x, xf1.y, xf2.x, xf2.y, xf3.x, xf3.y};
    float4 w0 = *reinterpret_cast<const float4*>(ww);
    float4 w1 = *reinterpret_cast<const float4*>(ww + 4);
    float4 b0 = *reinterpret_cast<const float4*>(bb);
    float4 b1 = *reinterpret_cast<const float4*>(bb + 4);
    float wv[8] = {w0.x, w0.y, w0.z, w0.w, w1.x, w1.y, w1.z, w1.w};
    float bv[8] = {b0.x, b0.y, b0.z, b0.w, b1.x, b1.y, b1.z, b1.w};

    uint32_t hp[4];
#pragma unroll
    for (int q = 0; q < 4; ++q) {
        float v0 = fmaxf((xv[2*q]   - st.x) * st.y * wv[2*q]   + bv[2*q],   0.f);
        float v1 = fmaxf((xv[2*q+1] - st.x) * st.y * wv[2*q+1] + bv[2*q+1], 0.f);
        hp[q] = pack_h(__float2half_rn(v0), __float2half_rn(v1));
    }
    ll o = row * (ll)LAT + c;
    *reinterpret_cast<uint4*>(yh + o) = make_uint4(hp[0], hp[1], hp[2], hp[3]);
}

// ---------------------------------------------------------------------------
// Launch
// ---------------------------------------------------------------------------
extern "C" void kernel_launch(void* const* d_in, const int* in_sizes, int n_in,
                              void* d_out, int out_size)
{
    const float* st_feat = (const float*)d_in[0];
    const float* lt_feat = (const float*)d_in[1];
    const float* w_st    = (const float*)d_in[2];
    const float* b_st    = (const float*)d_in[3];
    const float* w_lt    = (const float*)d_in[4];
    const float* b_lt    = (const float*)d_in[5];
    const float* w_g     = (const float*)d_in[6];
    const float* b_g     = (const float*)d_in[7];
    const float* ln_w    = (const float*)d_in[8];
    const float* ln_b    = (const float*)d_in[9];
    const float* w_out   = (const float*)d_in[10];
    const float* b_out   = (const float*)d_in[11];
    float* out = (float*)d_out;

    unsigned char* pool;
    cudaGetSymbolAddress((void**)&pool, g_pool);
    fp16* stT    = (fp16*)(pool + O_STT);
    fp16* ltT    = (fp16*)(pool + O_LTT);
    fp16* theta  = (fp16*)(pool + O_THETA);
    fp16* phi    = (fp16*)(pool + O_PHI);
    fp16* g      = (fp16*)(pool + O_G);
    float* scores= (float*)(pool + O_SCORE);
    fp16* p      = (fp16*)(pool + O_P);
    fp16* att    = (fp16*)(pool + O_ATT);
    fp16* y      = (fp16*)(pool + O_Y);
    fp16* wst    = (fp16*)(pool + O_WST);
    fp16* wlt    = (fp16*)(pool + O_WLT);
    fp16* wg     = (fp16*)(pool + O_WG);
    fp16* wout   = (fp16*)(pool + O_WOUT);
    float* lnw_t = (float*)(pool + O_LNW_T);
    float* lnb_t = (float*)(pool + O_LNB_T);
    float2* pstat= (float2*)(pool + O_PSTAT);
    float2* stats= (float2*)(pool + O_STATS);

    cudaFuncSetAttribute(mma_gemm<0>, cudaFuncAttributeMaxDynamicSharedMemorySize, SMEM_TOTAL);
    cudaFuncSetAttribute(mma_gemm<2>, cudaFuncAttributeMaxDynamicSharedMemorySize, SMEM_TOTAL);

    const float inv_sqrt_lat = 0.044194173824159216f;   // 1/sqrt(512)
    const float WS = 64.f, IWS = 1.f / 64.f;            // weight pre-scale
    const float IPS = 1.f / 1024.f;                     // p pre-scale undo

    // --- operand conversion ---
    round_kernel<<<512, 256>>>(w_st,  wst,  WS);
    round_kernel<<<512, 256>>>(w_lt,  wlt,  WS);
    round_kernel<<<512, 256>>>(w_g,   wg,   WS);
    round_kernel<<<512, 256>>>(w_out, wout, WS);
    transpose_h_kernel<<<dim3(SS / 64, C_ST / 64, NB), 256>>>(st_feat, stT, C_ST, SS);
    transpose_h_kernel<<<dim3(LL / 64, C_LT / 64, NB), 256>>>(lt_feat, ltT, C_LT, LL);
    transpose_f32_kernel<<<dim3(SS / 32, LAT / 32), 256>>>(ln_w, lnw_t, LAT, SS);
    transpose_f32_kernel<<<dim3(SS / 32, LAT / 32), 256>>>(ln_b, lnb_t, LAT, SS);

    // --- G1: theta(s,lat) = stT(s,c) . wst(lat,c)/64 + b_st -> fp16 ---
    mma_gemm<2><<<dim3(LAT / 256, SS / 128, NB), 256, SMEM_TOTAL>>>(
        stT, wst, nullptr, theta,
        C_ST, LAT, (ll)SS * C_ST, 0, (ll)SS * LAT, IWS, b_st, 1);

    // --- G2: phi(l,lat) = ltT(l,c) . wlt(lat,c)/64 + b_lt -> fp16 ---
    mma_gemm<2><<<dim3(LAT / 256, LL / 128, NB), 256, SMEM_TOTAL>>>(
        ltT, wlt, nullptr, phi,
        C_LT, LAT, (ll)LL * C_LT, 0, (ll)LL * LAT, IWS, b_lt, 1);

    // --- G3: g(lat,l) = wg(lat,c)/64 . ltT(l,c) + b_g -> fp16 ---
    mma_gemm<2><<<dim3(LL / 256, LAT / 128, NB), 256, SMEM_TOTAL>>>(
        wg, ltT, nullptr, g,
        C_LT, LL, 0, (ll)LL * C_LT, (ll)LAT * LL, IWS, b_g, 0);

    // --- G4: scores(s,l) = theta(s,.) . phi(l,.) / sqrt(LAT) -> fp32 ---
    mma_gemm<0><<<dim3(LL / 256, SS / 128, NB), 256, SMEM_TOTAL>>>(
        theta, phi, scores, nullptr,
        LAT, LL, (ll)SS * LAT, (ll)LL * LAT, (ll)SS * LL, inv_sqrt_lat, nullptr, 0);

    // --- softmax over L (+x1024 scale) -> fp16 ---
    softmax_kernel<<<NB * SS, 256>>>(scores, p);

    // --- G5: att(s,lat) = p(s,l)/1024 . g(lat,l) -> fp16 ---
    mma_gemm<2><<<dim3(LAT / 256, SS / 128, NB), 256, SMEM_TOTAL>>>(
        p, g, nullptr, att,
        LL, LAT, (ll)SS * LL, (ll)LAT * LL, (ll)SS * LAT, IPS, nullptr, 0);

    // --- LayerNorm stats (two-phase) + affine + relu -> fp16 ---
    stats1_kernel<<<256, 256>>>(att, pstat);
    stats2_kernel<<<1, 32>>>(pstat, stats);
    affine_relu_kernel<<<NB * SS / 4, 256>>>(att, lnw_t, lnb_t, stats, y);

    // --- G6: out(c,s) = wout(c,lat)/64 . y(s,lat) + b_out -> fp32 ---
    mma_gemm<0><<<dim3(SS / 256, C_ST / 128, NB), 256, SMEM_TOTAL>>>(
        wout, y, out, nullptr,
        LAT, SS, 0, (ll)SS * LAT, (ll)C_ST * SS, IWS, b_out, 0);
}

// round 14
// speedup vs baseline: 3.4889x; 1.0074x over previous
#include <cuda_runtime.h>
#include <cuda_fp16.h>
#include <cstdint>
#include <math.h>

// ---------------------------------------------------------------------------
// Problem constants
// ---------------------------------------------------------------------------
#define NB    32
#define C_ST  2048
#define C_LT  2048
#define LAT   512
#define SS    512
#define LL    2048
#define LN_EPS 1e-5f

typedef long long ll;
typedef __half fp16;

// ---------------------------------------------------------------------------
// Scratch pool (single __device__ global; offsets in bytes, 256-aligned)
// ---------------------------------------------------------------------------
static constexpr ll SZ_STT   = (ll)NB * SS  * C_ST * 2;
static constexpr ll SZ_LTT   = (ll)NB * LL  * C_LT * 2;
static constexpr ll SZ_THETA = (ll)NB * SS  * LAT  * 2;
static constexpr ll SZ_PHI   = (ll)NB * LL  * LAT  * 2;
static constexpr ll SZ_G     = (ll)NB * LAT * LL   * 2;
static constexpr ll SZ_SCORE = (ll)NB * SS  * LL   * 2;   // fp16 now
static constexpr ll SZ_P     = (ll)NB * SS  * LL   * 2;
static constexpr ll SZ_ATT   = (ll)NB * SS  * LAT  * 2;   // fp16
static constexpr ll SZ_Y     = (ll)NB * SS  * LAT  * 2;
static constexpr ll SZ_W     = (ll)LAT * C_ST * 2;
static constexpr ll SZ_LN    = (ll)LAT * SS * 4;

static constexpr ll O_STT    = 0;
static constexpr ll O_LTT    = O_STT   + SZ_STT;
static constexpr ll O_THETA  = O_LTT   + SZ_LTT;
static constexpr ll O_PHI    = O_THETA + SZ_THETA;
static constexpr ll O_G      = O_PHI   + SZ_PHI;
static constexpr ll O_SCORE  = O_G     + SZ_G;
static constexpr ll O_P      = O_SCORE + SZ_SCORE;
static constexpr ll O_ATT    = O_P     + SZ_P;
static constexpr ll O_Y      = O_ATT   + SZ_ATT;
static constexpr ll O_WST    = O_Y     + SZ_Y;
static constexpr ll O_WLT    = O_WST   + SZ_W;
static constexpr ll O_WG     = O_WLT   + SZ_W;
static constexpr ll O_WOUT   = O_WG    + SZ_W;
static constexpr ll O_LNW_T  = O_WOUT  + SZ_W;
static constexpr ll O_LNB_T  = O_LNW_T + SZ_LN;
static constexpr ll O_PSTAT  = O_LNB_T + SZ_LN;
static constexpr ll O_STATS  = O_PSTAT + 256 * 8;
static constexpr ll POOL_BYTES = O_STATS + 256;

__device__ __align__(256) unsigned char g_pool[POOL_BYTES];

// ---------------------------------------------------------------------------
// PTX helpers
// ---------------------------------------------------------------------------
__device__ __forceinline__ uint32_t smem_u32(const void* p) {
    uint32_t a;
    asm("{ .reg .u64 t; cvta.to.shared.u64 t, %1; cvt.u32.u64 %0, t; }"
        : "=r"(a) : "l"(p));
    return a;
}
__device__ __forceinline__ void cpa16(uint32_t s, const void* g) {
    asm volatile("cp.async.cg.shared.global [%0], [%1], 16;" :: "r"(s), "l"(g) : "memory");
}
#define CP_COMMIT asm volatile("cp.async.commit_group;" ::: "memory")
#define CP_WAIT2  asm volatile("cp.async.wait_group 2;" ::: "memory")
#define CP_WAIT1  asm volatile("cp.async.wait_group 1;" ::: "memory")
#define CP_WAIT0  asm volatile("cp.async.wait_group 0;" ::: "memory")

#define LDSM4(r, addr) \
    asm volatile("ldmatrix.sync.aligned.m8n8.x4.shared.b16 {%0,%1,%2,%3}, [%4];" \
        : "=r"((r)[0]), "=r"((r)[1]), "=r"((r)[2]), "=r"((r)[3]) : "r"(addr))

// fp16 MMA, k16, fp32 accumulate (full-rate HMMA class)
#define MMAH(d, a, b0, b1) \
    asm volatile("mma.sync.aligned.m16n8k16.row.col.f32.f16.f16.f32 " \
        "{%0,%1,%2,%3}, {%4,%5,%6,%7}, {%8,%9}, {%0,%1,%2,%3};" \
        : "+f"((d)[0]), "+f"((d)[1]), "+f"((d)[2]), "+f"((d)[3]) \
        : "r"((a)[0]), "r"((a)[1]), "r"((a)[2]), "r"((a)[3]), "r"(b0), "r"(b1))

__device__ __forceinline__ uint32_t pack_h(fp16 a, fp16 b) {
    return (uint32_t)__half_as_ushort(a) | ((uint32_t)__half_as_ushort(b) << 16);
}
__device__ __forceinline__ float2 h2f(uint32_t u) {
    __half2 h = *reinterpret_cast<__half2*>(&u);
    return __half22float2(h);
}

// ---------------------------------------------------------------------------
// Tensor-core GEMM (plain fp16):  C(m,n) = alpha*sum_k A(m,k)*B(n,k) + bias
//   A, B K-major fp16 (lda=ldb=K). CTA tile M=128, N=256, K-chunk 64.
//   Warp grid 2(m) x 4(n); warp tile 64x64. 3-stage cp.async ring.
//   OUT=0: fp32 Cf.  OUT=2: fp16 Ch.
// Stage: A[0,16K) B[16K,48K) -> 48K/stage, 144K total.
// ---------------------------------------------------------------------------
static constexpr uint32_t STAGE = 49152;
static constexpr int SMEM_TOTAL = 3 * (int)STAGE;

template <int OUT>
__global__ __launch_bounds__(256) void mma_gemm(
    const fp16* __restrict__ A, const fp16* __restrict__ B,
    float* __restrict__ Cf, fp16* __restrict__ Ch,
    int K, int ldc, ll sA, ll sB, ll sC,
    float alpha, const float* __restrict__ bias, int bias_per_n)
{
    extern __shared__ __align__(1024) char smem[];
    const uint32_t sb = smem_u32(smem);
    const int tid  = threadIdx.x;
    const int wid  = tid >> 5, lane = tid & 31;
    const ll  b    = blockIdx.z;
    const int m0   = blockIdx.y << 7;
    const int n0   = blockIdx.x << 8;

    const fp16* Ab = A + b * sA;
    const fp16* Bb = B + b * sB;

    const int C = K >> 6;

    auto load_chunk = [&](int ct, int stg) {
        const uint32_t base = sb + stg * STAGE;
        const int kt = ct << 6;
#pragma unroll
        for (int i = 0; i < 4; ++i) {           // A: 128 rows x 128B
            int idx = tid + (i << 8);
            int row = idx >> 3, seg = idx & 7;
            uint32_t so = (uint32_t)((row << 7) + (seg << 4));
            so ^= (so >> 3) & 0x70;
            cpa16(base + so, Ab + (ll)(m0 + row) * K + kt + (seg << 3));
        }
#pragma unroll
        for (int i = 0; i < 8; ++i) {           // B: 256 rows x 128B
            int idx = tid + (i << 8);
            int row = idx >> 3, seg = idx & 7;
            uint32_t so = (uint32_t)((row << 7) + (seg << 4));
            so ^= (so >> 3) & 0x70;
            cpa16(base + 16384 + so, Bb + (ll)(n0 + row) * K + kt + (seg << 3));
        }
    };

    load_chunk(0, 0); CP_COMMIT;
    if (C > 1) { load_chunk(1, 1); CP_COMMIT; }

    // warp tiling: 2 (m) x 4 (n); each warp 64(m) x 64(n)
    const int wm = wid >> 2, wn = wid & 3;
    float acc[4][8][4];
#pragma unroll
    for (int i = 0; i < 4; ++i)
#pragma unroll
        for (int j = 0; j < 8; ++j)
#pragma unroll
            for (int q = 0; q < 4; ++q) acc[i][j][q] = 0.f;

    const uint32_t a_row = (uint32_t)(wm * 64 + (lane & 15));
    const uint32_t a_sb  = (uint32_t)(lane >> 4);
    const uint32_t b_row = (uint32_t)(wn * 64 + ((lane >> 4) << 3) + (lane & 7));
    const uint32_t b_sb  = (uint32_t)((lane >> 3) & 1);

    for (int ct = 0; ct < C; ++ct) {
        // issue-ahead-2 into the stage freed two iterations ago
        if (ct + 2 < C) { load_chunk(ct + 2, (ct + 2) % 3); CP_COMMIT; CP_WAIT2; }
        else if (ct + 1 < C) { CP_WAIT1; }
        else { CP_WAIT0; }
        __syncthreads();
        const uint32_t sbase = sb + (ct % 3) * STAGE;

#pragma unroll
        for (int s = 0; s < 4; ++s) {           // 4 x k16 per chunk
            uint32_t ah[4][4];
#pragma unroll
            for (int mt = 0; mt < 4; ++mt) {
                uint32_t row = a_row + mt * 16;
                uint32_t seg = (uint32_t)(s * 2) + a_sb;
                uint32_t off = (row << 7) + (seg << 4);
                off ^= (off >> 3) & 0x70;
                LDSM4(ah[mt], sbase + off);
            }
            uint32_t bh[4][4];
#pragma unroll
            for (int ng = 0; ng < 4; ++ng) {
                uint32_t row = b_row + ng * 16;
                uint32_t seg = (uint32_t)(s * 2) + b_sb;
                uint32_t off = (row << 7) + (seg << 4);
                off ^= (off >> 3) & 0x70;
                LDSM4(bh[ng], sbase + 16384 + off);
            }
#pragma unroll
            for (int mt = 0; mt < 4; ++mt) {
#pragma unroll
                for (int ng = 0; ng < 4; ++ng) {
                    MMAH(acc[mt][2 * ng],     ah[mt], bh[ng][0], bh[ng][1]);
                    MMAH(acc[mt][2 * ng + 1], ah[mt], bh[ng][2], bh[ng][3]);
                }
            }
        }
        __syncthreads();
    }

    // ---- epilogue ----
    const int l4 = lane >> 2;
    const int l2 = (lane & 3) * 2;
#pragma unroll
    for (int mt = 0; mt < 4; ++mt) {
        const int m = m0 + wm * 64 + mt * 16 + l4;
        float bm0 = 0.f, bm8 = 0.f;
        if (bias && !bias_per_n) { bm0 = bias[m]; bm8 = bias[m + 8]; }
#pragma unroll
        for (int nt = 0; nt < 8; ++nt) {
            const int n = n0 + wn * 64 + nt * 8 + l2;
            float bn0 = 0.f, bn1 = 0.f;
            if (bias && bias_per_n) { bn0 = bias[n]; bn1 = bias[n + 1]; }
            const float* a4 = acc[mt][nt];
            float v00 = a4[0] * alpha, v01 = a4[1] * alpha;
            float v10 = a4[2] * alpha, v11 = a4[3] * alpha;
            if (bias) {
                if (bias_per_n) { v00 += bn0; v01 += bn1; v10 += bn0; v11 += bn1; }
                else            { v00 += bm0; v01 += bm0; v10 += bm8; v11 += bm8; }
            }
            ll o0 = b * sC + (ll)m * ldc + n;
            ll o1 = b * sC + (ll)(m + 8) * ldc + n;
            if (OUT == 0) {
                *reinterpret_cast<float2*>(Cf + o0) = make_float2(v00, v01);
                *reinterpret_cast<float2*>(Cf + o1) = make_float2(v10, v11);
            } else {
                *reinterpret_cast<uint32_t*>(Ch + o0) =
                    pack_h(__float2half_rn(v00), __float2half_rn(v01));
                *reinterpret_cast<uint32_t*>(Ch + o1) =
                    pack_h(__float2half_rn(v10), __float2half_rn(v11));
            }
        }
    }
}

// ---------------------------------------------------------------------------
// fp32 -> scaled fp16 round, 8 elems/thread, 16B stores.
// ---------------------------------------------------------------------------
__global__ __launch_bounds__(256) void round_kernel(
    const float* __restrict__ in, fp16* __restrict__ out, float scale)
{
    ll i = ((ll)blockIdx.x * 256 + threadIdx.x) * 8;
    float4 a = *reinterpret_cast<const float4*>(in + i);
    float4 c = *reinterpret_cast<const float4*>(in + i + 4);
    float v[8] = {a.x, a.y, a.z, a.w, c.x, c.y, c.z, c.w};
    uint32_t hp[4];
#pragma unroll
    for (int q = 0; q < 4; ++q)
        hp[q] = pack_h(__float2half_rn(v[2*q] * scale), __float2half_rn(v[2*q+1] * scale));
    *reinterpret_cast<uint4*>(out + i) = make_uint4(hp[0], hp[1], hp[2], hp[3]);
}

// ---------------------------------------------------------------------------
// Transpose + fp16 round: in (b, R, X) fp32 -> out (b, X, R) fp16
// ---------------------------------------------------------------------------
__global__ __launch_bounds__(256) void transpose_h_kernel(
    const float* __restrict__ in, fp16* __restrict__ hi, int R, int X)
{
    __shared__ float t[64][65];
    const ll b = blockIdx.z;
    const float* ib = in + b * (ll)R * X;
    const int x0 = blockIdx.x << 6, r0 = blockIdx.y << 6;
    const int tx = threadIdx.x & 15;
    const int ty = threadIdx.x >> 4;
#pragma unroll
    for (int i = 0; i < 4; ++i) {
        int r = ty + 16 * i;
        float4 v = *reinterpret_cast<const float4*>(
            ib + (ll)(r0 + r) * X + x0 + tx * 4);
        t[r][tx * 4 + 0] = v.x; t[r][tx * 4 + 1] = v.y;
        t[r][tx * 4 + 2] = v.z; t[r][tx * 4 + 3] = v.w;
    }
    __syncthreads();
    const ll ob = b * (ll)R * X;
#pragma unroll
    for (int i = 0; i < 4; ++i) {
        int xr = ty + 16 * i;
        fp16 h0 = __float2half_rn(t[tx * 4 + 0][xr]);
        fp16 h1 = __float2half_rn(t[tx * 4 + 1][xr]);
        fp16 h2 = __float2half_rn(t[tx * 4 + 2][xr]);
        fp16 h3 = __float2half_rn(t[tx * 4 + 3][xr]);
        ll o = ob + (ll)(x0 + xr) * R + r0 + tx * 4;
        *reinterpret_cast<uint2*>(hi + o) = make_uint2(pack_h(h0, h1), pack_h(h2, h3));
    }
}

// ---------------------------------------------------------------------------
// Plain fp32 transpose (ln params)
// ---------------------------------------------------------------------------
__global__ __launch_bounds__(256) void transpose_f32_kernel(
    const float* __restrict__ in, float* __restrict__ out, int R, int X)
{
    __shared__ float t[32][33];
    const int x0 = blockIdx.x << 5, r0 = blockIdx.y << 5;
    const int tx = threadIdx.x & 31, ty = threadIdx.x >> 5;
#pragma unroll
    for (int i = 0; i < 4; ++i)
        t[ty + 8 * i][tx] = in[(ll)(r0 + ty + 8 * i) * X + x0 + tx];
    __syncthreads();
#pragma unroll
    for (int i = 0; i < 4; ++i)
        out[(ll)(x0 + ty + 8 * i) * R + r0 + tx] = t[tx][ty + 8 * i];
}

// ---------------------------------------------------------------------------
// Softmax over L (=2048), fp16 logits in; p scaled x1024, fp16 out.
// One 256-thread block per row; each thread owns 8 consecutive elements.
// ---------------------------------------------------------------------------
__global__ __launch_bounds__(256) void softmax_kernel(
    const fp16* __restrict__ x, fp16* __restrict__ ph)
{
    const ll row = blockIdx.x;
    const int tid = threadIdx.x;
    const fp16* p = x + row * (ll)LL + tid * 8;

    uint4 u = *reinterpret_cast<const uint4*>(p);
    float2 f0 = h2f(u.x), f1 = h2f(u.y), f2 = h2f(u.z), f3 = h2f(u.w);
    float v[8] = {f0.x, f0.y, f1.x, f1.y, f2.x, f2.y, f3.x, f3.y};

    float m = v[0];
#pragma unroll
    for (int i = 1; i < 8; ++i) m = fmaxf(m, v[i]);
#pragma unroll
    for (int o = 16; o > 0; o >>= 1) m = fmaxf(m, __shfl_xor_sync(0xffffffffu, m, o));
    __shared__ float sm[8];
    if ((tid & 31) == 0) sm[tid >> 5] = m;
    __syncthreads();
    float mx = sm[0];
#pragma unroll
    for (int i = 1; i < 8; ++i) mx = fmaxf(mx, sm[i]);

    float s = 0.f;
#pragma unroll
    for (int i = 0; i < 8; ++i) { v[i] = __expf(v[i] - mx); s += v[i]; }
#pragma unroll
    for (int o = 16; o > 0; o >>= 1) s += __shfl_xor_sync(0xffffffffu, s, o);
    __shared__ float ss[8];
    if ((tid & 31) == 0) ss[tid >> 5] = s;
    __syncthreads();
    float tot = 0.f;
#pragma unroll
    for (int i = 0; i < 8; ++i) tot += ss[i];
    float inv = 1024.f / tot;     // p scaled by 1024 (undone by alpha in G5)

    uint32_t hp[4];
#pragma unroll
    for (int q = 0; q < 4; ++q)
        hp[q] = pack_h(__float2half_rn(v[2*q] * inv), __float2half_rn(v[2*q+1] * inv));
    ll o = row * (ll)LL + tid * 8;
    *reinterpret_cast<uint4*>(ph + o) = make_uint4(hp[0], hp[1], hp[2], hp[3]);
}

// ---------------------------------------------------------------------------
// LayerNorm stats, two-phase, att fp16.
// ---------------------------------------------------------------------------
__global__ __launch_bounds__(256) void stats1_kernel(
    const fp16* __restrict__ att, float2* __restrict__ part)
{
    const int blk = blockIdx.x;
    const int n = blk >> 3, ch = blk & 7;
    const fp16* x = att + (ll)n * LAT * SS + (ll)ch * 32768;
    const int tid = threadIdx.x;
    float s = 0.f, s2 = 0.f;
#pragma unroll
    for (int i = 0; i < 16; ++i) {
        uint4 u = *reinterpret_cast<const uint4*>(x + (ll)(i * 256 + tid) * 8);
        float2 f0 = h2f(u.x), f1 = h2f(u.y), f2 = h2f(u.z), f3 = h2f(u.w);
        s  += f0.x + f0.y + f1.x + f1.y + f2.x + f2.y + f3.x + f3.y;
        s2 += f0.x*f0.x + f0.y*f0.y + f1.x*f1.x + f1.y*f1.y
            + f2.x*f2.x + f2.y*f2.y + f3.x*f3.x + f3.y*f3.y;
    }
#pragma unroll
    for (int o = 16; o > 0; o >>= 1) {
        s  += __shfl_xor_sync(0xffffffffu, s,  o);
        s2 += __shfl_xor_sync(0xffffffffu, s2, o);
    }
    __shared__ float rs[8], rs2[8];
    if ((tid & 31) == 0) { rs[tid >> 5] = s; rs2[tid >> 5] = s2; }
    __syncthreads();
    if (tid == 0) {
        float S = 0.f, S2 = 0.f;
#pragma unroll
        for (int i = 0; i < 8; ++i) { S += rs[i]; S2 += rs2[i]; }
        part[blk] = make_float2(S, S2);
    }
}

__global__ __launch_bounds__(32) void stats2_kernel(
    const float2* __restrict__ part, float2* __restrict__ stats)
{
    const int n = threadIdx.x;
    float S = 0.f, S2 = 0.f;
#pragma unroll
    for (int i = 0; i < 8; ++i) {
        float2 p = part[n * 8 + i];
        S += p.x; S2 += p.y;
    }
    const float invM = 1.f / (float)(LAT * SS);
    float mu = S * invM;
    float var = S2 * invM - mu * mu;
    stats[n] = make_float2(mu, rsqrtf(var + LN_EPS));
}

// ---------------------------------------------------------------------------
// LN affine + ReLU, att fp16 -> y fp16
// ---------------------------------------------------------------------------
__global__ __launch_bounds__(256) void affine_relu_kernel(
    const fp16* __restrict__ att, const float* __restrict__ wT,
    const float* __restrict__ bT, const float2* __restrict__ stats,
    fp16* __restrict__ yh)
{
    const int r = threadIdx.x >> 6;
    const int c = (threadIdx.x & 63) * 8;
    const ll row = (ll)blockIdx.x * 4 + r;
    const int b = (int)(row >> 9), s = (int)(row & 511);
    const float2 st = stats[b];
    const fp16* xx = att + row * (ll)LAT + c;
    const float* ww = wT + (ll)s * LAT + c;
    const float* bb = bT + (ll)s * LAT + c;

    uint4 xu = *reinterpret_cast<const uint4*>(xx);
    float2 xf0 = h2f(xu.x), xf1 = h2f(xu.y), xf2 = h2f(xu.z), xf3 = h2f(xu.w);
    float xv[8] = {xf0.x, xf0.y, xf1.x, xf1.y, xf2.x, xf2.y, xf3.x, xf3.y};
    float4 w0 = *reinterpret_cast<const float4*>(ww);
    float4 w1 = *reinterpret_cast<const float4*>(ww + 4);
    float4 b0 = *reinterpret_cast<const float4*>(bb);
    float4 b1 = *reinterpret_cast<const float4*>(bb + 4);
    float wv[8] = {w0.x, w0.y, w0.z, w0.w, w1.x, w1.y, w1.z, w1.w};
    float bv[8] = {b0.x, b0.y, b0.z, b0.w, b1.x, b1.y, b1.z, b1.w};

    uint32_t hp[4];
#pragma unroll
    for (int q = 0; q < 4; ++q) {
        float v0 = fmaxf((xv[2*q]   - st.x) * st.y * wv[2*q]   + bv[2*q],   0.f);
        float v1 = fmaxf((xv[2*q+1] - st.x) * st.y * wv[2*q+1] + bv[2*q+1], 0.f);
        hp[q] = pack_h(__float2half_rn(v0), __float2half_rn(v1));
    }
    ll o = row * (ll)LAT + c;
    *reinterpret_cast<uint4*>(yh + o) = make_uint4(hp[0], hp[1], hp[2], hp[3]);
}

// ---------------------------------------------------------------------------
// Launch
// ---------------------------------------------------------------------------
extern "C" void kernel_launch(void* const* d_in, const int* in_sizes, int n_in,
                              void* d_out, int out_size)
{
    const float* st_feat = (const float*)d_in[0];
    const float* lt_feat = (const float*)d_in[1];
    const float* w_st    = (const float*)d_in[2];
    const float* b_st    = (const float*)d_in[3];
    const float* w_lt    = (const float*)d_in[4];
    const float* b_lt    = (const float*)d_in[5];
    const float* w_g     = (const float*)d_in[6];
    const float* b_g     = (const float*)d_in[7];
    const float* ln_w    = (const float*)d_in[8];
    const float* ln_b    = (const float*)d_in[9];
    const float* w_out   = (const float*)d_in[10];
    const float* b_out   = (const float*)d_in[11];
    float* out = (float*)d_out;

    unsigned char* pool;
    cudaGetSymbolAddress((void**)&pool, g_pool);
    fp16* stT    = (fp16*)(pool + O_STT);
    fp16* ltT    = (fp16*)(pool + O_LTT);
    fp16* theta  = (fp16*)(pool + O_THETA);
    fp16* phi    = (fp16*)(pool + O_PHI);
    fp16* g      = (fp16*)(pool + O_G);
    fp16* scores = (fp16*)(pool + O_SCORE);
    fp16* p      = (fp16*)(pool + O_P);
    fp16* att    = (fp16*)(pool + O_ATT);
    fp16* y      = (fp16*)(pool + O_Y);
    fp16* wst    = (fp16*)(pool + O_WST);
    fp16* wlt    = (fp16*)(pool + O_WLT);
    fp16* wg     = (fp16*)(pool + O_WG);
    fp16* wout   = (fp16*)(pool + O_WOUT);
    float* lnw_t = (float*)(pool + O_LNW_T);
    float* lnb_t = (float*)(pool + O_LNB_T);
    float2* pstat= (float2*)(pool + O_PSTAT);
    float2* stats= (float2*)(pool + O_STATS);

    cudaFuncSetAttribute(mma_gemm<0>, cudaFuncAttributeMaxDynamicSharedMemorySize, SMEM_TOTAL);
    cudaFuncSetAttribute(mma_gemm<2>, cudaFuncAttributeMaxDynamicSharedMemorySize, SMEM_TOTAL);

    const float inv_sqrt_lat = 0.044194173824159216f;   // 1/sqrt(512)
    const float WS = 64.f, IWS = 1.f / 64.f;            // weight pre-scale
    const float IPS = 1.f / 1024.f;                     // p pre-scale undo

    // --- operand conversion ---
    round_kernel<<<512, 256>>>(w_st,  wst,  WS);
    round_kernel<<<512, 256>>>(w_lt,  wlt,  WS);
    round_kernel<<<512, 256>>>(w_g,   wg,   WS);
    round_kernel<<<512, 256>>>(w_out, wout, WS);
    transpose_h_kernel<<<dim3(SS / 64, C_ST / 64, NB), 256>>>(st_feat, stT, C_ST, SS);
    transpose_h_kernel<<<dim3(LL / 64, C_LT / 64, NB), 256>>>(lt_feat, ltT, C_LT, LL);
    transpose_f32_kernel<<<dim3(SS / 32, LAT / 32), 256>>>(ln_w, lnw_t, LAT, SS);
    transpose_f32_kernel<<<dim3(SS / 32, LAT / 32), 256>>>(ln_b, lnb_t, LAT, SS);

    // --- G1: theta(s,lat) = stT(s,c) . wst(lat,c)/64 + b_st -> fp16 ---
    mma_gemm<2><<<dim3(LAT / 256, SS / 128, NB), 256, SMEM_TOTAL>>>(
        stT, wst, nullptr, theta,
        C_ST, LAT, (ll)SS * C_ST, 0, (ll)SS * LAT, IWS, b_st, 1);

    // --- G2: phi(l,lat) = ltT(l,c) . wlt(lat,c)/64 + b_lt -> fp16 ---
    mma_gemm<2><<<dim3(LAT / 256, LL / 128, NB), 256, SMEM_TOTAL>>>(
        ltT, wlt, nullptr, phi,
        C_LT, LAT, (ll)LL * C_LT, 0, (ll)LL * LAT, IWS, b_lt, 1);

    // --- G3: g(lat,l) = wg(lat,c)/64 . ltT(l,c) + b_g -> fp16 ---
    mma_gemm<2><<<dim3(LL / 256, LAT / 128, NB), 256, SMEM_TOTAL>>>(
        wg, ltT, nullptr, g,
        C_LT, LL, 0, (ll)LL * C_LT, (ll)LAT * LL, IWS, b_g, 0);

    // --- G4: scores(s,l) = theta(s,.) . phi(l,.) / sqrt(LAT) -> fp16 ---
    mma_gemm<2><<<dim3(LL / 256, SS / 128, NB), 256, SMEM_TOTAL>>>(
        theta, phi, nullptr, scores,
        LAT, LL, (ll)SS * LAT, (ll)LL * LAT, (ll)SS * LL, inv_sqrt_lat, nullptr, 0);

    // --- softmax over L (fp16 in, +x1024 scale) -> fp16 ---
    softmax_kernel<<<NB * SS, 256>>>(scores, p);

    // --- G5: att(s,lat) = p(s,l)/1024 . g(lat,l) -> fp16 ---
    mma_gemm<2><<<dim3(LAT / 256, SS / 128, NB), 256, SMEM_TOTAL>>>(
        p, g, nullptr, att,
        LL, LAT, (ll)SS * LL, (ll)LAT * LL, (ll)SS * LAT, IPS, nullptr, 0);

    // --- LayerNorm stats (two-phase) + affine + relu -> fp16 ---
    stats1_kernel<<<256, 256>>>(att, pstat);
    stats2_kernel<<<1, 32>>>(pstat, stats);
    affine_relu_kernel<<<NB * SS / 4, 256>>>(att, lnw_t, lnb_t, stats, y);

    // --- G6: out(c,s) = wout(c,lat)/64 . y(s,lat) + b_out -> fp32 ---
    mma_gemm<0><<<dim3(SS / 256, C_ST / 128, NB), 256, SMEM_TOTAL>>>(
        wout, y, out, nullptr,
        LAT, SS, 0, (ll)SS * LAT, (ll)C_ST * SS, IWS, b_out, 0);
}

// round 15
// speedup vs baseline: 3.4924x; 1.0010x over previous
#include <cuda_runtime.h>
#include <cuda_fp16.h>
#include <cstdint>
#include <math.h>

// ---------------------------------------------------------------------------
// Problem constants
// ---------------------------------------------------------------------------
#define NB    32
#define C_ST  2048
#define C_LT  2048
#define LAT   512
#define SS    512
#define LL    2048
#define LN_EPS 1e-5f

typedef long long ll;
typedef __half fp16;

// ---------------------------------------------------------------------------
// Scratch pool (single __device__ global; offsets in bytes, 256-aligned)
// ---------------------------------------------------------------------------
static constexpr ll SZ_STT   = (ll)NB * SS  * C_ST * 2;
static constexpr ll SZ_LTT   = (ll)NB * LL  * C_LT * 2;
static constexpr ll SZ_THETA = (ll)NB * SS  * LAT  * 2;
static constexpr ll SZ_PHI   = (ll)NB * LL  * LAT  * 2;
static constexpr ll SZ_G     = (ll)NB * LAT * LL   * 2;
static constexpr ll SZ_SCORE = (ll)NB * SS  * LL   * 2;   // fp16
static constexpr ll SZ_P     = (ll)NB * SS  * LL   * 2;
static constexpr ll SZ_ATT   = (ll)NB * SS  * LAT  * 2;   // fp16
static constexpr ll SZ_Y     = (ll)NB * SS  * LAT  * 2;
static constexpr ll SZ_W     = (ll)LAT * C_ST * 2;
static constexpr ll SZ_LN    = (ll)LAT * SS * 4;

static constexpr ll O_STT    = 0;
static constexpr ll O_LTT    = O_STT   + SZ_STT;
static constexpr ll O_THETA  = O_LTT   + SZ_LTT;
static constexpr ll O_PHI    = O_THETA + SZ_THETA;
static constexpr ll O_G      = O_PHI   + SZ_PHI;
static constexpr ll O_SCORE  = O_G     + SZ_G;
static constexpr ll O_P      = O_SCORE + SZ_SCORE;
static constexpr ll O_ATT    = O_P     + SZ_P;
static constexpr ll O_Y      = O_ATT   + SZ_ATT;
static constexpr ll O_WST    = O_Y     + SZ_Y;
static constexpr ll O_WLT    = O_WST   + SZ_W;
static constexpr ll O_WG     = O_WLT   + SZ_W;
static constexpr ll O_WOUT   = O_WG    + SZ_W;
static constexpr ll O_LNW_T  = O_WOUT  + SZ_W;
static constexpr ll O_LNB_T  = O_LNW_T + SZ_LN;
static constexpr ll O_PSTAT  = O_LNB_T + SZ_LN;
static constexpr ll O_STATS  = O_PSTAT + 256 * 8;
static constexpr ll POOL_BYTES = O_STATS + 256;

__device__ __align__(256) unsigned char g_pool[POOL_BYTES];

// ---------------------------------------------------------------------------
// PTX helpers
// ---------------------------------------------------------------------------
__device__ __forceinline__ uint32_t smem_u32(const void* p) {
    uint32_t a;
    asm("{ .reg .u64 t; cvta.to.shared.u64 t, %1; cvt.u32.u64 %0, t; }"
        : "=r"(a) : "l"(p));
    return a;
}
__device__ __forceinline__ void cpa16(uint32_t s, const void* g) {
    asm volatile("cp.async.cg.shared.global [%0], [%1], 16;" :: "r"(s), "l"(g) : "memory");
}
#define CP_COMMIT asm volatile("cp.async.commit_group;" ::: "memory")
#define CP_WAIT2  asm volatile("cp.async.wait_group 2;" ::: "memory")
#define CP_WAIT1  asm volatile("cp.async.wait_group 1;" ::: "memory")
#define CP_WAIT0  asm volatile("cp.async.wait_group 0;" ::: "memory")

#define LDSM4(r, addr) \
    asm volatile("ldmatrix.sync.aligned.m8n8.x4.shared.b16 {%0,%1,%2,%3}, [%4];" \
        : "=r"((r)[0]), "=r"((r)[1]), "=r"((r)[2]), "=r"((r)[3]) : "r"(addr))

// fp16 MMA, k16, fp32 accumulate (full-rate HMMA class)
#define MMAH(d, a, b0, b1) \
    asm volatile("mma.sync.aligned.m16n8k16.row.col.f32.f16.f16.f32 " \
        "{%0,%1,%2,%3}, {%4,%5,%6,%7}, {%8,%9}, {%0,%1,%2,%3};" \
        : "+f"((d)[0]), "+f"((d)[1]), "+f"((d)[2]), "+f"((d)[3]) \
        : "r"((a)[0]), "r"((a)[1]), "r"((a)[2]), "r"((a)[3]), "r"(b0), "r"(b1))

__device__ __forceinline__ uint32_t pack_h(fp16 a, fp16 b) {
    return (uint32_t)__half_as_ushort(a) | ((uint32_t)__half_as_ushort(b) << 16);
}
__device__ __forceinline__ float2 h2f(uint32_t u) {
    __half2 h = *reinterpret_cast<__half2*>(&u);
    return __half22float2(h);
}

// ---------------------------------------------------------------------------
// Tensor-core GEMM (plain fp16):  C(m,n) = alpha*sum_k A(m,k)*B(n,k) + bias
//   A, B K-major fp16 (lda=ldb=K). CTA tile M=128, N=256, K-chunk 64.
//   Warp grid 2(m) x 4(n); warp tile 64x64. 3-stage cp.async ring.
//   OUT=0: fp32 Cf.  OUT=2: fp16 Ch.
//   STATS=1: additionally reduce all outputs (pre-round fp32) to a
//            per-CTA (sum, sumsq) partial at pstat[b*8 + bx*4 + by].
// Stage: A[0,16K) B[16K,48K) -> 48K/stage, 144K total.
// ---------------------------------------------------------------------------
static constexpr uint32_t STAGE = 49152;
static constexpr int SMEM_TOTAL = 3 * (int)STAGE;

template <int OUT, int STATS>
__global__ __launch_bounds__(256) void mma_gemm(
    const fp16* __restrict__ A, const fp16* __restrict__ B,
    float* __restrict__ Cf, fp16* __restrict__ Ch,
    int K, int ldc, ll sA, ll sB, ll sC,
    float alpha, const float* __restrict__ bias, int bias_per_n,
    float2* __restrict__ pstat)
{
    extern __shared__ __align__(1024) char smem[];
    const uint32_t sb = smem_u32(smem);
    const int tid  = threadIdx.x;
    const int wid  = tid >> 5, lane = tid & 31;
    const ll  b    = blockIdx.z;
    const int m0   = blockIdx.y << 7;
    const int n0   = blockIdx.x << 8;

    const fp16* Ab = A + b * sA;
    const fp16* Bb = B + b * sB;

    const int C = K >> 6;

    auto load_chunk = [&](int ct, int stg) {
        const uint32_t base = sb + stg * STAGE;
        const int kt = ct << 6;
#pragma unroll
        for (int i = 0; i < 4; ++i) {           // A: 128 rows x 128B
            int idx = tid + (i << 8);
            int row = idx >> 3, seg = idx & 7;
            uint32_t so = (uint32_t)((row << 7) + (seg << 4));
            so ^= (so >> 3) & 0x70;
            cpa16(base + so, Ab + (ll)(m0 + row) * K + kt + (seg << 3));
        }
#pragma unroll
        for (int i = 0; i < 8; ++i) {           // B: 256 rows x 128B
            int idx = tid + (i << 8);
            int row = idx >> 3, seg = idx & 7;
            uint32_t so = (uint32_t)((row << 7) + (seg << 4));
            so ^= (so >> 3) & 0x70;
            cpa16(base + 16384 + so, Bb + (ll)(n0 + row) * K + kt + (seg << 3));
        }
    };

    load_chunk(0, 0); CP_COMMIT;
    if (C > 1) { load_chunk(1, 1); CP_COMMIT; }

    // warp tiling: 2 (m) x 4 (n); each warp 64(m) x 64(n)
    const int wm = wid >> 2, wn = wid & 3;
    float acc[4][8][4];
#pragma unroll
    for (int i = 0; i < 4; ++i)
#pragma unroll
        for (int j = 0; j < 8; ++j)
#pragma unroll
            for (int q = 0; q < 4; ++q) acc[i][j][q] = 0.f;

    const uint32_t a_row = (uint32_t)(wm * 64 + (lane & 15));
    const uint32_t a_sb  = (uint32_t)(lane >> 4);
    const uint32_t b_row = (uint32_t)(wn * 64 + ((lane >> 4) << 3) + (lane & 7));
    const uint32_t b_sb  = (uint32_t)((lane >> 3) & 1);

    for (int ct = 0; ct < C; ++ct) {
        // issue-ahead-2 into the stage freed two iterations ago
        if (ct + 2 < C) { load_chunk(ct + 2, (ct + 2) % 3); CP_COMMIT; CP_WAIT2; }
        else if (ct + 1 < C) { CP_WAIT1; }
        else { CP_WAIT0; }
        __syncthreads();
        const uint32_t sbase = sb + (ct % 3) * STAGE;

#pragma unroll
        for (int s = 0; s < 4; ++s) {           // 4 x k16 per chunk
            uint32_t ah[4][4];
#pragma unroll
            for (int mt = 0; mt < 4; ++mt) {
                uint32_t row = a_row + mt * 16;
                uint32_t seg = (uint32_t)(s * 2) + a_sb;
                uint32_t off = (row << 7) + (seg << 4);
                off ^= (off >> 3) & 0x70;
                LDSM4(ah[mt], sbase + off);
            }
            uint32_t bh[4][4];
#pragma unroll
            for (int ng = 0; ng < 4; ++ng) {
                uint32_t row = b_row + ng * 16;
                uint32_t seg = (uint32_t)(s * 2) + b_sb;
                uint32_t off = (row << 7) + (seg << 4);
                off ^= (off >> 3) & 0x70;
                LDSM4(bh[ng], sbase + 16384 + off);
            }
#pragma unroll
            for (int mt = 0; mt < 4; ++mt) {
#pragma unroll
                for (int ng = 0; ng < 4; ++ng) {
                    MMAH(acc[mt][2 * ng],     ah[mt], bh[ng][0], bh[ng][1]);
                    MMAH(acc[mt][2 * ng + 1], ah[mt], bh[ng][2], bh[ng][3]);
                }
            }
        }
        __syncthreads();
    }

    // ---- epilogue ----
    float ls = 0.f, ls2 = 0.f;                  // STATS accumulators
    const int l4 = lane >> 2;
    const int l2 = (lane & 3) * 2;
#pragma unroll
    for (int mt = 0; mt < 4; ++mt) {
        const int m = m0 + wm * 64 + mt * 16 + l4;
        float bm0 = 0.f, bm8 = 0.f;
        if (bias && !bias_per_n) { bm0 = bias[m]; bm8 = bias[m + 8]; }
#pragma unroll
        for (int nt = 0; nt < 8; ++nt) {
            const int n = n0 + wn * 64 + nt * 8 + l2;
            float bn0 = 0.f, bn1 = 0.f;
            if (bias && bias_per_n) { bn0 = bias[n]; bn1 = bias[n + 1]; }
            const float* a4 = acc[mt][nt];
            float v00 = a4[0] * alpha, v01 = a4[1] * alpha;
            float v10 = a4[2] * alpha, v11 = a4[3] * alpha;
            if (bias) {
                if (bias_per_n) { v00 += bn0; v01 += bn1; v10 += bn0; v11 += bn1; }
                else            { v00 += bm0; v01 += bm0; v10 += bm8; v11 += bm8; }
            }
            if (STATS) {
                ls  += v00 + v01 + v10 + v11;
                ls2 += v00 * v00 + v01 * v01 + v10 * v10 + v11 * v11;
            }
            ll o0 = b * sC + (ll)m * ldc + n;
            ll o1 = b * sC + (ll)(m + 8) * ldc + n;
            if (OUT == 0) {
                *reinterpret_cast<float2*>(Cf + o0) = make_float2(v00, v01);
                *reinterpret_cast<float2*>(Cf + o1) = make_float2(v10, v11);
            } else {
                *reinterpret_cast<uint32_t*>(Ch + o0) =
                    pack_h(__float2half_rn(v00), __float2half_rn(v01));
                *reinterpret_cast<uint32_t*>(Ch + o1) =
                    pack_h(__float2half_rn(v10), __float2half_rn(v11));
            }
        }
    }
    if (STATS) {
#pragma unroll
        for (int o = 16; o > 0; o >>= 1) {
            ls  += __shfl_xor_sync(0xffffffffu, ls,  o);
            ls2 += __shfl_xor_sync(0xffffffffu, ls2, o);
        }
        __shared__ float rs[8], rs2[8];
        if (lane == 0) { rs[wid] = ls; rs2[wid] = ls2; }
        __syncthreads();
        if (tid == 0) {
            float S = 0.f, S2 = 0.f;
#pragma unroll
            for (int i = 0; i < 8; ++i) { S += rs[i]; S2 += rs2[i]; }
            pstat[b * 8 + blockIdx.x * 4 + blockIdx.y] = make_float2(S, S2);
        }
    }
}

// ---------------------------------------------------------------------------
// fp32 -> scaled fp16 round, 8 elems/thread, 16B stores.
// ---------------------------------------------------------------------------
__global__ __launch_bounds__(256) void round_kernel(
    const float* __restrict__ in, fp16* __restrict__ out, float scale)
{
    ll i = ((ll)blockIdx.x * 256 + threadIdx.x) * 8;
    float4 a = *reinterpret_cast<const float4*>(in + i);
    float4 c = *reinterpret_cast<const float4*>(in + i + 4);
    float v[8] = {a.x, a.y, a.z, a.w, c.x, c.y, c.z, c.w};
    uint32_t hp[4];
#pragma unroll
    for (int q = 0; q < 4; ++q)
        hp[q] = pack_h(__float2half_rn(v[2*q] * scale), __float2half_rn(v[2*q+1] * scale));
    *reinterpret_cast<uint4*>(out + i) = make_uint4(hp[0], hp[1], hp[2], hp[3]);
}

// ---------------------------------------------------------------------------
// Transpose + fp16 round: in (b, R, X) fp32 -> out (b, X, R) fp16
// ---------------------------------------------------------------------------
__global__ __launch_bounds__(256) void transpose_h_kernel(
    const float* __restrict__ in, fp16* __restrict__ hi, int R, int X)
{
    __shared__ float t[64][65];
    const ll b = blockIdx.z;
    const float* ib = in + b * (ll)R * X;
    const int x0 = blockIdx.x << 6, r0 = blockIdx.y << 6;
    const int tx = threadIdx.x & 15;
    const int ty = threadIdx.x >> 4;
#pragma unroll
    for (int i = 0; i < 4; ++i) {
        int r = ty + 16 * i;
        float4 v = *reinterpret_cast<const float4*>(
            ib + (ll)(r0 + r) * X + x0 + tx * 4);
        t[r][tx * 4 + 0] = v.x; t[r][tx * 4 + 1] = v.y;
        t[r][tx * 4 + 2] = v.z; t[r][tx * 4 + 3] = v.w;
    }
    __syncthreads();
    const ll ob = b * (ll)R * X;
#pragma unroll
    for (int i = 0; i < 4; ++i) {
        int xr = ty + 16 * i;
        fp16 h0 = __float2half_rn(t[tx * 4 + 0][xr]);
        fp16 h1 = __float2half_rn(t[tx * 4 + 1][xr]);
        fp16 h2 = __float2half_rn(t[tx * 4 + 2][xr]);
        fp16 h3 = __float2half_rn(t[tx * 4 + 3][xr]);
        ll o = ob + (ll)(x0 + xr) * R + r0 + tx * 4;
        *reinterpret_cast<uint2*>(hi + o) = make_uint2(pack_h(h0, h1), pack_h(h2, h3));
    }
}

// ---------------------------------------------------------------------------
// Plain fp32 transpose (ln params)
// ---------------------------------------------------------------------------
__global__ __launch_bounds__(256) void transpose_f32_kernel(
    const float* __restrict__ in, float* __restrict__ out, int R, int X)
{
    __shared__ float t[32][33];
    const int x0 = blockIdx.x << 5, r0 = blockIdx.y << 5;
    const int tx = threadIdx.x & 31, ty = threadIdx.x >> 5;
#pragma unroll
    for (int i = 0; i < 4; ++i)
        t[ty + 8 * i][tx] = in[(ll)(r0 + ty + 8 * i) * X + x0 + tx];
    __syncthreads();
#pragma unroll
    for (int i = 0; i < 4; ++i)
        out[(ll)(x0 + ty + 8 * i) * R + r0 + tx] = t[tx][ty + 8 * i];
}

// ---------------------------------------------------------------------------
// Softmax over L (=2048), fp16 logits in; p scaled x1024, fp16 out.
// ---------------------------------------------------------------------------
__global__ __launch_bounds__(256) void softmax_kernel(
    const fp16* __restrict__ x, fp16* __restrict__ ph)
{
    const ll row = blockIdx.x;
    const int tid = threadIdx.x;
    const fp16* p = x + row * (ll)LL + tid * 8;

    uint4 u = *reinterpret_cast<const uint4*>(p);
    float2 f0 = h2f(u.x), f1 = h2f(u.y), f2 = h2f(u.z), f3 = h2f(u.w);
    float v[8] = {f0.x, f0.y, f1.x, f1.y, f2.x, f2.y, f3.x, f3.y};

    float m = v[0];
#pragma unroll
    for (int i = 1; i < 8; ++i) m = fmaxf(m, v[i]);
#pragma unroll
    for (int o = 16; o > 0; o >>= 1) m = fmaxf(m, __shfl_xor_sync(0xffffffffu, m, o));
    __shared__ float sm[8];
    if ((tid & 31) == 0) sm[tid >> 5] = m;
    __syncthreads();
    float mx = sm[0];
#pragma unroll
    for (int i = 1; i < 8; ++i) mx = fmaxf(mx, sm[i]);

    float s = 0.f;
#pragma unroll
    for (int i = 0; i < 8; ++i) { v[i] = __expf(v[i] - mx); s += v[i]; }
#pragma unroll
    for (int o = 16; o > 0; o >>= 1) s += __shfl_xor_sync(0xffffffffu, s, o);
    __shared__ float ss[8];
    if ((tid & 31) == 0) ss[tid >> 5] = s;
    __syncthreads();
    float tot = 0.f;
#pragma unroll
    for (int i = 0; i < 8; ++i) tot += ss[i];
    float inv = 1024.f / tot;     // p scaled by 1024 (undone by alpha in G5)

    uint32_t hp[4];
#pragma unroll
    for (int q = 0; q < 4; ++q)
        hp[q] = pack_h(__float2half_rn(v[2*q] * inv), __float2half_rn(v[2*q+1] * inv));
    ll o = row * (ll)LL + tid * 8;
    *reinterpret_cast<uint4*>(ph + o) = make_uint4(hp[0], hp[1], hp[2], hp[3]);
}

// ---------------------------------------------------------------------------
// LN stats phase 2: combine 8 per-CTA partials per batch (fixed order).
// ---------------------------------------------------------------------------
__global__ __launch_bounds__(32) void stats2_kernel(
    const float2* __restrict__ part, float2* __restrict__ stats)
{
    const int n = threadIdx.x;
    float S = 0.f, S2 = 0.f;
#pragma unroll
    for (int i = 0; i < 8; ++i) {
        float2 p = part[n * 8 + i];
        S += p.x; S2 += p.y;
    }
    const float invM = 1.f / (float)(LAT * SS);
    float mu = S * invM;
    float var = S2 * invM - mu * mu;
    stats[n] = make_float2(mu, rsqrtf(var + LN_EPS));
}

// ---------------------------------------------------------------------------
// LN affine + ReLU, att fp16 -> y fp16
// ---------------------------------------------------------------------------
__global__ __launch_bounds__(256) void affine_relu_kernel(
    const fp16* __restrict__ att, const float* __restrict__ wT,
    const float* __restrict__ bT, const float2* __restrict__ stats,
    fp16* __restrict__ yh)
{
    const int r = threadIdx.x >> 6;
    const int c = (threadIdx.x & 63) * 8;
    const ll row = (ll)blockIdx.x * 4 + r;
    const int b = (int)(row >> 9), s = (int)(row & 511);
    const float2 st = stats[b];
    const fp16* xx = att + row * (ll)LAT + c;
    const float* ww = wT + (ll)s * LAT + c;
    const float* bb = bT + (ll)s * LAT + c;

    uint4 xu = *reinterpret_cast<const uint4*>(xx);
    float2 xf0 = h2f(xu.x), xf1 = h2f(xu.y), xf2 = h2f(xu.z), xf3 = h2f(xu.w);
    float xv[8] = {xf0.x, xf0.y, xf1.x, xf1.y, xf2.x, xf2.y, xf3.x, xf3.y};
    float4 w0 = *reinterpret_cast<const float4*>(ww);
    float4 w1 = *reinterpret_cast<const float4*>(ww + 4);
    float4 b0 = *reinterpret_cast<const float4*>(bb);
    float4 b1 = *reinterpret_cast<const float4*>(bb + 4);
    float wv[8] = {w0.x, w0.y, w0.z, w0.w, w1.x, w1.y, w1.z, w1.w};
    float bv[8] = {b0.x, b0.y, b0.z, b0.w, b1.x, b1.y, b1.z, b1.w};

    uint32_t hp[4];
#pragma unroll
    for (int q = 0; q < 4; ++q) {
        float v0 = fmaxf((xv[2*q]   - st.x) * st.y * wv[2*q]   + bv[2*q],   0.f);
        float v1 = fmaxf((xv[2*q+1] - st.x) * st.y * wv[2*q+1] + bv[2*q+1], 0.f);
        hp[q] = pack_h(__float2half_rn(v0), __float2half_rn(v1));
    }
    ll o = row * (ll)LAT + c;
    *reinterpret_cast<uint4*>(yh + o) = make_uint4(hp[0], hp[1], hp[2], hp[3]);
}

// ---------------------------------------------------------------------------
// Launch
// ---------------------------------------------------------------------------
extern "C" void kernel_launch(void* const* d_in, const int* in_sizes, int n_in,
                              void* d_out, int out_size)
{
    const float* st_feat = (const float*)d_in[0];
    const float* lt_feat = (const float*)d_in[1];
    const float* w_st    = (const float*)d_in[2];
    const float* b_st    = (const float*)d_in[3];
    const float* w_lt    = (const float*)d_in[4];
    const float* b_lt    = (const float*)d_in[5];
    const float* w_g     = (const float*)d_in[6];
    const float* b_g     = (const float*)d_in[7];
    const float* ln_w    = (const float*)d_in[8];
    const float* ln_b    = (const float*)d_in[9];
    const float* w_out   = (const float*)d_in[10];
    const float* b_out   = (const float*)d_in[11];
    float* out = (float*)d_out;

    unsigned char* pool;
    cudaGetSymbolAddress((void**)&pool, g_pool);
    fp16* stT    = (fp16*)(pool + O_STT);
    fp16* ltT    = (fp16*)(pool + O_LTT);
    fp16* theta  = (fp16*)(pool + O_THETA);
    fp16* phi    = (fp16*)(pool + O_PHI);
    fp16* g      = (fp16*)(pool + O_G);
    fp16* scores = (fp16*)(pool + O_SCORE);
    fp16* p      = (fp16*)(pool + O_P);
    fp16* att    = (fp16*)(pool + O_ATT);
    fp16* y      = (fp16*)(pool + O_Y);
    fp16* wst    = (fp16*)(pool + O_WST);
    fp16* wlt    = (fp16*)(pool + O_WLT);
    fp16* wg     = (fp16*)(pool + O_WG);
    fp16* wout   = (fp16*)(pool + O_WOUT);
    float* lnw_t = (float*)(pool + O_LNW_T);
    float* lnb_t = (float*)(pool + O_LNB_T);
    float2* pstat= (float2*)(pool + O_PSTAT);
    float2* stats= (float2*)(pool + O_STATS);

    cudaFuncSetAttribute(mma_gemm<0,0>, cudaFuncAttributeMaxDynamicSharedMemorySize, SMEM_TOTAL);
    cudaFuncSetAttribute(mma_gemm<2,0>, cudaFuncAttributeMaxDynamicSharedMemorySize, SMEM_TOTAL);
    cudaFuncSetAttribute(mma_gemm<2,1>, cudaFuncAttributeMaxDynamicSharedMemorySize, SMEM_TOTAL);

    const float inv_sqrt_lat = 0.044194173824159216f;   // 1/sqrt(512)
    const float WS = 64.f, IWS = 1.f / 64.f;            // weight pre-scale
    const float IPS = 1.f / 1024.f;                     // p pre-scale undo

    // --- operand conversion ---
    round_kernel<<<512, 256>>>(w_st,  wst,  WS);
    round_kernel<<<512, 256>>>(w_lt,  wlt,  WS);
    round_kernel<<<512, 256>>>(w_g,   wg,   WS);
    round_kernel<<<512, 256>>>(w_out, wout, WS);
    transpose_h_kernel<<<dim3(SS / 64, C_ST / 64, NB), 256>>>(st_feat, stT, C_ST, SS);
    transpose_h_kernel<<<dim3(LL / 64, C_LT / 64, NB), 256>>>(lt_feat, ltT, C_LT, LL);
    transpose_f32_kernel<<<dim3(SS / 32, LAT / 32), 256>>>(ln_w, lnw_t, LAT, SS);
    transpose_f32_kernel<<<dim3(SS / 32, LAT / 32), 256>>>(ln_b, lnb_t, LAT, SS);

    // --- G1: theta(s,lat) = stT(s,c) . wst(lat,c)/64 + b_st -> fp16 ---
    mma_gemm<2,0><<<dim3(LAT / 256, SS / 128, NB), 256, SMEM_TOTAL>>>(
        stT, wst, nullptr, theta,
        C_ST, LAT, (ll)SS * C_ST, 0, (ll)SS * LAT, IWS, b_st, 1, nullptr);

    // --- G2: phi(l,lat) = ltT(l,c) . wlt(lat,c)/64 + b_lt -> fp16 ---
    mma_gemm<2,0><<<dim3(LAT / 256, LL / 128, NB), 256, SMEM_TOTAL>>>(
        ltT, wlt, nullptr, phi,
        C_LT, LAT, (ll)LL * C_LT, 0, (ll)LL * LAT, IWS, b_lt, 1, nullptr);

    // --- G3: g(lat,l) = wg(lat,c)/64 . ltT(l,c) + b_g -> fp16 ---
    mma_gemm<2,0><<<dim3(LL / 256, LAT / 128, NB), 256, SMEM_TOTAL>>>(
        wg, ltT, nullptr, g,
        C_LT, LL, 0, (ll)LL * C_LT, (ll)LAT * LL, IWS, b_g, 0, nullptr);

    // --- G4: scores(s,l) = theta(s,.) . phi(l,.) / sqrt(LAT) -> fp16 ---
    mma_gemm<2,0><<<dim3(LL / 256, SS / 128, NB), 256, SMEM_TOTAL>>>(
        theta, phi, nullptr, scores,
        LAT, LL, (ll)SS * LAT, (ll)LL * LAT, (ll)SS * LL, inv_sqrt_lat, nullptr, 0, nullptr);

    // --- softmax over L (fp16 in, +x1024 scale) -> fp16 ---
    softmax_kernel<<<NB * SS, 256>>>(scores, p);

    // --- G5: att(s,lat) = p(s,l)/1024 . g(lat,l) -> fp16, fused LN partials ---
    mma_gemm<2,1><<<dim3(LAT / 256, SS / 128, NB), 256, SMEM_TOTAL>>>(
        p, g, nullptr, att,
        LL, LAT, (ll)SS * LL, (ll)LAT * LL, (ll)SS * LAT, IPS, nullptr, 0, pstat);

    // --- LN stats combine + affine + relu -> fp16 ---
    stats2_kernel<<<1, 32>>>(pstat, stats);
    affine_relu_kernel<<<NB * SS / 4, 256>>>(att, lnw_t, lnb_t, stats, y);

    // --- G6: out(c,s) = wout(c,lat)/64 . y(s,lat) + b_out -> fp32 ---
    mma_gemm<0,0><<<dim3(SS / 256, C_ST / 128, NB), 256, SMEM_TOTAL>>>(
        wout, y, out, nullptr,
        LAT, SS, 0, (ll)SS * LAT, (ll)C_ST * SS, IWS, b_out, 0, nullptr);
}

// round 16
// speedup vs baseline: 3.5217x; 1.0084x over previous
#include <cuda_runtime.h>
#include <cuda_fp16.h>
#include <cstdint>
#include <math.h>

// ---------------------------------------------------------------------------
// Problem constants
// ---------------------------------------------------------------------------
#define NB    32
#define C_ST  2048
#define C_LT  2048
#define LAT   512
#define SS    512
#define LL    2048
#define LN_EPS 1e-5f

typedef long long ll;
typedef __half fp16;

// ---------------------------------------------------------------------------
// Scratch pool (single __device__ global; offsets in bytes, 256-aligned)
// ---------------------------------------------------------------------------
static constexpr ll SZ_STT   = (ll)NB * SS  * C_ST * 2;
static constexpr ll SZ_LTT   = (ll)NB * LL  * C_LT * 2;
static constexpr ll SZ_THETA = (ll)NB * SS  * LAT  * 2;
static constexpr ll SZ_PHI   = (ll)NB * LL  * LAT  * 2;
static constexpr ll SZ_G     = (ll)NB * LAT * LL   * 2;
static constexpr ll SZ_SCORE = (ll)NB * SS  * LL   * 2;   // fp16
static constexpr ll SZ_P     = (ll)NB * SS  * LL   * 2;
static constexpr ll SZ_ATT   = (ll)NB * SS  * LAT  * 2;   // fp16
static constexpr ll SZ_Y     = (ll)NB * SS  * LAT  * 2;
static constexpr ll SZ_W     = (ll)LAT * C_ST * 2;
static constexpr ll SZ_LN    = (ll)LAT * SS * 4;

static constexpr ll O_STT    = 0;
static constexpr ll O_LTT    = O_STT   + SZ_STT;
static constexpr ll O_THETA  = O_LTT   + SZ_LTT;
static constexpr ll O_PHI    = O_THETA + SZ_THETA;
static constexpr ll O_G      = O_PHI   + SZ_PHI;
static constexpr ll O_SCORE  = O_G     + SZ_G;
static constexpr ll O_P      = O_SCORE + SZ_SCORE;
static constexpr ll O_ATT    = O_P     + SZ_P;
static constexpr ll O_Y      = O_ATT   + SZ_ATT;
static constexpr ll O_WST    = O_Y     + SZ_Y;
static constexpr ll O_WLT    = O_WST   + SZ_W;
static constexpr ll O_WG     = O_WLT   + SZ_W;
static constexpr ll O_WOUT   = O_WG    + SZ_W;
static constexpr ll O_LNW_T  = O_WOUT  + SZ_W;
static constexpr ll O_LNB_T  = O_LNW_T + SZ_LN;
static constexpr ll O_PSTAT  = O_LNB_T + SZ_LN;
static constexpr ll O_STATS  = O_PSTAT + 256 * 8;
static constexpr ll POOL_BYTES = O_STATS + 256;

__device__ __align__(256) unsigned char g_pool[POOL_BYTES];

// ---------------------------------------------------------------------------
// PTX helpers
// ---------------------------------------------------------------------------
__device__ __forceinline__ uint32_t smem_u32(const void* p) {
    uint32_t a;
    asm("{ .reg .u64 t; cvta.to.shared.u64 t, %1; cvt.u32.u64 %0, t; }"
        : "=r"(a) : "l"(p));
    return a;
}
__device__ __forceinline__ void cpa16(uint32_t s, const void* g) {
    asm volatile("cp.async.cg.shared.global [%0], [%1], 16;" :: "r"(s), "l"(g) : "memory");
}
#define CP_COMMIT asm volatile("cp.async.commit_group;" ::: "memory")
#define CP_WAIT2  asm volatile("cp.async.wait_group 2;" ::: "memory")
#define CP_WAIT1  asm volatile("cp.async.wait_group 1;" ::: "memory")
#define CP_WAIT0  asm volatile("cp.async.wait_group 0;" ::: "memory")

#define LDSM4(r, addr) \
    asm volatile("ldmatrix.sync.aligned.m8n8.x4.shared.b16 {%0,%1,%2,%3}, [%4];" \
        : "=r"((r)[0]), "=r"((r)[1]), "=r"((r)[2]), "=r"((r)[3]) : "r"(addr))

// fp16 MMA, k16, fp32 accumulate (full-rate HMMA class)
#define MMAH(d, a, b0, b1) \
    asm volatile("mma.sync.aligned.m16n8k16.row.col.f32.f16.f16.f32 " \
        "{%0,%1,%2,%3}, {%4,%5,%6,%7}, {%8,%9}, {%0,%1,%2,%3};" \
        : "+f"((d)[0]), "+f"((d)[1]), "+f"((d)[2]), "+f"((d)[3]) \
        : "r"((a)[0]), "r"((a)[1]), "r"((a)[2]), "r"((a)[3]), "r"(b0), "r"(b1))

__device__ __forceinline__ uint32_t pack_h(fp16 a, fp16 b) {
    return (uint32_t)__half_as_ushort(a) | ((uint32_t)__half_as_ushort(b) << 16);
}
__device__ __forceinline__ float2 h2f(uint32_t u) {
    __half2 h = *reinterpret_cast<__half2*>(&u);
    return __half22float2(h);
}

// ---------------------------------------------------------------------------
// Tensor-core GEMM (plain fp16):  C(m,n) = alpha*sum_k A(m,k)*B(n,k) + bias
//   A, B K-major fp16 (lda=ldb=K). CTA tile M=128, N=256, K-chunk 64.
//   Warp grid 2(m) x 4(n); warp tile 64x64. 3-stage cp.async ring.
//   OUT=0: fp32 Cf.  OUT=2: fp16 Ch.
//   STATS=1: reduce outputs (pre-round fp32) to per-CTA (sum,sumsq) partial.
// Stage: A[0,16K) B[16K,48K) -> 48K/stage, 144K total.
// ---------------------------------------------------------------------------
static constexpr uint32_t STAGE = 49152;
static constexpr int SMEM_TOTAL = 3 * (int)STAGE;

template <int OUT, int STATS>
__global__ __launch_bounds__(256) void mma_gemm(
    const fp16* __restrict__ A, const fp16* __restrict__ B,
    float* __restrict__ Cf, fp16* __restrict__ Ch,
    int K, int ldc, ll sA, ll sB, ll sC,
    float alpha, const float* __restrict__ bias, int bias_per_n,
    float2* __restrict__ pstat)
{
    extern __shared__ __align__(1024) char smem[];
    const uint32_t sb = smem_u32(smem);
    const int tid  = threadIdx.x;
    const int wid  = tid >> 5, lane = tid & 31;
    const ll  b    = blockIdx.z;
    const int m0   = blockIdx.y << 7;
    const int n0   = blockIdx.x << 8;

    const fp16* Ab = A + b * sA;
    const fp16* Bb = B + b * sB;

    const int C = K >> 6;

    auto load_chunk = [&](int ct, int stg) {
        const uint32_t base = sb + stg * STAGE;
        const int kt = ct << 6;
#pragma unroll
        for (int i = 0; i < 4; ++i) {           // A: 128 rows x 128B
            int idx = tid + (i << 8);
            int row = idx >> 3, seg = idx & 7;
            uint32_t so = (uint32_t)((row << 7) + (seg << 4));
            so ^= (so >> 3) & 0x70;
            cpa16(base + so, Ab + (ll)(m0 + row) * K + kt + (seg << 3));
        }
#pragma unroll
        for (int i = 0; i < 8; ++i) {           // B: 256 rows x 128B
            int idx = tid + (i << 8);
            int row = idx >> 3, seg = idx & 7;
            uint32_t so = (uint32_t)((row << 7) + (seg << 4));
            so ^= (so >> 3) & 0x70;
            cpa16(base + 16384 + so, Bb + (ll)(n0 + row) * K + kt + (seg << 3));
        }
    };

    load_chunk(0, 0); CP_COMMIT;
    if (C > 1) { load_chunk(1, 1); CP_COMMIT; }

    // warp tiling: 2 (m) x 4 (n); each warp 64(m) x 64(n)
    const int wm = wid >> 2, wn = wid & 3;
    float acc[4][8][4];
#pragma unroll
    for (int i = 0; i < 4; ++i)
#pragma unroll
        for (int j = 0; j < 8; ++j)
#pragma unroll
            for (int q = 0; q < 4; ++q) acc[i][j][q] = 0.f;

    const uint32_t a_row = (uint32_t)(wm * 64 + (lane & 15));
    const uint32_t a_sb  = (uint32_t)(lane >> 4);
    const uint32_t b_row = (uint32_t)(wn * 64 + ((lane >> 4) << 3) + (lane & 7));
    const uint32_t b_sb  = (uint32_t)((lane >> 3) & 1);

    for (int ct = 0; ct < C; ++ct) {
        if (ct + 2 < C) { load_chunk(ct + 2, (ct + 2) % 3); CP_COMMIT; CP_WAIT2; }
        else if (ct + 1 < C) { CP_WAIT1; }
        else { CP_WAIT0; }
        __syncthreads();
        const uint32_t sbase = sb + (ct % 3) * STAGE;

#pragma unroll
        for (int s = 0; s < 4; ++s) {           // 4 x k16 per chunk
            uint32_t ah[4][4];
#pragma unroll
            for (int mt = 0; mt < 4; ++mt) {
                uint32_t row = a_row + mt * 16;
                uint32_t seg = (uint32_t)(s * 2) + a_sb;
                uint32_t off = (row << 7) + (seg << 4);
                off ^= (off >> 3) & 0x70;
                LDSM4(ah[mt], sbase + off);
            }
            uint32_t bh[4][4];
#pragma unroll
            for (int ng = 0; ng < 4; ++ng) {
                uint32_t row = b_row + ng * 16;
                uint32_t seg = (uint32_t)(s * 2) + b_sb;
                uint32_t off = (row << 7) + (seg << 4);
                off ^= (off >> 3) & 0x70;
                LDSM4(bh[ng], sbase + 16384 + off);
            }
#pragma unroll
            for (int mt = 0; mt < 4; ++mt) {
#pragma unroll
                for (int ng = 0; ng < 4; ++ng) {
                    MMAH(acc[mt][2 * ng],     ah[mt], bh[ng][0], bh[ng][1]);
                    MMAH(acc[mt][2 * ng + 1], ah[mt], bh[ng][2], bh[ng][3]);
                }
            }
        }
        __syncthreads();
    }

    // ---- epilogue ----
    float ls = 0.f, ls2 = 0.f;
    const int l4 = lane >> 2;
    const int l2 = (lane & 3) * 2;
#pragma unroll
    for (int mt = 0; mt < 4; ++mt) {
        const int m = m0 + wm * 64 + mt * 16 + l4;
        float bm0 = 0.f, bm8 = 0.f;
        if (bias && !bias_per_n) { bm0 = bias[m]; bm8 = bias[m + 8]; }
#pragma unroll
        for (int nt = 0; nt < 8; ++nt) {
            const int n = n0 + wn * 64 + nt * 8 + l2;
            float bn0 = 0.f, bn1 = 0.f;
            if (bias && bias_per_n) { bn0 = bias[n]; bn1 = bias[n + 1]; }
            const float* a4 = acc[mt][nt];
            float v00 = a4[0] * alpha, v01 = a4[1] * alpha;
            float v10 = a4[2] * alpha, v11 = a4[3] * alpha;
            if (bias) {
                if (bias_per_n) { v00 += bn0; v01 += bn1; v10 += bn0; v11 += bn1; }
                else            { v00 += bm0; v01 += bm0; v10 += bm8; v11 += bm8; }
            }
            if (STATS) {
                ls  += v00 + v01 + v10 + v11;
                ls2 += v00 * v00 + v01 * v01 + v10 * v10 + v11 * v11;
            }
            ll o0 = b * sC + (ll)m * ldc + n;
            ll o1 = b * sC + (ll)(m + 8) * ldc + n;
            if (OUT == 0) {
                *reinterpret_cast<float2*>(Cf + o0) = make_float2(v00, v01);
                *reinterpret_cast<float2*>(Cf + o1) = make_float2(v10, v11);
            } else {
                *reinterpret_cast<uint32_t*>(Ch + o0) =
                    pack_h(__float2half_rn(v00), __float2half_rn(v01));
                *reinterpret_cast<uint32_t*>(Ch + o1) =
                    pack_h(__float2half_rn(v10), __float2half_rn(v11));
            }
        }
    }
    if (STATS) {
#pragma unroll
        for (int o = 16; o > 0; o >>= 1) {
            ls  += __shfl_xor_sync(0xffffffffu, ls,  o);
            ls2 += __shfl_xor_sync(0xffffffffu, ls2, o);
        }
        __shared__ float rs[8], rs2[8];
        if (lane == 0) { rs[wid] = ls; rs2[wid] = ls2; }
        __syncthreads();
        if (tid == 0) {
            float S = 0.f, S2 = 0.f;
#pragma unroll
            for (int i = 0; i < 8; ++i) { S += rs[i]; S2 += rs2[i]; }
            pstat[b * 8 + blockIdx.x * 4 + blockIdx.y] = make_float2(S, S2);
        }
    }
}

// ---------------------------------------------------------------------------
// Fused prep: y=0..3 -> round 4 weight matrices (512 blocks x 2048 elems);
//             y=4    -> ln_w (blocks 0-255) / ln_b (blocks 256-511) 32x32
//                       fp32 transposes (LAT x SS -> SS x LAT).
// ---------------------------------------------------------------------------
__global__ __launch_bounds__(256) void prep_kernel(
    const float* __restrict__ w_st,  fp16* __restrict__ wst,
    const float* __restrict__ w_lt,  fp16* __restrict__ wlt,
    const float* __restrict__ w_g,   fp16* __restrict__ wg,
    const float* __restrict__ w_out, fp16* __restrict__ wout,
    const float* __restrict__ ln_w,  float* __restrict__ lnw_t,
    const float* __restrict__ ln_b,  float* __restrict__ lnb_t,
    float scale)
{
    const int yv = blockIdx.y;
    if (yv < 4) {
        const float* in  = (yv == 0) ? w_st : (yv == 1) ? w_lt : (yv == 2) ? w_g : w_out;
        fp16*        out = (yv == 0) ? wst  : (yv == 1) ? wlt  : (yv == 2) ? wg  : wout;
        ll i = ((ll)blockIdx.x * 256 + threadIdx.x) * 8;
        float4 a = *reinterpret_cast<const float4*>(in + i);
        float4 c = *reinterpret_cast<const float4*>(in + i + 4);
        float v[8] = {a.x, a.y, a.z, a.w, c.x, c.y, c.z, c.w};
        uint32_t hp[4];
#pragma unroll
        for (int q = 0; q < 4; ++q)
            hp[q] = pack_h(__float2half_rn(v[2*q] * scale), __float2half_rn(v[2*q+1] * scale));
        *reinterpret_cast<uint4*>(out + i) = make_uint4(hp[0], hp[1], hp[2], hp[3]);
    } else {
        __shared__ float t[32][33];
        const int which = blockIdx.x >> 8;          // 0 = ln_w, 1 = ln_b
        const int tile  = blockIdx.x & 255;
        const float* in  = which ? ln_b  : ln_w;    // (LAT, SS)
        float*       out = which ? lnb_t : lnw_t;   // (SS, LAT)
        const int x0 = (tile & 15) << 5;            // SS tile
        const int r0 = (tile >> 4) << 5;            // LAT tile
        const int tx = threadIdx.x & 31, ty = threadIdx.x >> 5;
#pragma unroll
        for (int i = 0; i < 4; ++i)
            t[ty + 8 * i][tx] = in[(ll)(r0 + ty + 8 * i) * SS + x0 + tx];
        __syncthreads();
#pragma unroll
        for (int i = 0; i < 4; ++i)
            out[(ll)(x0 + ty + 8 * i) * LAT + r0 + tx] = t[tx][ty + 8 * i];
    }
}

// ---------------------------------------------------------------------------
// Fused feature transpose + fp16 round:
//   z in [0,32):  lt_feat (b=z,   R=C_LT, X=LL)  -> ltT
//   z in [32,64): st_feat (b=z-32, R=C_ST, X=SS) -> stT (x-guarded, X/64=8)
// ---------------------------------------------------------------------------
__global__ __launch_bounds__(256) void transpose_both_kernel(
    const float* __restrict__ lt_in, fp16* __restrict__ lt_out,
    const float* __restrict__ st_in, fp16* __restrict__ st_out)
{
    const int zv = blockIdx.z;
    const int is_st = zv >> 5;
    const int X = is_st ? SS : LL;
    if (is_st && blockIdx.x >= (SS >> 6)) return;
    const int R = 2048;                         // C_ST == C_LT
    const ll b = zv & 31;
    const float* ib = (is_st ? st_in : lt_in) + b * (ll)R * X;
    fp16* ob_p = (is_st ? st_out : lt_out);

    __shared__ float t[64][65];
    const int x0 = blockIdx.x << 6, r0 = blockIdx.y << 6;
    const int tx = threadIdx.x & 15;
    const int ty = threadIdx.x >> 4;
#pragma unroll
    for (int i = 0; i < 4; ++i) {
        int r = ty + 16 * i;
        float4 v = *reinterpret_cast<const float4*>(
            ib + (ll)(r0 + r) * X + x0 + tx * 4);
        t[r][tx * 4 + 0] = v.x; t[r][tx * 4 + 1] = v.y;
        t[r][tx * 4 + 2] = v.z; t[r][tx * 4 + 3] = v.w;
    }
    __syncthreads();
    const ll ob = b * (ll)R * X;
#pragma unroll
    for (int i = 0; i < 4; ++i) {
        int xr = ty + 16 * i;
        fp16 h0 = __float2half_rn(t[tx * 4 + 0][xr]);
        fp16 h1 = __float2half_rn(t[tx * 4 + 1][xr]);
        fp16 h2 = __float2half_rn(t[tx * 4 + 2][xr]);
        fp16 h3 = __float2half_rn(t[tx * 4 + 3][xr]);
        ll o = ob + (ll)(x0 + xr) * R + r0 + tx * 4;
        *reinterpret_cast<uint2*>(ob_p + o) = make_uint2(pack_h(h0, h1), pack_h(h2, h3));
    }
}

// ---------------------------------------------------------------------------
// Softmax over L (=2048), fp16 logits in; p scaled x1024, fp16 out.
// ---------------------------------------------------------------------------
__global__ __launch_bounds__(256) void softmax_kernel(
    const fp16* __restrict__ x, fp16* __restrict__ ph)
{
    const ll row = blockIdx.x;
    const int tid = threadIdx.x;
    const fp16* p = x + row * (ll)LL + tid * 8;

    uint4 u = *reinterpret_cast<const uint4*>(p);
    float2 f0 = h2f(u.x), f1 = h2f(u.y), f2 = h2f(u.z), f3 = h2f(u.w);
    float v[8] = {f0.x, f0.y, f1.x, f1.y, f2.x, f2.y, f3.x, f3.y};

    float m = v[0];
#pragma unroll
    for (int i = 1; i < 8; ++i) m = fmaxf(m, v[i]);
#pragma unroll
    for (int o = 16; o > 0; o >>= 1) m = fmaxf(m, __shfl_xor_sync(0xffffffffu, m, o));
    __shared__ float sm[8];
    if ((tid & 31) == 0) sm[tid >> 5] = m;
    __syncthreads();
    float mx = sm[0];
#pragma unroll
    for (int i = 1; i < 8; ++i) mx = fmaxf(mx, sm[i]);

    float s = 0.f;
#pragma unroll
    for (int i = 0; i < 8; ++i) { v[i] = __expf(v[i] - mx); s += v[i]; }
#pragma unroll
    for (int o = 16; o > 0; o >>= 1) s += __shfl_xor_sync(0xffffffffu, s, o);
    __shared__ float ss[8];
    if ((tid & 31) == 0) ss[tid >> 5] = s;
    __syncthreads();
    float tot = 0.f;
#pragma unroll
    for (int i = 0; i < 8; ++i) tot += ss[i];
    float inv = 1024.f / tot;     // p scaled by 1024 (undone by alpha in G5)

    uint32_t hp[4];
#pragma unroll
    for (int q = 0; q < 4; ++q)
        hp[q] = pack_h(__float2half_rn(v[2*q] * inv), __float2half_rn(v[2*q+1] * inv));
    ll o = row * (ll)LL + tid * 8;
    *reinterpret_cast<uint4*>(ph + o) = make_uint4(hp[0], hp[1], hp[2], hp[3]);
}

// ---------------------------------------------------------------------------
// LN stats phase 2: combine 8 per-CTA partials per batch (fixed order).
// ---------------------------------------------------------------------------
__global__ __launch_bounds__(32) void stats2_kernel(
    const float2* __restrict__ part, float2* __restrict__ stats)
{
    const int n = threadIdx.x;
    float S = 0.f, S2 = 0.f;
#pragma unroll
    for (int i = 0; i < 8; ++i) {
        float2 p = part[n * 8 + i];
        S += p.x; S2 += p.y;
    }
    const float invM = 1.f / (float)(LAT * SS);
    float mu = S * invM;
    float var = S2 * invM - mu * mu;
    stats[n] = make_float2(mu, rsqrtf(var + LN_EPS));
}

// ---------------------------------------------------------------------------
// LN affine + ReLU, att fp16 -> y fp16
// ---------------------------------------------------------------------------
__global__ __launch_bounds__(256) void affine_relu_kernel(
    const fp16* __restrict__ att, const float* __restrict__ wT,
    const float* __restrict__ bT, const float2* __restrict__ stats,
    fp16* __restrict__ yh)
{
    const int r = threadIdx.x >> 6;
    const int c = (threadIdx.x & 63) * 8;
    const ll row = (ll)blockIdx.x * 4 + r;
    const int b = (int)(row >> 9), s = (int)(row & 511);
    const float2 st = stats[b];
    const fp16* xx = att + row * (ll)LAT + c;
    const float* ww = wT + (ll)s * LAT + c;
    const float* bb = bT + (ll)s * LAT + c;

    uint4 xu = *reinterpret_cast<const uint4*>(xx);
    float2 xf0 = h2f(xu.x), xf1 = h2f(xu.y), xf2 = h2f(xu.z), xf3 = h2f(xu.w);
    float xv[8] = {xf0.x, xf0.y, xf1.x, xf1.y, xf2.x, xf2.y, xf3.x, xf3.y};
    float4 w0 = *reinterpret_cast<const float4*>(ww);
    float4 w1 = *reinterpret_cast<const float4*>(ww + 4);
    float4 b0 = *reinterpret_cast<const float4*>(bb);
    float4 b1 = *reinterpret_cast<const float4*>(bb + 4);
    float wv[8] = {w0.x, w0.y, w0.z, w0.w, w1.x, w1.y, w1.z, w1.w};
    float bv[8] = {b0.x, b0.y, b0.z, b0.w, b1.x, b1.y, b1.z, b1.w};

    uint32_t hp[4];
#pragma unroll
    for (int q = 0; q < 4; ++q) {
        float v0 = fmaxf((xv[2*q]   - st.x) * st.y * wv[2*q]   + bv[2*q],   0.f);
        float v1 = fmaxf((xv[2*q+1] - st.x) * st.y * wv[2*q+1] + bv[2*q+1], 0.f);
        hp[q] = pack_h(__float2half_rn(v0), __float2half_rn(v1));
    }
    ll o = row * (ll)LAT + c;
    *reinterpret_cast<uint4*>(yh + o) = make_uint4(hp[0], hp[1], hp[2], hp[3]);
}

// ---------------------------------------------------------------------------
// Launch
// ---------------------------------------------------------------------------
extern "C" void kernel_launch(void* const* d_in, const int* in_sizes, int n_in,
                              void* d_out, int out_size)
{
    const float* st_feat = (const float*)d_in[0];
    const float* lt_feat = (const float*)d_in[1];
    const float* w_st    = (const float*)d_in[2];
    const float* b_st    = (const float*)d_in[3];
    const float* w_lt    = (const float*)d_in[4];
    const float* b_lt    = (const float*)d_in[5];
    const float* w_g     = (const float*)d_in[6];
    const float* b_g     = (const float*)d_in[7];
    const float* ln_w    = (const float*)d_in[8];
    const float* ln_b    = (const float*)d_in[9];
    const float* w_out   = (const float*)d_in[10];
    const float* b_out   = (const float*)d_in[11];
    float* out = (float*)d_out;

    unsigned char* pool;
    cudaGetSymbolAddress((void**)&pool, g_pool);
    fp16* stT    = (fp16*)(pool + O_STT);
    fp16* ltT    = (fp16*)(pool + O_LTT);
    fp16* theta  = (fp16*)(pool + O_THETA);
    fp16* phi    = (fp16*)(pool + O_PHI);
    fp16* g      = (fp16*)(pool + O_G);
    fp16* scores = (fp16*)(pool + O_SCORE);
    fp16* p      = (fp16*)(pool + O_P);
    fp16* att    = (fp16*)(pool + O_ATT);
    fp16* y      = (fp16*)(pool + O_Y);
    fp16* wst    = (fp16*)(pool + O_WST);
    fp16* wlt    = (fp16*)(pool + O_WLT);
    fp16* wg     = (fp16*)(pool + O_WG);
    fp16* wout   = (fp16*)(pool + O_WOUT);
    float* lnw_t = (float*)(pool + O_LNW_T);
    float* lnb_t = (float*)(pool + O_LNB_T);
    float2* pstat= (float2*)(pool + O_PSTAT);
    float2* stats= (float2*)(pool + O_STATS);

    cudaFuncSetAttribute(mma_gemm<0,0>, cudaFuncAttributeMaxDynamicSharedMemorySize, SMEM_TOTAL);
    cudaFuncSetAttribute(mma_gemm<2,0>, cudaFuncAttributeMaxDynamicSharedMemorySize, SMEM_TOTAL);
    cudaFuncSetAttribute(mma_gemm<2,1>, cudaFuncAttributeMaxDynamicSharedMemorySize, SMEM_TOTAL);

    const float inv_sqrt_lat = 0.044194173824159216f;   // 1/sqrt(512)
    const float WS = 64.f, IWS = 1.f / 64.f;            // weight pre-scale
    const float IPS = 1.f / 1024.f;                     // p pre-scale undo

    // --- fused operand conversion (2 launches instead of 8) ---
    prep_kernel<<<dim3(512, 5), 256>>>(
        w_st, wst, w_lt, wlt, w_g, wg, w_out, wout,
        ln_w, lnw_t, ln_b, lnb_t, WS);
    transpose_both_kernel<<<dim3(LL / 64, 32, 64), 256>>>(
        lt_feat, ltT, st_feat, stT);

    // --- G1: theta(s,lat) = stT(s,c) . wst(lat,c)/64 + b_st -> fp16 ---
    mma_gemm<2,0><<<dim3(LAT / 256, SS / 128, NB), 256, SMEM_TOTAL>>>(
        stT, wst, nullptr, theta,
        C_ST, LAT, (ll)SS * C_ST, 0, (ll)SS * LAT, IWS, b_st, 1, nullptr);

    // --- G2: phi(l,lat) = ltT(l,c) . wlt(lat,c)/64 + b_lt -> fp16 ---
    mma_gemm<2,0><<<dim3(LAT / 256, LL / 128, NB), 256, SMEM_TOTAL>>>(
        ltT, wlt, nullptr, phi,
        C_LT, LAT, (ll)LL * C_LT, 0, (ll)LL * LAT, IWS, b_lt, 1, nullptr);

    // --- G3: g(lat,l) = wg(lat,c)/64 . ltT(l,c) + b_g -> fp16 ---
    mma_gemm<2,0><<<dim3(LL / 256, LAT / 128, NB), 256, SMEM_TOTAL>>>(
        wg, ltT, nullptr, g,
        C_LT, LL, 0, (ll)LL * C_LT, (ll)LAT * LL, IWS, b_g, 0, nullptr);

    // --- G4: scores(s,l) = theta(s,.) . phi(l,.) / sqrt(LAT) -> fp16 ---
    mma_gemm<2,0><<<dim3(LL / 256, SS / 128, NB), 256, SMEM_TOTAL>>>(
        theta, phi, nullptr, scores,
        LAT, LL, (ll)SS * LAT, (ll)LL * LAT, (ll)SS * LL, inv_sqrt_lat, nullptr, 0, nullptr);

    // --- softmax over L (fp16 in, +x1024 scale) -> fp16 ---
    softmax_kernel<<<NB * SS, 256>>>(scores, p);

    // --- G5: att(s,lat) = p(s,l)/1024 . g(lat,l) -> fp16, fused LN partials ---
    mma_gemm<2,1><<<dim3(LAT / 256, SS / 128, NB), 256, SMEM_TOTAL>>>(
        p, g, nullptr, att,
        LL, LAT, (ll)SS * LL, (ll)LAT * LL, (ll)SS * LAT, IPS, nullptr, 0, pstat);

    // --- LN stats combine + affine + relu -> fp16 ---
    stats2_kernel<<<1, 32>>>(pstat, stats);
    affine_relu_kernel<<<NB * SS / 4, 256>>>(att, lnw_t, lnb_t, stats, y);

    // --- G6: out(c,s) = wout(c,lat)/64 . y(s,lat) + b_out -> fp32 ---
    mma_gemm<0,0><<<dim3(SS / 256, C_ST / 128, NB), 256, SMEM_TOTAL>>>(
        wout, y, out, nullptr,
        LAT, SS, 0, (ll)SS * LAT, (ll)C_ST * SS, IWS, b_out, 0, nullptr);
}

// round 17
// speedup vs baseline: 3.7179x; 1.0557x over previous
#include <cuda_runtime.h>
#include <cuda_fp16.h>
#include <cstdint>
#include <math.h>

// ---------------------------------------------------------------------------
// Problem constants
// ---------------------------------------------------------------------------
#define NB    32
#define C_ST  2048
#define C_LT  2048
#define LAT   512
#define SS    512
#define LL    2048
#define LN_EPS 1e-5f

typedef long long ll;
typedef __half fp16;

// ---------------------------------------------------------------------------
// Scratch pool (single __device__ global; offsets in bytes, 256-aligned)
// ---------------------------------------------------------------------------
static constexpr ll SZ_STT   = (ll)NB * SS  * C_ST * 2;
static constexpr ll SZ_LTT   = (ll)NB * LL  * C_LT * 2;
static constexpr ll SZ_THETA = (ll)NB * SS  * LAT  * 2;
static constexpr ll SZ_PHI   = (ll)NB * LL  * LAT  * 2;
static constexpr ll SZ_G     = (ll)NB * LAT * LL   * 2;
static constexpr ll SZ_SCORE = (ll)NB * SS  * LL   * 2;   // fp16
static constexpr ll SZ_P     = (ll)NB * SS  * LL   * 2;
static constexpr ll SZ_ATT   = (ll)NB * SS  * LAT  * 2;   // fp16
static constexpr ll SZ_Y     = (ll)NB * SS  * LAT  * 2;
static constexpr ll SZ_W     = (ll)LAT * C_ST * 2;
static constexpr ll SZ_LN    = (ll)LAT * SS * 4;

static constexpr ll O_STT    = 0;
static constexpr ll O_LTT    = O_STT   + SZ_STT;
static constexpr ll O_THETA  = O_LTT   + SZ_LTT;
static constexpr ll O_PHI    = O_THETA + SZ_THETA;
static constexpr ll O_G      = O_PHI   + SZ_PHI;
static constexpr ll O_SCORE  = O_G     + SZ_G;
static constexpr ll O_P      = O_SCORE + SZ_SCORE;
static constexpr ll O_ATT    = O_P     + SZ_P;
static constexpr ll O_Y      = O_ATT   + SZ_ATT;
static constexpr ll O_WST    = O_Y     + SZ_Y;
static constexpr ll O_WLT    = O_WST   + SZ_W;
static constexpr ll O_WG     = O_WLT   + SZ_W;
static constexpr ll O_WOUT   = O_WG    + SZ_W;
static constexpr ll O_LNW_T  = O_WOUT  + SZ_W;
static constexpr ll O_LNB_T  = O_LNW_T + SZ_LN;
static constexpr ll O_PSTAT  = O_LNB_T + SZ_LN;
static constexpr ll O_STATS  = O_PSTAT + 256 * 8;
static constexpr ll POOL_BYTES = O_STATS + 256;

__device__ __align__(256) unsigned char g_pool[POOL_BYTES];

// ---------------------------------------------------------------------------
// PTX helpers
// ---------------------------------------------------------------------------
__device__ __forceinline__ uint32_t smem_u32(const void* p) {
    uint32_t a;
    asm("{ .reg .u64 t; cvta.to.shared.u64 t, %1; cvt.u32.u64 %0, t; }"
        : "=r"(a) : "l"(p));
    return a;
}
__device__ __forceinline__ void cpa16(uint32_t s, const void* g) {
    asm volatile("cp.async.cg.shared.global [%0], [%1], 16;" :: "r"(s), "l"(g) : "memory");
}
#define CP_COMMIT asm volatile("cp.async.commit_group;" ::: "memory")
#define CP_WAIT2  asm volatile("cp.async.wait_group 2;" ::: "memory")
#define CP_WAIT1  asm volatile("cp.async.wait_group 1;" ::: "memory")
#define CP_WAIT0  asm volatile("cp.async.wait_group 0;" ::: "memory")

#define LDSM4(r, addr) \
    asm volatile("ldmatrix.sync.aligned.m8n8.x4.shared.b16 {%0,%1,%2,%3}, [%4];" \
        : "=r"((r)[0]), "=r"((r)[1]), "=r"((r)[2]), "=r"((r)[3]) : "r"(addr))

// fp16 MMA, k16, fp32 accumulate (full-rate HMMA class)
#define MMAH(d, a, b0, b1) \
    asm volatile("mma.sync.aligned.m16n8k16.row.col.f32.f16.f16.f32 " \
        "{%0,%1,%2,%3}, {%4,%5,%6,%7}, {%8,%9}, {%0,%1,%2,%3};" \
        : "+f"((d)[0]), "+f"((d)[1]), "+f"((d)[2]), "+f"((d)[3]) \
        : "r"((a)[0]), "r"((a)[1]), "r"((a)[2]), "r"((a)[3]), "r"(b0), "r"(b1))

__device__ __forceinline__ uint32_t pack_h(fp16 a, fp16 b) {
    return (uint32_t)__half_as_ushort(a) | ((uint32_t)__half_as_ushort(b) << 16);
}
__device__ __forceinline__ float2 h2f(uint32_t u) {
    __half2 h = *reinterpret_cast<__half2*>(&u);
    return __half22float2(h);
}

// ---------------------------------------------------------------------------
// Tensor-core GEMM (plain fp16):  C(m,n) = alpha*sum_k A(m,k)*B(n,k) + bias
//   A, B K-major fp16 (lda=ldb=K). CTA tile M=128, N=256, K-chunk 64.
//   Warp grid 2(m) x 4(n); warp tile 64x64. 4-stage cp.async ring,
//   ONE barrier per chunk (stage distance 4 removes the WAR hazard the
//   end-of-loop barrier guarded at 3 stages; warp skew bounded to 1 iter
//   by the top barrier).
//   OUT=0: fp32 Cf.  OUT=2: fp16 Ch.
//   STATS=1: reduce outputs (pre-round fp32) to per-CTA (sum,sumsq) partial.
// Stage: A[0,16K) B[16K,48K) -> 48K/stage, 192K total.
// ---------------------------------------------------------------------------
static constexpr uint32_t STAGE = 49152;
static constexpr int SMEM_TOTAL = 4 * (int)STAGE;     // 196608

template <int OUT, int STATS>
__global__ __launch_bounds__(256) void mma_gemm(
    const fp16* __restrict__ A, const fp16* __restrict__ B,
    float* __restrict__ Cf, fp16* __restrict__ Ch,
    int K, int ldc, ll sA, ll sB, ll sC,
    float alpha, const float* __restrict__ bias, int bias_per_n,
    float2* __restrict__ pstat)
{
    extern __shared__ __align__(1024) char smem[];
    const uint32_t sb = smem_u32(smem);
    const int tid  = threadIdx.x;
    const int wid  = tid >> 5, lane = tid & 31;
    const ll  b    = blockIdx.z;
    const int m0   = blockIdx.y << 7;
    const int n0   = blockIdx.x << 8;

    const fp16* Ab = A + b * sA;
    const fp16* Bb = B + b * sB;

    const int C = K >> 6;

    auto load_chunk = [&](int ct, int stg) {
        const uint32_t base = sb + stg * STAGE;
        const int kt = ct << 6;
#pragma unroll
        for (int i = 0; i < 4; ++i) {           // A: 128 rows x 128B
            int idx = tid + (i << 8);
            int row = idx >> 3, seg = idx & 7;
            uint32_t so = (uint32_t)((row << 7) + (seg << 4));
            so ^= (so >> 3) & 0x70;
            cpa16(base + so, Ab + (ll)(m0 + row) * K + kt + (seg << 3));
        }
#pragma unroll
        for (int i = 0; i < 8; ++i) {           // B: 256 rows x 128B
            int idx = tid + (i << 8);
            int row = idx >> 3, seg = idx & 7;
            uint32_t so = (uint32_t)((row << 7) + (seg << 4));
            so ^= (so >> 3) & 0x70;
            cpa16(base + 16384 + so, Bb + (ll)(n0 + row) * K + kt + (seg << 3));
        }
    };

    load_chunk(0, 0); CP_COMMIT;
    if (C > 1) { load_chunk(1, 1); CP_COMMIT; }

    // warp tiling: 2 (m) x 4 (n); each warp 64(m) x 64(n)
    const int wm = wid >> 2, wn = wid & 3;
    float acc[4][8][4];
#pragma unroll
    for (int i = 0; i < 4; ++i)
#pragma unroll
        for (int j = 0; j < 8; ++j)
#pragma unroll
            for (int q = 0; q < 4; ++q) acc[i][j][q] = 0.f;

    const uint32_t a_row = (uint32_t)(wm * 64 + (lane & 15));
    const uint32_t a_sb  = (uint32_t)(lane >> 4);
    const uint32_t b_row = (uint32_t)(wn * 64 + ((lane >> 4) << 3) + (lane & 7));
    const uint32_t b_sb  = (uint32_t)((lane >> 3) & 1);

    for (int ct = 0; ct < C; ++ct) {
        // issue-ahead-2 into stage (ct+2)%4; stages in use by any resident
        // warp are (ct-1..ct+1)%4 -- all distinct from (ct+2)%4.
        if (ct + 2 < C) { load_chunk(ct + 2, (ct + 2) & 3); CP_COMMIT; CP_WAIT2; }
        else if (ct + 1 < C) { CP_WAIT1; }
        else { CP_WAIT0; }
        __syncthreads();                        // single barrier per chunk
        const uint32_t sbase = sb + (ct & 3) * STAGE;

#pragma unroll
        for (int s = 0; s < 4; ++s) {           // 4 x k16 per chunk
            uint32_t ah[4][4];
#pragma unroll
            for (int mt = 0; mt < 4; ++mt) {
                uint32_t row = a_row + mt * 16;
                uint32_t seg = (uint32_t)(s * 2) + a_sb;
                uint32_t off = (row << 7) + (seg << 4);
                off ^= (off >> 3) & 0x70;
                LDSM4(ah[mt], sbase + off);
            }
            uint32_t bh[4][4];
#pragma unroll
            for (int ng = 0; ng < 4; ++ng) {
                uint32_t row = b_row + ng * 16;
                uint32_t seg = (uint32_t)(s * 2) + b_sb;
                uint32_t off = (row << 7) + (seg << 4);
                off ^= (off >> 3) & 0x70;
                LDSM4(bh[ng], sbase + 16384 + off);
            }
#pragma unroll
            for (int mt = 0; mt < 4; ++mt) {
#pragma unroll
                for (int ng = 0; ng < 4; ++ng) {
                    MMAH(acc[mt][2 * ng],     ah[mt], bh[ng][0], bh[ng][1]);
                    MMAH(acc[mt][2 * ng + 1], ah[mt], bh[ng][2], bh[ng][3]);
                }
            }
        }
        // no end-of-loop barrier: 4-stage ring makes the WAR distance safe
    }

    // ---- epilogue ----
    float ls = 0.f, ls2 = 0.f;
    const int l4 = lane >> 2;
    const int l2 = (lane & 3) * 2;
#pragma unroll
    for (int mt = 0; mt < 4; ++mt) {
        const int m = m0 + wm * 64 + mt * 16 + l4;
        float bm0 = 0.f, bm8 = 0.f;
        if (bias && !bias_per_n) { bm0 = bias[m]; bm8 = bias[m + 8]; }
#pragma unroll
        for (int nt = 0; nt < 8; ++nt) {
            const int n = n0 + wn * 64 + nt * 8 + l2;
            float bn0 = 0.f, bn1 = 0.f;
            if (bias && bias_per_n) { bn0 = bias[n]; bn1 = bias[n + 1]; }
            const float* a4 = acc[mt][nt];
            float v00 = a4[0] * alpha, v01 = a4[1] * alpha;
            float v10 = a4[2] * alpha, v11 = a4[3] * alpha;
            if (bias) {
                if (bias_per_n) { v00 += bn0; v01 += bn1; v10 += bn0; v11 += bn1; }
                else            { v00 += bm0; v01 += bm0; v10 += bm8; v11 += bm8; }
            }
            if (STATS) {
                ls  += v00 + v01 + v10 + v11;
                ls2 += v00 * v00 + v01 * v01 + v10 * v10 + v11 * v11;
            }
            ll o0 = b * sC + (ll)m * ldc + n;
            ll o1 = b * sC + (ll)(m + 8) * ldc + n;
            if (OUT == 0) {
                *reinterpret_cast<float2*>(Cf + o0) = make_float2(v00, v01);
                *reinterpret_cast<float2*>(Cf + o1) = make_float2(v10, v11);
            } else {
                *reinterpret_cast<uint32_t*>(Ch + o0) =
                    pack_h(__float2half_rn(v00), __float2half_rn(v01));
                *reinterpret_cast<uint32_t*>(Ch + o1) =
                    pack_h(__float2half_rn(v10), __float2half_rn(v11));
            }
        }
    }
    if (STATS) {
#pragma unroll
        for (int o = 16; o > 0; o >>= 1) {
            ls  += __shfl_xor_sync(0xffffffffu, ls,  o);
            ls2 += __shfl_xor_sync(0xffffffffu, ls2, o);
        }
        __shared__ float rs[8], rs2[8];
        if (lane == 0) { rs[wid] = ls; rs2[wid] = ls2; }
        __syncthreads();
        if (tid == 0) {
            float S = 0.f, S2 = 0.f;
#pragma unroll
            for (int i = 0; i < 8; ++i) { S += rs[i]; S2 += rs2[i]; }
            pstat[b * 8 + blockIdx.x * 4 + blockIdx.y] = make_float2(S, S2);
        }
    }
}

// ---------------------------------------------------------------------------
// Fused prep: y=0..3 -> round 4 weight matrices (512 blocks x 2048 elems);
//             y=4    -> ln_w (blocks 0-255) / ln_b (blocks 256-511) 32x32
//                       fp32 transposes (LAT x SS -> SS x LAT).
// ---------------------------------------------------------------------------
__global__ __launch_bounds__(256) void prep_kernel(
    const float* __restrict__ w_st,  fp16* __restrict__ wst,
    const float* __restrict__ w_lt,  fp16* __restrict__ wlt,
    const float* __restrict__ w_g,   fp16* __restrict__ wg,
    const float* __restrict__ w_out, fp16* __restrict__ wout,
    const float* __restrict__ ln_w,  float* __restrict__ lnw_t,
    const float* __restrict__ ln_b,  float* __restrict__ lnb_t,
    float scale)
{
    const int yv = blockIdx.y;
    if (yv < 4) {
        const float* in  = (yv == 0) ? w_st : (yv == 1) ? w_lt : (yv == 2) ? w_g : w_out;
        fp16*        out = (yv == 0) ? wst  : (yv == 1) ? wlt  : (yv == 2) ? wg  : wout;
        ll i = ((ll)blockIdx.x * 256 + threadIdx.x) * 8;
        float4 a = *reinterpret_cast<const float4*>(in + i);
        float4 c = *reinterpret_cast<const float4*>(in + i + 4);
        float v[8] = {a.x, a.y, a.z, a.w, c.x, c.y, c.z, c.w};
        uint32_t hp[4];
#pragma unroll
        for (int q = 0; q < 4; ++q)
            hp[q] = pack_h(__float2half_rn(v[2*q] * scale), __float2half_rn(v[2*q+1] * scale));
        *reinterpret_cast<uint4*>(out + i) = make_uint4(hp[0], hp[1], hp[2], hp[3]);
    } else {
        __shared__ float t[32][33];
        const int which = blockIdx.x >> 8;          // 0 = ln_w, 1 = ln_b
        const int tile  = blockIdx.x & 255;
        const float* in  = which ? ln_b  : ln_w;    // (LAT, SS)
        float*       out = which ? lnb_t : lnw_t;   // (SS, LAT)
        const int x0 = (tile & 15) << 5;            // SS tile
        const int r0 = (tile >> 4) << 5;            // LAT tile
        const int tx = threadIdx.x & 31, ty = threadIdx.x >> 5;
#pragma unroll
        for (int i = 0; i < 4; ++i)
            t[ty + 8 * i][tx] = in[(ll)(r0 + ty + 8 * i) * SS + x0 + tx];
        __syncthreads();
#pragma unroll
        for (int i = 0; i < 4; ++i)
            out[(ll)(x0 + ty + 8 * i) * LAT + r0 + tx] = t[tx][ty + 8 * i];
    }
}

// ---------------------------------------------------------------------------
// Fused feature transpose + fp16 round:
//   z in [0,32):  lt_feat (b=z,   R=C_LT, X=LL)  -> ltT
//   z in [32,64): st_feat (b=z-32, R=C_ST, X=SS) -> stT (x-guarded)
// ---------------------------------------------------------------------------
__global__ __launch_bounds__(256) void transpose_both_kernel(
    const float* __restrict__ lt_in, fp16* __restrict__ lt_out,
    const float* __restrict__ st_in, fp16* __restrict__ st_out)
{
    const int zv = blockIdx.z;
    const int is_st = zv >> 5;
    const int X = is_st ? SS : LL;
    if (is_st && blockIdx.x >= (SS >> 6)) return;
    const int R = 2048;                         // C_ST == C_LT
    const ll b = zv & 31;
    const float* ib = (is_st ? st_in : lt_in) + b * (ll)R * X;
    fp16* ob_p = (is_st ? st_out : lt_out);

    __shared__ float t[64][65];
    const int x0 = blockIdx.x << 6, r0 = blockIdx.y << 6;
    const int tx = threadIdx.x & 15;
    const int ty = threadIdx.x >> 4;
#pragma unroll
    for (int i = 0; i < 4; ++i) {
        int r = ty + 16 * i;
        float4 v = *reinterpret_cast<const float4*>(
            ib + (ll)(r0 + r) * X + x0 + tx * 4);
        t[r][tx * 4 + 0] = v.x; t[r][tx * 4 + 1] = v.y;
        t[r][tx * 4 + 2] = v.z; t[r][tx * 4 + 3] = v.w;
    }
    __syncthreads();
    const ll ob = b * (ll)R * X;
#pragma unroll
    for (int i = 0; i < 4; ++i) {
        int xr = ty + 16 * i;
        fp16 h0 = __float2half_rn(t[tx * 4 + 0][xr]);
        fp16 h1 = __float2half_rn(t[tx * 4 + 1][xr]);
        fp16 h2 = __float2half_rn(t[tx * 4 + 2][xr]);
        fp16 h3 = __float2half_rn(t[tx * 4 + 3][xr]);
        ll o = ob + (ll)(x0 + xr) * R + r0 + tx * 4;
        *reinterpret_cast<uint2*>(ob_p + o) = make_uint2(pack_h(h0, h1), pack_h(h2, h3));
    }
}

// ---------------------------------------------------------------------------
// Softmax over L (=2048), fp16 logits in; p scaled x1024, fp16 out.
// ---------------------------------------------------------------------------
__global__ __launch_bounds__(256) void softmax_kernel(
    const fp16* __restrict__ x, fp16* __restrict__ ph)
{
    const ll row = blockIdx.x;
    const int tid = threadIdx.x;
    const fp16* p = x + row * (ll)LL + tid * 8;

    uint4 u = *reinterpret_cast<const uint4*>(p);
    float2 f0 = h2f(u.x), f1 = h2f(u.y), f2 = h2f(u.z), f3 = h2f(u.w);
    float v[8] = {f0.x, f0.y, f1.x, f1.y, f2.x, f2.y, f3.x, f3.y};

    float m = v[0];
#pragma unroll
    for (int i = 1; i < 8; ++i) m = fmaxf(m, v[i]);
#pragma unroll
    for (int o = 16; o > 0; o >>= 1) m = fmaxf(m, __shfl_xor_sync(0xffffffffu, m, o));
    __shared__ float sm[8];
    if ((tid & 31) == 0) sm[tid >> 5] = m;
    __syncthreads();
    float mx = sm[0];
#pragma unroll
    for (int i = 1; i < 8; ++i) mx = fmaxf(mx, sm[i]);

    float s = 0.f;
#pragma unroll
    for (int i = 0; i < 8; ++i) { v[i] = __expf(v[i] - mx); s += v[i]; }
#pragma unroll
    for (int o = 16; o > 0; o >>= 1) s += __shfl_xor_sync(0xffffffffu, s, o);
    __shared__ float ss[8];
    if ((tid & 31) == 0) ss[tid >> 5] = s;
    __syncthreads();
    float tot = 0.f;
#pragma unroll
    for (int i = 0; i < 8; ++i) tot += ss[i];
    float inv = 1024.f / tot;     // p scaled by 1024 (undone by alpha in G5)

    uint32_t hp[4];
#pragma unroll
    for (int q = 0; q < 4; ++q)
        hp[q] = pack_h(__float2half_rn(v[2*q] * inv), __float2half_rn(v[2*q+1] * inv));
    ll o = row * (ll)LL + tid * 8;
    *reinterpret_cast<uint4*>(ph + o) = make_uint4(hp[0], hp[1], hp[2], hp[3]);
}

// ---------------------------------------------------------------------------
// LN stats phase 2: combine 8 per-CTA partials per batch (fixed order).
// ---------------------------------------------------------------------------
__global__ __launch_bounds__(32) void stats2_kernel(
    const float2* __restrict__ part, float2* __restrict__ stats)
{
    const int n = threadIdx.x;
    float S = 0.f, S2 = 0.f;
#pragma unroll
    for (int i = 0; i < 8; ++i) {
        float2 p = part[n * 8 + i];
        S += p.x; S2 += p.y;
    }
    const float invM = 1.f / (float)(LAT * SS);
    float mu = S * invM;
    float var = S2 * invM - mu * mu;
    stats[n] = make_float2(mu, rsqrtf(var + LN_EPS));
}

// ---------------------------------------------------------------------------
// LN affine + ReLU, att fp16 -> y fp16
// ---------------------------------------------------------------------------
__global__ __launch_bounds__(256) void affine_relu_kernel(
    const fp16* __restrict__ att, const float* __restrict__ wT,
    const float* __restrict__ bT, const float2* __restrict__ stats,
    fp16* __restrict__ yh)
{
    const int r = threadIdx.x >> 6;
    const int c = (threadIdx.x & 63) * 8;
    const ll row = (ll)blockIdx.x * 4 + r;
    const int b = (int)(row >> 9), s = (int)(row & 511);
    const float2 st = stats[b];
    const fp16* xx = att + row * (ll)LAT + c;
    const float* ww = wT + (ll)s * LAT + c;
    const float* bb = bT + (ll)s * LAT + c;

    uint4 xu = *reinterpret_cast<const uint4*>(xx);
    float2 xf0 = h2f(xu.x), xf1 = h2f(xu.y), xf2 = h2f(xu.z), xf3 = h2f(xu.w);
    float xv[8] = {xf0.x, xf0.y, xf1.x, xf1.y, xf2.x, xf2.y, xf3.x, xf3.y};
    float4 w0 = *reinterpret_cast<const float4*>(ww);
    float4 w1 = *reinterpret_cast<const float4*>(ww + 4);
    float4 b0 = *reinterpret_cast<const float4*>(bb);
    float4 b1 = *reinterpret_cast<const float4*>(bb + 4);
    float wv[8] = {w0.x, w0.y, w0.z, w0.w, w1.x, w1.y, w1.z, w1.w};
    float bv[8] = {b0.x, b0.y, b0.z, b0.w, b1.x, b1.y, b1.z, b1.w};

    uint32_t hp[4];
#pragma unroll
    for (int q = 0; q < 4; ++q) {
        float v0 = fmaxf((xv[2*q]   - st.x) * st.y * wv[2*q]   + bv[2*q],   0.f);
        float v1 = fmaxf((xv[2*q+1] - st.x) * st.y * wv[2*q+1] + bv[2*q+1], 0.f);
        hp[q] = pack_h(__float2half_rn(v0), __float2half_rn(v1));
    }
    ll o = row * (ll)LAT + c;
    *reinterpret_cast<uint4*>(yh + o) = make_uint4(hp[0], hp[1], hp[2], hp[3]);
}

// ---------------------------------------------------------------------------
// Launch
// ---------------------------------------------------------------------------
extern "C" void kernel_launch(void* const* d_in, const int* in_sizes, int n_in,
                              void* d_out, int out_size)
{
    const float* st_feat = (const float*)d_in[0];
    const float* lt_feat = (const float*)d_in[1];
    const float* w_st    = (const float*)d_in[2];
    const float* b_st    = (const float*)d_in[3];
    const float* w_lt    = (const float*)d_in[4];
    const float* b_lt    = (const float*)d_in[5];
    const float* w_g     = (const float*)d_in[6];
    const float* b_g     = (const float*)d_in[7];
    const float* ln_w    = (const float*)d_in[8];
    const float* ln_b    = (const float*)d_in[9];
    const float* w_out   = (const float*)d_in[10];
    const float* b_out   = (const float*)d_in[11];
    float* out = (float*)d_out;

    unsigned char* pool;
    cudaGetSymbolAddress((void**)&pool, g_pool);
    fp16* stT    = (fp16*)(pool + O_STT);
    fp16* ltT    = (fp16*)(pool + O_LTT);
    fp16* theta  = (fp16*)(pool + O_THETA);
    fp16* phi    = (fp16*)(pool + O_PHI);
    fp16* g      = (fp16*)(pool + O_G);
    fp16* scores = (fp16*)(pool + O_SCORE);
    fp16* p      = (fp16*)(pool + O_P);
    fp16* att    = (fp16*)(pool + O_ATT);
    fp16* y      = (fp16*)(pool + O_Y);
    fp16* wst    = (fp16*)(pool + O_WST);
    fp16* wlt    = (fp16*)(pool + O_WLT);
    fp16* wg     = (fp16*)(pool + O_WG);
    fp16* wout   = (fp16*)(pool + O_WOUT);
    float* lnw_t = (float*)(pool + O_LNW_T);
    float* lnb_t = (float*)(pool + O_LNB_T);
    float2* pstat= (float2*)(pool + O_PSTAT);
    float2* stats= (float2*)(pool + O_STATS);

    cudaFuncSetAttribute(mma_gemm<0,0>, cudaFuncAttributeMaxDynamicSharedMemorySize, SMEM_TOTAL);
    cudaFuncSetAttribute(mma_gemm<2,0>, cudaFuncAttributeMaxDynamicSharedMemorySize, SMEM_TOTAL);
    cudaFuncSetAttribute(mma_gemm<2,1>, cudaFuncAttributeMaxDynamicSharedMemorySize, SMEM_TOTAL);

    const float inv_sqrt_lat = 0.044194173824159216f;   // 1/sqrt(512)
    const float WS = 64.f, IWS = 1.f / 64.f;            // weight pre-scale
    const float IPS = 1.f / 1024.f;                     // p pre-scale undo

    // --- fused operand conversion (2 launches) ---
    prep_kernel<<<dim3(512, 5), 256>>>(
        w_st, wst, w_lt, wlt, w_g, wg, w_out, wout,
        ln_w, lnw_t, ln_b, lnb_t, WS);
    transpose_both_kernel<<<dim3(LL / 64, 32, 64), 256>>>(
        lt_feat, ltT, st_feat, stT);

    // --- G1: theta(s,lat) = stT(s,c) . wst(lat,c)/64 + b_st -> fp16 ---
    mma_gemm<2,0><<<dim3(LAT / 256, SS / 128, NB), 256, SMEM_TOTAL>>>(
        stT, wst, nullptr, theta,
        C_ST, LAT, (ll)SS * C_ST, 0, (ll)SS * LAT, IWS, b_st, 1, nullptr);

    // --- G2: phi(l,lat) = ltT(l,c) . wlt(lat,c)/64 + b_lt -> fp16 ---
    mma_gemm<2,0><<<dim3(LAT / 256, LL / 128, NB), 256, SMEM_TOTAL>>>(
        ltT, wlt, nullptr, phi,
        C_LT, LAT, (ll)LL * C_LT, 0, (ll)LL * LAT, IWS, b_lt, 1, nullptr);

    // --- G3: g(lat,l) = wg(lat,c)/64 . ltT(l,c) + b_g -> fp16 ---
    mma_gemm<2,0><<<dim3(LL / 256, LAT / 128, NB), 256, SMEM_TOTAL>>>(
        wg, ltT, nullptr, g,
        C_LT, LL, 0, (ll)LL * C_LT, (ll)LAT * LL, IWS, b_g, 0, nullptr);

    // --- G4: scores(s,l) = theta(s,.) . phi(l,.) / sqrt(LAT) -> fp16 ---
    mma_gemm<2,0><<<dim3(LL / 256, SS / 128, NB), 256, SMEM_TOTAL>>>(
        theta, phi, nullptr, scores,
        LAT, LL, (ll)SS * LAT, (ll)LL * LAT, (ll)SS * LL, inv_sqrt_lat, nullptr, 0, nullptr);

    // --- softmax over L (fp16 in, +x1024 scale) -> fp16 ---
    softmax_kernel<<<NB * SS, 256>>>(scores, p);

    // --- G5: att(s,lat) = p(s,l)/1024 . g(lat,l) -> fp16, fused LN partials ---
    mma_gemm<2,1><<<dim3(LAT / 256, SS / 128, NB), 256, SMEM_TOTAL>>>(
        p, g, nullptr, att,
        LL, LAT, (ll)SS * LL, (ll)LAT * LL, (ll)SS * LAT, IPS, nullptr, 0, pstat);

    // --- LN stats combine + affine + relu -> fp16 ---
    stats2_kernel<<<1, 32>>>(pstat, stats);
    affine_relu_kernel<<<NB * SS / 4, 256>>>(att, lnw_t, lnb_t, stats, y);

    // --- G6: out(c,s) = wout(c,lat)/64 . y(s,lat) + b_out -> fp32 ---
    mma_gemm<0,0><<<dim3(SS / 256, C_ST / 128, NB), 256, SMEM_TOTAL>>>(
        wout, y, out, nullptr,
        LAT, SS, 0, (ll)SS * LAT, (ll)C_ST * SS, IWS, b_out, 0, nullptr);
}